// round 5
// baseline (speedup 1.0000x reference)
#include <cuda_runtime.h>
#include <math.h>
#include <stdint.h>

#define BATCH  2
#define SEQ    1024
#define DMODEL 1024
#define DINNER 2048
#define DSTATE 16
#define NROWS  (BATCH*SEQ)      // 2048
#define DBCN   96
#define XZN    (2*DINNER)       // 4096
#define NSPLIT 8

// ---------------- scratch ---------------------------------------------------
__device__ float g_xz  [2][(size_t)NROWS*XZN];
__device__ float g_xi  [2][(size_t)NROWS*DINNER];
__device__ float g_dbc [2][(size_t)NROWS*DBCN];
__device__ float g_dbcp[2][NSPLIT][(size_t)NROWS*DBCN];
__device__ float g_dt  [2][(size_t)NROWS*DINNER];
__device__ float g_y   [2][(size_t)NROWS*DINNER];
__device__ float g_outd[2][(size_t)NROWS*DMODEL];
__device__ float g_A   [2][DINNER*DSTATE];
__device__ int   g_fastA[2];

// ---------------- helpers ---------------------------------------------------
__device__ __forceinline__ uint32_t smem_u32(const void* p) {
    uint32_t a;
    asm("{ .reg .u64 t; cvta.to.shared.u64 t, %1; cvt.u32.u64 %0, t; }"
        : "=r"(a) : "l"(p));
    return a;
}
__device__ __forceinline__ uint32_t f2tf32(float f) {
    uint32_t r;
    asm("cvt.rna.tf32.f32 %0, %1;" : "=r"(r) : "f"(f));
    return r;
}
__device__ __forceinline__ void cp16(uint32_t dst, const void* src, int sz) {
    asm volatile("cp.async.cg.shared.global [%0], [%1], 16, %2;"
                 :: "r"(dst), "l"(src), "r"(sz) : "memory");
}
__device__ __forceinline__ void cp_commit() {
    asm volatile("cp.async.commit_group;" ::: "memory");
}
__device__ __forceinline__ void cp_wait2() {
    asm volatile("cp.async.wait_group 2;" ::: "memory");
}

__global__ void prepA_kernel(const float* __restrict__ Alog0,
                             const float* __restrict__ Alog1) {
    int dir = blockIdx.x;
    const float* Alog = dir ? Alog1 : Alog0;
    __shared__ int ok;
    if (threadIdx.x == 0) ok = 1;
    __syncthreads();
    bool good = true;
    for (int i = threadIdx.x; i < DINNER*DSTATE; i += blockDim.x) {
        float a = -__expf(Alog[i]);
        g_A[dir][i] = a;
        int s = i & (DSTATE-1);
        if (fabsf(a + (float)(s+1)) > 1e-3f * (float)(s+1)) good = false;
    }
    if (!good) atomicExch(&ok, 0);
    __syncthreads();
    if (threadIdx.x == 0) g_fastA[dir] = ok;
}

// ==============  TF32 mma.sync GEMM, CTA 256x128, warp 64x64  ===============
// C(2048, Ntot) = A(2048, K; lda) * W(N, K; ldw)^T.
// 4-stage cp.async pipeline, BK=16, 256 threads.
// SMEM per stage: A 256x16 fp32 (16KB) + B 128x16 (8KB) = 24KB; 4 stages = 96KB.
// Swizzle: word(row,k) = row*16 + 4*((k>>2)^((row>>1)&3)) + (k&3).
// EPI: 0 none, 1 softplus(v+bias[n]), 2 sigmoid(v).  rev: reverse A rows within SEQ (dir 1).

#define STG4 24576

template<int EPI>
__global__ __launch_bounds__(256)
void mma_gemm3(const float* __restrict__ A0, const float* __restrict__ A1,
               const float* __restrict__ W0, const float* __restrict__ W1,
               const float* __restrict__ b0, const float* __restrict__ b1,
               float* __restrict__ C0, float* __restrict__ C1,
               int N, int Ntot, int Ksub, int lda, int ldw,
               int nsplit, size_t csplit, int revA) {
    const int dir   = blockIdx.z / nsplit;
    const int split = blockIdx.z - dir*nsplit;
    const float* A = dir ? A1 : A0;
    const float* W = dir ? W1 : W0;
    const float* bias = dir ? b1 : b0;
    float* C = (dir ? C1 : C0) + (size_t)split * csplit;
    const int koff = split * Ksub;
    const int rev  = revA && dir;

    extern __shared__ __align__(16) char sm[];
    const uint32_t sbase = smem_u32(sm);

    const int tid  = threadIdx.x;
    const int lane = tid & 31;
    const int wid  = tid >> 5;
    const int warp_m = (wid & 3) * 64;
    const int warp_n = (wid >> 2) * 64;
    const int m0 = blockIdx.y * 256;
    const int n0 = blockIdx.x * 128;

    const int lrow = tid >> 2;            // loader row
    const int lkc  = tid & 3;             // loader 16B chunk

    // fragment addressing constants
    const int lq = lane & 3;
    const int kx = (lane >> 3) & 3;
    int ko[4];
    #pragma unroll
    for (int c = 0; c < 4; c++) ko[c] = 4*(c ^ kx);
    int abase[4], bbase[8];
    #pragma unroll
    for (int mi = 0; mi < 4; mi++)
        abase[mi] = (warp_m + mi*16 + (lane>>2))*16 + lq;
    #pragma unroll
    for (int ni = 0; ni < 8; ni++)
        bbase[ni] = 4096 + (warp_n + ni*8 + (lane>>2))*16 + lq;   // B at +16KB

    float acc[4][8][4];
    #pragma unroll
    for (int i = 0; i < 4; i++)
        #pragma unroll
        for (int j = 0; j < 8; j++)
            #pragma unroll
            for (int r = 0; r < 4; r++) acc[i][j][r] = 0.f;

    const int nk = Ksub / 16;

    auto stage_load = [&](int it) {
        int st = it & 3;
        uint32_t sA = sbase + st*STG4;
        uint32_t sB = sA + 16384;
        int k0 = koff + it*16;
        #pragma unroll
        for (int j = 0; j < 4; j++) {             // A: 256 rows
            int row = lrow + j*64;
            int gm = m0 + row;
            if (rev) gm = (gm & ~(SEQ-1)) | ((SEQ-1) - (gm & (SEQ-1)));
            uint32_t d = sA + row*64 + 16*(lkc ^ ((row>>1)&3));
            cp16(d, A + (size_t)gm*lda + k0 + lkc*4, 16);
        }
        #pragma unroll
        for (int j = 0; j < 2; j++) {             // B: 128 rows
            int row = lrow + j*64;
            int wr = n0 + row;
            int valid = (wr < N);
            uint32_t d = sB + row*64 + 16*(lkc ^ ((row>>1)&3));
            cp16(d, W + (size_t)(valid ? wr : 0)*ldw + k0 + lkc*4, valid ? 16 : 0);
        }
        cp_commit();
    };

    stage_load(0);
    if (nk > 1) stage_load(1); else cp_commit();
    if (nk > 2) stage_load(2); else cp_commit();

    for (int it = 0; it < nk; it++) {
        cp_wait2();
        __syncthreads();
        if (it + 3 < nk) stage_load(it + 3); else cp_commit();

        const uint32_t* S = (const uint32_t*)(sm + (it & 3)*STG4);

        #pragma unroll
        for (int kc2 = 0; kc2 < 2; kc2++) {
            const int o0 = ko[kc2*2], o1 = ko[kc2*2+1];
            uint32_t afrag[4][4];
            #pragma unroll
            for (int mi = 0; mi < 4; mi++) {
                afrag[mi][0] = f2tf32(__uint_as_float(S[abase[mi] + o0]));
                afrag[mi][1] = f2tf32(__uint_as_float(S[abase[mi] + 128 + o0]));
                afrag[mi][2] = f2tf32(__uint_as_float(S[abase[mi] + o1]));
                afrag[mi][3] = f2tf32(__uint_as_float(S[abase[mi] + 128 + o1]));
            }
            uint32_t bfrag[8][2];
            #pragma unroll
            for (int ni = 0; ni < 8; ni++) {
                bfrag[ni][0] = f2tf32(__uint_as_float(S[bbase[ni] + o0]));
                bfrag[ni][1] = f2tf32(__uint_as_float(S[bbase[ni] + o1]));
            }
            #pragma unroll
            for (int mi = 0; mi < 4; mi++)
                #pragma unroll
                for (int ni = 0; ni < 8; ni++) {
                    asm volatile(
                        "mma.sync.aligned.m16n8k8.row.col.f32.tf32.tf32.f32 "
                        "{%0,%1,%2,%3}, {%4,%5,%6,%7}, {%8,%9}, {%0,%1,%2,%3};"
                        : "+f"(acc[mi][ni][0]), "+f"(acc[mi][ni][1]),
                          "+f"(acc[mi][ni][2]), "+f"(acc[mi][ni][3])
                        : "r"(afrag[mi][0]), "r"(afrag[mi][1]),
                          "r"(afrag[mi][2]), "r"(afrag[mi][3]),
                          "r"(bfrag[ni][0]), "r"(bfrag[ni][1]));
                }
        }
        __syncthreads();
    }

    // epilogue
    #pragma unroll
    for (int mi = 0; mi < 4; mi++) {
        #pragma unroll
        for (int ni = 0; ni < 8; ni++) {
            int row = m0 + warp_m + mi*16 + (lane>>2);
            int col = n0 + warp_n + ni*8 + 2*(lane&3);
            #pragma unroll
            for (int half = 0; half < 2; half++) {
                int r = row + half*8;
                float v0 = acc[mi][ni][half*2+0];
                float v1 = acc[mi][ni][half*2+1];
                if (EPI == 1) {
                    v0 += bias[col];   v1 += bias[col+1];
                    v0 = (v0 > 20.f) ? v0 : log1pf(__expf(v0));
                    v1 = (v1 > 20.f) ? v1 : log1pf(__expf(v1));
                } else if (EPI == 2) {
                    v0 = 1.f / (1.f + __expf(-v0));
                    v1 = 1.f / (1.f + __expf(-v1));
                }
                if (col + 1 < N)
                    *(float2*)(C + (size_t)r*Ntot + col) = make_float2(v0, v1);
            }
        }
    }
}

// ---------------- split-K reduce for x_proj --------------------------------
__global__ void reduce_dbc_kernel() {
    int idx = blockIdx.x * blockDim.x + threadIdx.x;
    const int TOT = NROWS*DBCN;
    if (idx >= 2*TOT) return;
    int dir = idx / TOT;
    int e = idx - dir*TOT;
    float s = 0.f;
    #pragma unroll
    for (int p = 0; p < NSPLIT; p++) s += g_dbcp[dir][p][e];
    g_dbc[dir][e] = s;
}

// ---------------- causal depthwise conv (k=4) + SiLU -----------------------
__global__ void conv_silu_kernel(const float* __restrict__ w0, const float* __restrict__ w1,
                                 const float* __restrict__ cb0, const float* __restrict__ cb1) {
    int dir = blockIdx.z;
    const float* w  = dir ? w1 : w0;
    const float* cb = dir ? cb1 : cb0;
    int idx = blockIdx.x * blockDim.x + threadIdx.x;
    const int NC4 = DINNER/4;
    if (idx >= NROWS * NC4) return;
    int c4 = idx % NC4;
    int row = idx / NC4;
    int l = row & (SEQ-1);
    const float* base = g_xz[dir] + (size_t)row*XZN + c4*4;
    float4 x0  = *(const float4*)(base);
    float4 xm1 = (l>=1) ? *(const float4*)(base - 1*XZN) : make_float4(0,0,0,0);
    float4 xm2 = (l>=2) ? *(const float4*)(base - 2*XZN) : make_float4(0,0,0,0);
    float4 xm3 = (l>=3) ? *(const float4*)(base - 3*XZN) : make_float4(0,0,0,0);
    float4 cbv = ((const float4*)cb)[c4];
    float4 out;
    {
        float4 wv = ((const float4*)w)[c4*4+0];
        float a = cbv.x;
        a = fmaf(wv.x, xm3.x, a); a = fmaf(wv.y, xm2.x, a);
        a = fmaf(wv.z, xm1.x, a); a = fmaf(wv.w, x0.x, a);
        out.x = a / (1.f + __expf(-a));
    }
    {
        float4 wv = ((const float4*)w)[c4*4+1];
        float a = cbv.y;
        a = fmaf(wv.x, xm3.y, a); a = fmaf(wv.y, xm2.y, a);
        a = fmaf(wv.z, xm1.y, a); a = fmaf(wv.w, x0.y, a);
        out.y = a / (1.f + __expf(-a));
    }
    {
        float4 wv = ((const float4*)w)[c4*4+2];
        float a = cbv.z;
        a = fmaf(wv.x, xm3.z, a); a = fmaf(wv.y, xm2.z, a);
        a = fmaf(wv.z, xm1.z, a); a = fmaf(wv.w, x0.z, a);
        out.z = a / (1.f + __expf(-a));
    }
    {
        float4 wv = ((const float4*)w)[c4*4+3];
        float a = cbv.w;
        a = fmaf(wv.x, xm3.w, a); a = fmaf(wv.y, xm2.w, a);
        a = fmaf(wv.z, xm1.w, a); a = fmaf(wv.w, x0.w, a);
        out.w = a / (1.f + __expf(-a));
    }
    *(float4*)(g_xi[dir] + (size_t)row*DINNER + c4*4) = out;
}

// ---------------- selective scan -------------------------------------------
__global__ __launch_bounds__(256)
void scan_kernel(const float* __restrict__ D0, const float* __restrict__ D1) {
    int dir = blockIdx.z;
    const float* Dp = dir ? D1 : D0;
    int d = blockIdx.x * blockDim.x + threadIdx.x;
    int b = blockIdx.y;
    int lane = threadIdx.x & 31;

    const float* dtp = g_dt[dir]  + (size_t)b*SEQ*DINNER + d;
    const float* xip = g_xi[dir]  + (size_t)b*SEQ*DINNER + d;
    const float* zp  = g_xz[dir]  + (size_t)b*SEQ*XZN + DINNER + d;
    const float* vp  = g_dbc[dir] + (size_t)b*SEQ*DBCN + 64 + lane;
    float* yp        = g_y[dir]   + (size_t)b*SEQ*DINNER + d;

    float h[DSTATE];
    #pragma unroll
    for (int s = 0; s < DSTATE; s++) h[s] = 0.f;
    float Av[DSTATE];
    #pragma unroll
    for (int s = 0; s < DSTATE; s++) Av[s] = g_A[dir][d*DSTATE + s];
    float Dv = Dp[d];
    int fast = g_fastA[dir];

    #pragma unroll 1
    for (int l0 = 0; l0 < SEQ; l0 += 4) {
        float cdt[4], cxi[4], cz[4], cv[4];
        #pragma unroll
        for (int u = 0; u < 4; u++) {
            int r = l0 + u;
            cdt[u] = dtp[(size_t)r*DINNER];
            cxi[u] = xip[(size_t)r*DINNER];
            cz[u]  = zp [(size_t)r*XZN];
            cv[u]  = vp [(size_t)r*DBCN];
        }
        #pragma unroll
        for (int u = 0; u < 4; u++) {
            float dt = cdt[u], xi = cxi[u], z = cz[u], v = cv[u];
            float dtxi = dt * xi;
            float acc = 0.f;
            if (fast) {
                float e = __expf(-dt);
                float p = 1.f;
                #pragma unroll
                for (int s = 0; s < DSTATE; s++) {
                    p *= e;
                    float bs = __shfl_sync(0xffffffffu, v, s);
                    float cs = __shfl_sync(0xffffffffu, v, 16 + s);
                    h[s] = fmaf(p, h[s], dtxi * bs);
                    acc = fmaf(h[s], cs, acc);
                }
            } else {
                #pragma unroll
                for (int s = 0; s < DSTATE; s++) {
                    float a = __expf(dt * Av[s]);
                    float bs = __shfl_sync(0xffffffffu, v, s);
                    float cs = __shfl_sync(0xffffffffu, v, 16 + s);
                    h[s] = fmaf(a, h[s], dtxi * bs);
                    acc = fmaf(h[s], cs, acc);
                }
            }
            float sz = z / (1.f + __expf(-z));
            yp[(size_t)(l0+u)*DINNER] = (acc + xi * Dv) * sz;
        }
    }
}

// ---------------- combine dirs + LayerNorm + residual ----------------------
__global__ __launch_bounds__(256)
void combine_ln_kernel(const float* __restrict__ x,
                       const float* __restrict__ lng, const float* __restrict__ lnb,
                       float* __restrict__ out) {
    int row = blockIdx.x;
    int b = row / SEQ, l = row % SEQ;
    const float* f  = g_outd[0] + (size_t)row*DMODEL;
    const float* bk = g_outd[1] + (size_t)(b*SEQ + (SEQ-1-l))*DMODEL;
    int tid = threadIdx.x;

    float vals[4];
    float s = 0.f, s2 = 0.f;
    #pragma unroll
    for (int j = 0; j < 4; j++) {
        int i = tid + j*256;
        float dv = 0.5f * (f[i] + bk[i]);
        vals[j] = dv;
        s += dv; s2 += dv*dv;
    }
    #pragma unroll
    for (int o = 16; o; o >>= 1) {
        s  += __shfl_xor_sync(0xffffffffu, s,  o);
        s2 += __shfl_xor_sync(0xffffffffu, s2, o);
    }
    __shared__ float sh[2][8];
    if ((tid & 31) == 0) { sh[0][tid>>5] = s; sh[1][tid>>5] = s2; }
    __syncthreads();
    if (tid < 32) {
        float a  = (tid < 8) ? sh[0][tid] : 0.f;
        float a2 = (tid < 8) ? sh[1][tid] : 0.f;
        #pragma unroll
        for (int o = 4; o; o >>= 1) {
            a  += __shfl_xor_sync(0xffffffffu, a,  o);
            a2 += __shfl_xor_sync(0xffffffffu, a2, o);
        }
        if (tid == 0) { sh[0][0] = a; sh[1][0] = a2; }
    }
    __syncthreads();
    float mu  = sh[0][0] * (1.f/DMODEL);
    float var = sh[1][0] * (1.f/DMODEL) - mu*mu;
    float rstd = rsqrtf(var + 1e-5f);
    #pragma unroll
    for (int j = 0; j < 4; j++) {
        int i = tid + j*256;
        out[(size_t)row*DMODEL + i] =
            (vals[j] - mu) * rstd * lng[i] + lnb[i] + x[(size_t)row*DMODEL + i];
    }
}

// ---------------- host launcher --------------------------------------------
extern "C" void kernel_launch(void* const* d_in, const int* in_sizes, int n_in,
                              void* d_out, int out_size) {
    (void)in_sizes; (void)n_in; (void)out_size;
    const float* x       = (const float*)d_in[0];
    const float* Win[2]  = {(const float*)d_in[1],  (const float*)d_in[10]};
    const float* cw[2]   = {(const float*)d_in[2],  (const float*)d_in[11]};
    const float* cbv[2]  = {(const float*)d_in[3],  (const float*)d_in[12]};
    const float* xproj[2]= {(const float*)d_in[4],  (const float*)d_in[13]};
    const float* dtw[2]  = {(const float*)d_in[5],  (const float*)d_in[14]};
    const float* dtb[2]  = {(const float*)d_in[6],  (const float*)d_in[15]};
    const float* Alog[2] = {(const float*)d_in[7],  (const float*)d_in[16]};
    const float* Dp[2]   = {(const float*)d_in[8],  (const float*)d_in[17]};
    const float* Wout[2] = {(const float*)d_in[9],  (const float*)d_in[18]};
    const float* lng = (const float*)d_in[19];
    const float* lnb = (const float*)d_in[20];
    float* out = (float*)d_out;

    float *p_xz, *p_xi, *p_dbc, *p_dbcp, *p_dt, *p_y, *p_out;
    cudaGetSymbolAddress((void**)&p_xz,   g_xz);
    cudaGetSymbolAddress((void**)&p_xi,   g_xi);
    cudaGetSymbolAddress((void**)&p_dbc,  g_dbc);
    cudaGetSymbolAddress((void**)&p_dbcp, g_dbcp);
    cudaGetSymbolAddress((void**)&p_dt,   g_dt);
    cudaGetSymbolAddress((void**)&p_y,    g_y);
    cudaGetSymbolAddress((void**)&p_out,  g_outd);

    const size_t sXZ  = (size_t)NROWS*XZN;
    const size_t sIN  = (size_t)NROWS*DINNER;
    const size_t sDBC = (size_t)NROWS*DBCN;
    const size_t sMD  = (size_t)NROWS*DMODEL;
    const int SMEM = 4*STG4;   // 98304

    cudaFuncSetAttribute(mma_gemm3<0>, cudaFuncAttributeMaxDynamicSharedMemorySize, SMEM);
    cudaFuncSetAttribute(mma_gemm3<1>, cudaFuncAttributeMaxDynamicSharedMemorySize, SMEM);
    cudaFuncSetAttribute(mma_gemm3<2>, cudaFuncAttributeMaxDynamicSharedMemorySize, SMEM);

    prepA_kernel<<<2, 256>>>(Alog[0], Alog[1]);

    // in_proj: xz = x @ Win^T  (N=4096, K=1024); dir-1 A rows read reversed
    mma_gemm3<0><<<dim3(XZN/128, NROWS/256, 2), 256, SMEM>>>(
        x, x, Win[0], Win[1], nullptr, nullptr,
        p_xz, p_xz + sXZ, XZN, XZN, DMODEL, DMODEL, DMODEL, 1, 0, 1);

    conv_silu_kernel<<<dim3((NROWS*(DINNER/4) + 255)/256, 1, 2), 256>>>(
        cw[0], cw[1], cbv[0], cbv[1]);

    // x_proj split-K: (N=96, K=256 per split)
    mma_gemm3<0><<<dim3(1, NROWS/256, 2*NSPLIT), 256, SMEM>>>(
        p_xi, p_xi + sIN, xproj[0], xproj[1], nullptr, nullptr,
        p_dbcp, p_dbcp + NSPLIT*sDBC, DBCN, DBCN, DINNER/NSPLIT, DINNER, DINNER,
        NSPLIT, sDBC, 0);
    reduce_dbc_kernel<<<(2*NROWS*DBCN + 255)/256, 256>>>();

    // dt = softplus(dbc[:, :64] @ dtw^T + dtb)  (N=2048, K=64, lda=96)
    mma_gemm3<1><<<dim3(DINNER/128, NROWS/256, 2), 256, SMEM>>>(
        p_dbc, p_dbc + sDBC, dtw[0], dtw[1], dtb[0], dtb[1],
        p_dt, p_dt + sIN, DINNER, DINNER, 64, DBCN, 64, 1, 0, 0);

    scan_kernel<<<dim3(DINNER/256, BATCH, 2), 256>>>(Dp[0], Dp[1]);

    // out = sigmoid(y @ Wout^T)  (N=1024, K=2048)
    mma_gemm3<2><<<dim3(DMODEL/128, NROWS/256, 2), 256, SMEM>>>(
        p_y, p_y + sIN, Wout[0], Wout[1], nullptr, nullptr,
        p_out, p_out + sMD, DMODEL, DMODEL, DINNER, DINNER, DINNER, 1, 0, 0);

    combine_ln_kernel<<<NROWS, 256>>>(x, lng, lnb, out);
}

// round 6
// speedup vs baseline: 1.3991x; 1.3991x over previous
#include <cuda_runtime.h>
#include <cuda_fp16.h>
#include <math.h>
#include <stdint.h>

#define BATCH  2
#define SEQ    1024
#define DMODEL 1024
#define DINNER 2048
#define DSTATE 16
#define NROWS  (BATCH*SEQ)      // 2048
#define DBCN   96
#define XZN    (2*DINNER)       // 4096
#define NSPLIT 8

// ---------------- scratch (fp32) -------------------------------------------
__device__ float g_xz  [2][(size_t)NROWS*XZN];
__device__ float g_xi  [2][(size_t)NROWS*DINNER];
__device__ float g_dbc [2][(size_t)NROWS*DBCN];
__device__ float g_dbcp[2][NSPLIT][(size_t)NROWS*DBCN];
__device__ float g_dt  [2][(size_t)NROWS*DINNER];
__device__ float g_outd[2][(size_t)NROWS*DMODEL];
__device__ float g_A   [2][DINNER*DSTATE];
__device__ int   g_fastA[2];

// ---------------- scratch (fp16 GEMM operands) ------------------------------
__device__ __half g_xh    [(size_t)NROWS*DMODEL];
__device__ __half g_winh  [2][(size_t)XZN*DMODEL];
__device__ __half g_xih   [2][(size_t)NROWS*DINNER];
__device__ __half g_xprojh[2][(size_t)DBCN*DINNER];
__device__ __half g_dbch  [2][(size_t)NROWS*DBCN];
__device__ __half g_dtwh  [2][(size_t)DINNER*64];
__device__ __half g_yh    [2][(size_t)NROWS*DINNER];
__device__ __half g_wouth [2][(size_t)DMODEL*DINNER];

// ---------------- helpers ---------------------------------------------------
__device__ __forceinline__ uint32_t smem_u32(const void* p) {
    uint32_t a;
    asm("{ .reg .u64 t; cvta.to.shared.u64 t, %1; cvt.u32.u64 %0, t; }"
        : "=r"(a) : "l"(p));
    return a;
}
__device__ __forceinline__ void cp16(uint32_t dst, const void* src, int sz) {
    asm volatile("cp.async.cg.shared.global [%0], [%1], 16, %2;"
                 :: "r"(dst), "l"(src), "r"(sz) : "memory");
}
__device__ __forceinline__ void cp_commit() {
    asm volatile("cp.async.commit_group;" ::: "memory");
}
__device__ __forceinline__ void cp_wait1() {
    asm volatile("cp.async.wait_group 1;" ::: "memory");
}
#define LDSM4(r0,r1,r2,r3,a) \
    asm volatile("ldmatrix.sync.aligned.m8n8.x4.shared.b16 {%0,%1,%2,%3}, [%4];" \
                 : "=r"(r0),"=r"(r1),"=r"(r2),"=r"(r3) : "r"(a))

// ---------------- fp32 -> fp16 conversion ----------------------------------
__global__ void f2h_kernel(const float* __restrict__ src, __half* __restrict__ dst, int n) {
    int i = (blockIdx.x*blockDim.x + threadIdx.x)*4;
    if (i >= n) return;
    float4 v = *(const float4*)(src+i);
    __half2 h0 = __floats2half2_rn(v.x, v.y);
    __half2 h1 = __floats2half2_rn(v.z, v.w);
    *(__half2*)(dst+i)   = h0;
    *(__half2*)(dst+i+2) = h1;
}

__global__ void prepA_kernel(const float* __restrict__ Alog0,
                             const float* __restrict__ Alog1) {
    int dir = blockIdx.x;
    const float* Alog = dir ? Alog1 : Alog0;
    __shared__ int ok;
    if (threadIdx.x == 0) ok = 1;
    __syncthreads();
    bool good = true;
    for (int i = threadIdx.x; i < DINNER*DSTATE; i += blockDim.x) {
        float a = -__expf(Alog[i]);
        g_A[dir][i] = a;
        int s = i & (DSTATE-1);
        if (fabsf(a + (float)(s+1)) > 1e-3f * (float)(s+1)) good = false;
    }
    if (!good) atomicExch(&ok, 0);
    __syncthreads();
    if (threadIdx.x == 0) g_fastA[dir] = ok;
}

// ==============  FP16 mma.sync GEMM (m16n8k16) ==============================
// C(2048, Ntot) = A(2048, K; lda) * W(N, K; ldw)^T, A/W fp16, accum fp32.
// CTA tile 128x128, BK=32 halfs, 3-stage cp.async, 256 thr (8 warps @64x32).
// SMEM stage: A 128x32h (8KB) + B 128x32h (8KB) = 16KB.
// Swizzle: 16B chunk' = chunk ^ ((row>>1)&3), row = 64B.
// EPI: 0 none, 1 softplus(v+bias[n]), 2 sigmoid(v).

#define HSTG 16384

template<int EPI>
__global__ __launch_bounds__(256, 2)
void hgemm(const __half* __restrict__ A0, const __half* __restrict__ A1,
           const __half* __restrict__ W0, const __half* __restrict__ W1,
           const float* __restrict__ b0, const float* __restrict__ b1,
           float* __restrict__ C0, float* __restrict__ C1,
           int N, int Ntot, int Ksub, int lda, int ldw,
           int nsplit, size_t csplit, int revA) {
    const int dir   = blockIdx.z / nsplit;
    const int split = blockIdx.z - dir*nsplit;
    const __half* A = dir ? A1 : A0;
    const __half* W = dir ? W1 : W0;
    const float* bias = dir ? b1 : b0;
    float* C = (dir ? C1 : C0) + (size_t)split * csplit;
    const int koff = split * Ksub;
    const int rev  = revA && dir;

    extern __shared__ __align__(16) char sm[];
    const uint32_t sbase = smem_u32(sm);

    const int tid  = threadIdx.x;
    const int lane = tid & 31;
    const int wid  = tid >> 5;
    const int warp_m = (wid & 1) * 64;
    const int warp_n = (wid >> 1) * 32;
    const int m0 = blockIdx.y * 128;
    const int n0 = blockIdx.x * 128;

    const int lrow = tid >> 2;   // loader row (0..63), handles lrow, lrow+64
    const int lkc  = tid & 3;    // 16B chunk (8 halfs)

    // ldmatrix base addresses (stage 0, ks 0)
    uint32_t aaddr[4], baddr[2];
    {
        int ar = warp_m + (lane & 7) + ((lane >> 3) & 1) * 8;
        int acb = (lane >> 4) & 1;
        #pragma unroll
        for (int mi = 0; mi < 4; mi++) {
            int r = ar + mi*16;
            aaddr[mi] = r*64 + ((acb ^ ((r>>1)&3))*16);
        }
        int br = warp_n + (lane & 7) + ((lane >> 4) & 1) * 8;
        int bcb = (lane >> 3) & 1;
        #pragma unroll
        for (int p = 0; p < 2; p++) {
            int r = br + p*16;
            baddr[p] = 8192 + r*64 + ((bcb ^ ((r>>1)&3))*16);
        }
    }

    float acc[4][4][4];
    #pragma unroll
    for (int i = 0; i < 4; i++)
        #pragma unroll
        for (int j = 0; j < 4; j++)
            #pragma unroll
            for (int r = 0; r < 4; r++) acc[i][j][r] = 0.f;

    const int nk = Ksub / 32;

    auto stage_load = [&](int it) {
        uint32_t sA = sbase + (it % 3)*HSTG;
        uint32_t sB = sA + 8192;
        int k0 = koff + it*32;
        #pragma unroll
        for (int j = 0; j < 2; j++) {
            int row = lrow + j*64;
            int gm = m0 + row;
            if (rev) gm = (gm & ~(SEQ-1)) | ((SEQ-1) - (gm & (SEQ-1)));
            uint32_t d = sA + row*64 + ((lkc ^ ((row>>1)&3))*16);
            cp16(d, A + (size_t)gm*lda + k0 + lkc*8, 16);
        }
        #pragma unroll
        for (int j = 0; j < 2; j++) {
            int row = lrow + j*64;
            int wr = n0 + row;
            int valid = (wr < N);
            uint32_t d = sB + row*64 + ((lkc ^ ((row>>1)&3))*16);
            cp16(d, W + (size_t)(valid ? wr : 0)*ldw + k0 + lkc*8, valid ? 16 : 0);
        }
        cp_commit();
    };

    stage_load(0);
    if (nk > 1) stage_load(1); else cp_commit();

    for (int it = 0; it < nk; it++) {
        cp_wait1();
        __syncthreads();
        if (it + 2 < nk) stage_load(it + 2); else cp_commit();

        uint32_t sb = sbase + (it % 3)*HSTG;

        #pragma unroll
        for (int ks = 0; ks < 2; ks++) {
            const uint32_t kx = ks * 32;
            uint32_t af[4][4];
            #pragma unroll
            for (int mi = 0; mi < 4; mi++)
                LDSM4(af[mi][0], af[mi][1], af[mi][2], af[mi][3],
                      sb + (aaddr[mi] ^ kx));
            uint32_t bf[4][2];
            #pragma unroll
            for (int p = 0; p < 2; p++)
                LDSM4(bf[2*p][0], bf[2*p][1], bf[2*p+1][0], bf[2*p+1][1],
                      sb + (baddr[p] ^ kx));
            #pragma unroll
            for (int mi = 0; mi < 4; mi++)
                #pragma unroll
                for (int ni = 0; ni < 4; ni++) {
                    asm volatile(
                        "mma.sync.aligned.m16n8k16.row.col.f32.f16.f16.f32 "
                        "{%0,%1,%2,%3}, {%4,%5,%6,%7}, {%8,%9}, {%0,%1,%2,%3};"
                        : "+f"(acc[mi][ni][0]), "+f"(acc[mi][ni][1]),
                          "+f"(acc[mi][ni][2]), "+f"(acc[mi][ni][3])
                        : "r"(af[mi][0]), "r"(af[mi][1]),
                          "r"(af[mi][2]), "r"(af[mi][3]),
                          "r"(bf[ni][0]), "r"(bf[ni][1]));
                }
        }
        __syncthreads();
    }

    // epilogue
    #pragma unroll
    for (int mi = 0; mi < 4; mi++) {
        #pragma unroll
        for (int ni = 0; ni < 4; ni++) {
            int row = m0 + warp_m + mi*16 + (lane>>2);
            int col = n0 + warp_n + ni*8 + 2*(lane&3);
            #pragma unroll
            for (int half = 0; half < 2; half++) {
                int r = row + half*8;
                float v0 = acc[mi][ni][half*2+0];
                float v1 = acc[mi][ni][half*2+1];
                if (EPI == 1) {
                    v0 += bias[col];   v1 += bias[col+1];
                    v0 = (v0 > 20.f) ? v0 : log1pf(__expf(v0));
                    v1 = (v1 > 20.f) ? v1 : log1pf(__expf(v1));
                } else if (EPI == 2) {
                    v0 = 1.f / (1.f + __expf(-v0));
                    v1 = 1.f / (1.f + __expf(-v1));
                }
                if (col + 1 < N)
                    *(float2*)(C + (size_t)r*Ntot + col) = make_float2(v0, v1);
            }
        }
    }
}

// ---------------- split-K reduce for x_proj (fp32 + fp16 out) ---------------
__global__ void reduce_dbc_kernel() {
    int idx = blockIdx.x * blockDim.x + threadIdx.x;
    const int TOT = NROWS*DBCN;
    if (idx >= 2*TOT) return;
    int dir = idx / TOT;
    int e = idx - dir*TOT;
    float s = 0.f;
    #pragma unroll
    for (int p = 0; p < NSPLIT; p++) s += g_dbcp[dir][p][e];
    g_dbc[dir][e] = s;
    g_dbch[dir][e] = __float2half(s);
}

// ---------------- causal depthwise conv (k=4) + SiLU -----------------------
__global__ void conv_silu_kernel(const float* __restrict__ w0, const float* __restrict__ w1,
                                 const float* __restrict__ cb0, const float* __restrict__ cb1) {
    int dir = blockIdx.z;
    const float* w  = dir ? w1 : w0;
    const float* cb = dir ? cb1 : cb0;
    int idx = blockIdx.x * blockDim.x + threadIdx.x;
    const int NC4 = DINNER/4;
    if (idx >= NROWS * NC4) return;
    int c4 = idx % NC4;
    int row = idx / NC4;
    int l = row & (SEQ-1);
    const float* base = g_xz[dir] + (size_t)row*XZN + c4*4;
    float4 x0  = *(const float4*)(base);
    float4 xm1 = (l>=1) ? *(const float4*)(base - 1*XZN) : make_float4(0,0,0,0);
    float4 xm2 = (l>=2) ? *(const float4*)(base - 2*XZN) : make_float4(0,0,0,0);
    float4 xm3 = (l>=3) ? *(const float4*)(base - 3*XZN) : make_float4(0,0,0,0);
    float4 cbv = ((const float4*)cb)[c4];
    float4 out;
    {
        float4 wv = ((const float4*)w)[c4*4+0];
        float a = cbv.x;
        a = fmaf(wv.x, xm3.x, a); a = fmaf(wv.y, xm2.x, a);
        a = fmaf(wv.z, xm1.x, a); a = fmaf(wv.w, x0.x, a);
        out.x = a / (1.f + __expf(-a));
    }
    {
        float4 wv = ((const float4*)w)[c4*4+1];
        float a = cbv.y;
        a = fmaf(wv.x, xm3.y, a); a = fmaf(wv.y, xm2.y, a);
        a = fmaf(wv.z, xm1.y, a); a = fmaf(wv.w, x0.y, a);
        out.y = a / (1.f + __expf(-a));
    }
    {
        float4 wv = ((const float4*)w)[c4*4+2];
        float a = cbv.z;
        a = fmaf(wv.x, xm3.z, a); a = fmaf(wv.y, xm2.z, a);
        a = fmaf(wv.z, xm1.z, a); a = fmaf(wv.w, x0.z, a);
        out.z = a / (1.f + __expf(-a));
    }
    {
        float4 wv = ((const float4*)w)[c4*4+3];
        float a = cbv.w;
        a = fmaf(wv.x, xm3.w, a); a = fmaf(wv.y, xm2.w, a);
        a = fmaf(wv.z, xm1.w, a); a = fmaf(wv.w, x0.w, a);
        out.w = a / (1.f + __expf(-a));
    }
    *(float4*)(g_xi[dir] + (size_t)row*DINNER + c4*4) = out;
    __half2 h0 = __floats2half2_rn(out.x, out.y);
    __half2 h1 = __floats2half2_rn(out.z, out.w);
    __half* hd = g_xih[dir] + (size_t)row*DINNER + c4*4;
    *(__half2*)(hd)   = h0;
    *(__half2*)(hd+2) = h1;
}

// ---------------- selective scan (writes y as fp16) -------------------------
__global__ __launch_bounds__(256)
void scan_kernel(const float* __restrict__ D0, const float* __restrict__ D1) {
    int dir = blockIdx.z;
    const float* Dp = dir ? D1 : D0;
    int d = blockIdx.x * blockDim.x + threadIdx.x;
    int b = blockIdx.y;
    int lane = threadIdx.x & 31;

    const float* dtp = g_dt[dir]  + (size_t)b*SEQ*DINNER + d;
    const float* xip = g_xi[dir]  + (size_t)b*SEQ*DINNER + d;
    const float* zp  = g_xz[dir]  + (size_t)b*SEQ*XZN + DINNER + d;
    const float* vp  = g_dbc[dir] + (size_t)b*SEQ*DBCN + 64 + lane;
    __half* yp       = g_yh[dir]  + (size_t)b*SEQ*DINNER + d;

    float h[DSTATE];
    #pragma unroll
    for (int s = 0; s < DSTATE; s++) h[s] = 0.f;
    float Av[DSTATE];
    #pragma unroll
    for (int s = 0; s < DSTATE; s++) Av[s] = g_A[dir][d*DSTATE + s];
    float Dv = Dp[d];
    int fast = g_fastA[dir];

    #pragma unroll 1
    for (int l0 = 0; l0 < SEQ; l0 += 4) {
        float cdt[4], cxi[4], cz[4], cv[4];
        #pragma unroll
        for (int u = 0; u < 4; u++) {
            int r = l0 + u;
            cdt[u] = dtp[(size_t)r*DINNER];
            cxi[u] = xip[(size_t)r*DINNER];
            cz[u]  = zp [(size_t)r*XZN];
            cv[u]  = vp [(size_t)r*DBCN];
        }
        #pragma unroll
        for (int u = 0; u < 4; u++) {
            float dt = cdt[u], xi = cxi[u], z = cz[u], v = cv[u];
            float dtxi = dt * xi;
            float acc = 0.f;
            if (fast) {
                float e = __expf(-dt);
                float p = 1.f;
                #pragma unroll
                for (int s = 0; s < DSTATE; s++) {
                    p *= e;
                    float bs = __shfl_sync(0xffffffffu, v, s);
                    float cs = __shfl_sync(0xffffffffu, v, 16 + s);
                    h[s] = fmaf(p, h[s], dtxi * bs);
                    acc = fmaf(h[s], cs, acc);
                }
            } else {
                #pragma unroll
                for (int s = 0; s < DSTATE; s++) {
                    float a = __expf(dt * Av[s]);
                    float bs = __shfl_sync(0xffffffffu, v, s);
                    float cs = __shfl_sync(0xffffffffu, v, 16 + s);
                    h[s] = fmaf(a, h[s], dtxi * bs);
                    acc = fmaf(h[s], cs, acc);
                }
            }
            float sz = z / (1.f + __expf(-z));
            yp[(size_t)(l0+u)*DINNER] = __float2half((acc + xi * Dv) * sz);
        }
    }
}

// ---------------- combine dirs + LayerNorm + residual ----------------------
__global__ __launch_bounds__(256)
void combine_ln_kernel(const float* __restrict__ x,
                       const float* __restrict__ lng, const float* __restrict__ lnb,
                       float* __restrict__ out) {
    int row = blockIdx.x;
    int b = row / SEQ, l = row % SEQ;
    const float* f  = g_outd[0] + (size_t)row*DMODEL;
    const float* bk = g_outd[1] + (size_t)(b*SEQ + (SEQ-1-l))*DMODEL;
    int tid = threadIdx.x;

    float vals[4];
    float s = 0.f, s2 = 0.f;
    #pragma unroll
    for (int j = 0; j < 4; j++) {
        int i = tid + j*256;
        float dv = 0.5f * (f[i] + bk[i]);
        vals[j] = dv;
        s += dv; s2 += dv*dv;
    }
    #pragma unroll
    for (int o = 16; o; o >>= 1) {
        s  += __shfl_xor_sync(0xffffffffu, s,  o);
        s2 += __shfl_xor_sync(0xffffffffu, s2, o);
    }
    __shared__ float sh[2][8];
    if ((tid & 31) == 0) { sh[0][tid>>5] = s; sh[1][tid>>5] = s2; }
    __syncthreads();
    if (tid < 32) {
        float a  = (tid < 8) ? sh[0][tid] : 0.f;
        float a2 = (tid < 8) ? sh[1][tid] : 0.f;
        #pragma unroll
        for (int o = 4; o; o >>= 1) {
            a  += __shfl_xor_sync(0xffffffffu, a,  o);
            a2 += __shfl_xor_sync(0xffffffffu, a2, o);
        }
        if (tid == 0) { sh[0][0] = a; sh[1][0] = a2; }
    }
    __syncthreads();
    float mu  = sh[0][0] * (1.f/DMODEL);
    float var = sh[1][0] * (1.f/DMODEL) - mu*mu;
    float rstd = rsqrtf(var + 1e-5f);
    #pragma unroll
    for (int j = 0; j < 4; j++) {
        int i = tid + j*256;
        out[(size_t)row*DMODEL + i] =
            (vals[j] - mu) * rstd * lng[i] + lnb[i] + x[(size_t)row*DMODEL + i];
    }
}

// ---------------- host launcher --------------------------------------------
extern "C" void kernel_launch(void* const* d_in, const int* in_sizes, int n_in,
                              void* d_out, int out_size) {
    (void)in_sizes; (void)n_in; (void)out_size;
    const float* x       = (const float*)d_in[0];
    const float* Win[2]  = {(const float*)d_in[1],  (const float*)d_in[10]};
    const float* cw[2]   = {(const float*)d_in[2],  (const float*)d_in[11]};
    const float* cbv[2]  = {(const float*)d_in[3],  (const float*)d_in[12]};
    const float* xproj[2]= {(const float*)d_in[4],  (const float*)d_in[13]};
    const float* dtw[2]  = {(const float*)d_in[5],  (const float*)d_in[14]};
    const float* dtb[2]  = {(const float*)d_in[6],  (const float*)d_in[15]};
    const float* Alog[2] = {(const float*)d_in[7],  (const float*)d_in[16]};
    const float* Dp[2]   = {(const float*)d_in[8],  (const float*)d_in[17]};
    const float* Wout[2] = {(const float*)d_in[9],  (const float*)d_in[18]};
    const float* lng = (const float*)d_in[19];
    const float* lnb = (const float*)d_in[20];
    float* out = (float*)d_out;

    float *p_xz, *p_dbc, *p_dbcp, *p_dt, *p_out;
    cudaGetSymbolAddress((void**)&p_xz,   g_xz);
    cudaGetSymbolAddress((void**)&p_dbc,  g_dbc);
    cudaGetSymbolAddress((void**)&p_dbcp, g_dbcp);
    cudaGetSymbolAddress((void**)&p_dt,   g_dt);
    cudaGetSymbolAddress((void**)&p_out,  g_outd);
    __half *p_xh, *p_winh, *p_xih, *p_xprojh, *p_dbch, *p_dtwh, *p_yh, *p_wouth;
    cudaGetSymbolAddress((void**)&p_xh,     g_xh);
    cudaGetSymbolAddress((void**)&p_winh,   g_winh);
    cudaGetSymbolAddress((void**)&p_xih,    g_xih);
    cudaGetSymbolAddress((void**)&p_xprojh, g_xprojh);
    cudaGetSymbolAddress((void**)&p_dbch,   g_dbch);
    cudaGetSymbolAddress((void**)&p_dtwh,   g_dtwh);
    cudaGetSymbolAddress((void**)&p_yh,     g_yh);
    cudaGetSymbolAddress((void**)&p_wouth,  g_wouth);

    const size_t sXZ  = (size_t)NROWS*XZN;
    const size_t sIN  = (size_t)NROWS*DINNER;
    const size_t sDBC = (size_t)NROWS*DBCN;
    const size_t sMD  = (size_t)NROWS*DMODEL;
    const int SMEM = 3*HSTG;   // 49152

    cudaFuncSetAttribute(hgemm<0>, cudaFuncAttributeMaxDynamicSharedMemorySize, SMEM);
    cudaFuncSetAttribute(hgemm<1>, cudaFuncAttributeMaxDynamicSharedMemorySize, SMEM);
    cudaFuncSetAttribute(hgemm<2>, cudaFuncAttributeMaxDynamicSharedMemorySize, SMEM);

    prepA_kernel<<<2, 256>>>(Alog[0], Alog[1]);

    // fp16 conversions (x + all weights)
    auto cvt = [&](const float* s, __half* d, size_t n) {
        f2h_kernel<<<(int)((n/4 + 255)/256), 256>>>(s, d, (int)n);
    };
    cvt(x, p_xh, (size_t)NROWS*DMODEL);
    cvt(Win[0], p_winh,              (size_t)XZN*DMODEL);
    cvt(Win[1], p_winh + (size_t)XZN*DMODEL, (size_t)XZN*DMODEL);
    cvt(xproj[0], p_xprojh,          (size_t)DBCN*DINNER);
    cvt(xproj[1], p_xprojh + (size_t)DBCN*DINNER, (size_t)DBCN*DINNER);
    cvt(dtw[0], p_dtwh,              (size_t)DINNER*64);
    cvt(dtw[1], p_dtwh + (size_t)DINNER*64, (size_t)DINNER*64);
    cvt(Wout[0], p_wouth,            (size_t)DMODEL*DINNER);
    cvt(Wout[1], p_wouth + (size_t)DMODEL*DINNER, (size_t)DMODEL*DINNER);

    // in_proj: xz = x @ Win^T (N=4096, K=1024); dir-1 reads A rows reversed
    hgemm<0><<<dim3(XZN/128, NROWS/128, 2), 256, SMEM>>>(
        p_xh, p_xh, p_winh, p_winh + (size_t)XZN*DMODEL, nullptr, nullptr,
        p_xz, p_xz + sXZ, XZN, XZN, DMODEL, DMODEL, DMODEL, 1, 0, 1);

    conv_silu_kernel<<<dim3((NROWS*(DINNER/4) + 255)/256, 1, 2), 256>>>(
        cw[0], cw[1], cbv[0], cbv[1]);

    // x_proj split-K (N=96, K=256 per split)
    hgemm<0><<<dim3(1, NROWS/128, 2*NSPLIT), 256, SMEM>>>(
        p_xih, p_xih + sIN, p_xprojh, p_xprojh + (size_t)DBCN*DINNER,
        nullptr, nullptr,
        p_dbcp, p_dbcp + NSPLIT*sDBC, DBCN, DBCN, DINNER/NSPLIT, DINNER, DINNER,
        NSPLIT, sDBC, 0);
    reduce_dbc_kernel<<<(2*NROWS*DBCN + 255)/256, 256>>>();

    // dt = softplus(dbc[:, :64] @ dtw^T + dtb) (N=2048, K=64, lda=96)
    hgemm<1><<<dim3(DINNER/128, NROWS/128, 2), 256, SMEM>>>(
        p_dbch, p_dbch + sDBC, p_dtwh, p_dtwh + (size_t)DINNER*64, dtb[0], dtb[1],
        p_dt, p_dt + sIN, DINNER, DINNER, 64, DBCN, 64, 1, 0, 0);

    scan_kernel<<<dim3(DINNER/256, BATCH, 2), 256>>>(Dp[0], Dp[1]);

    // out = sigmoid(y @ Wout^T) (N=1024, K=2048)
    hgemm<2><<<dim3(DMODEL/128, NROWS/128, 2), 256, SMEM>>>(
        p_yh, p_yh + sIN, p_wouth, p_wouth + (size_t)DMODEL*DINNER,
        nullptr, nullptr,
        p_out, p_out + sMD, DMODEL, DMODEL, DINNER, DINNER, DINNER, 1, 0, 0);

    combine_ln_kernel<<<NROWS, 256>>>(x, lng, lnb, out);
}

// round 9
// speedup vs baseline: 1.4837x; 1.0605x over previous
#include <cuda_runtime.h>
#include <cuda_fp16.h>
#include <math.h>
#include <stdint.h>

#define BATCH  2
#define SEQ    1024
#define DMODEL 1024
#define DINNER 2048
#define DSTATE 16
#define NROWS  (BATCH*SEQ)      // 2048
#define DBCN   96
#define XZN    (2*DINNER)       // 4096
#define NSPLIT 8

// ---------------- scratch (fp32) -------------------------------------------
__device__ float g_xz  [2][(size_t)NROWS*XZN];
__device__ float g_xi  [2][(size_t)NROWS*DINNER];
__device__ float g_dbc [2][(size_t)NROWS*DBCN];
__device__ float g_dbcp[2][NSPLIT][(size_t)NROWS*DBCN];
__device__ float g_dt  [2][(size_t)NROWS*DINNER];
__device__ float g_outd[2][(size_t)NROWS*DMODEL];
__device__ float g_A   [2][DINNER*DSTATE];
__device__ int   g_fastA[2];

// ---------------- scratch (fp16 GEMM operands) ------------------------------
__device__ __half g_xh    [(size_t)NROWS*DMODEL];
__device__ __half g_winh  [2][(size_t)XZN*DMODEL];
__device__ __half g_xih   [2][(size_t)NROWS*DINNER];
__device__ __half g_xprojh[2][(size_t)DBCN*DINNER];
__device__ __half g_dbch  [2][(size_t)NROWS*DBCN];
__device__ __half g_dtwh  [2][(size_t)DINNER*64];
__device__ __half g_yh    [2][(size_t)NROWS*DINNER];
__device__ __half g_wouth [2][(size_t)DMODEL*DINNER];

// ---------------- helpers ---------------------------------------------------
__device__ __forceinline__ uint32_t smem_u32(const void* p) {
    uint32_t a;
    asm("{ .reg .u64 t; cvta.to.shared.u64 t, %1; cvt.u32.u64 %0, t; }"
        : "=r"(a) : "l"(p));
    return a;
}
__device__ __forceinline__ void cp16(uint32_t dst, const void* src, int sz) {
    asm volatile("cp.async.cg.shared.global [%0], [%1], 16, %2;"
                 :: "r"(dst), "l"(src), "r"(sz) : "memory");
}
__device__ __forceinline__ void cp_commit() {
    asm volatile("cp.async.commit_group;" ::: "memory");
}
__device__ __forceinline__ void cp_wait1() {
    asm volatile("cp.async.wait_group 1;" ::: "memory");
}
#define LDSM4(r0,r1,r2,r3,a) \
    asm volatile("ldmatrix.sync.aligned.m8n8.x4.shared.b16 {%0,%1,%2,%3}, [%4];" \
                 : "=r"(r0),"=r"(r1),"=r"(r2),"=r"(r3) : "r"(a))

// ---------------- fused fp32->fp16 conversion (9 segments, 1 launch) --------
struct CvtSegs {
    const float* s[9];
    __half*      d[9];
    int          off[10];
};
__global__ void f2h_multi_kernel(CvtSegs segs) {
    int i4 = (blockIdx.x*blockDim.x + threadIdx.x) * 4;
    if (i4 >= segs.off[9]) return;
    int j = 0;
    #pragma unroll
    for (int k = 1; k < 9; k++) j += (i4 >= segs.off[k]);
    int local = i4 - segs.off[j];
    float4 v = *(const float4*)(segs.s[j] + local);
    __half* dst = segs.d[j] + local;
    *(__half2*)(dst)   = __floats2half2_rn(v.x, v.y);
    *(__half2*)(dst+2) = __floats2half2_rn(v.z, v.w);
}

__global__ void prepA_kernel(const float* __restrict__ Alog0,
                             const float* __restrict__ Alog1) {
    int dir = blockIdx.x;
    const float* Alog = dir ? Alog1 : Alog0;
    __shared__ int ok;
    if (threadIdx.x == 0) ok = 1;
    __syncthreads();
    bool good = true;
    for (int i = threadIdx.x; i < DINNER*DSTATE; i += blockDim.x) {
        float a = -__expf(Alog[i]);
        g_A[dir][i] = a;
        int s = i & (DSTATE-1);
        if (fabsf(a + (float)(s+1)) > 1e-3f * (float)(s+1)) good = false;
    }
    if (!good) atomicExch(&ok, 0);
    __syncthreads();
    if (threadIdx.x == 0) g_fastA[dir] = ok;
}

// ==============  FP16 mma.sync GEMM (m16n8k16) ==============================
// CTA 128x128, BK=32, 3-stage cp.async, TWO barriers per k-iter,
// stage_load issued BEFORE compute (R5-proven structure — do not reorder).
// EPI: 0 none, 1 softplus(+bias), 2 sigmoid.  fp32 C output.

#define HSTG 16384

template<int EPI>
__global__ __launch_bounds__(256, 2)
void hgemm(const __half* __restrict__ A0, const __half* __restrict__ A1,
           const __half* __restrict__ W0, const __half* __restrict__ W1,
           const float* __restrict__ b0, const float* __restrict__ b1,
           float* __restrict__ C0, float* __restrict__ C1,
           int N, int Ntot, int Ksub, int lda, int ldw,
           int nsplit, size_t csplit, int revA) {
    const int dir   = blockIdx.z / nsplit;
    const int split = blockIdx.z - dir*nsplit;
    const __half* A = dir ? A1 : A0;
    const __half* W = dir ? W1 : W0;
    const float* bias = dir ? b1 : b0;
    float* C = (dir ? C1 : C0) + (size_t)split * csplit;
    const int koff = split * Ksub;
    const int rev  = revA && dir;

    extern __shared__ __align__(16) char sm[];
    const uint32_t sbase = smem_u32(sm);

    const int tid  = threadIdx.x;
    const int lane = tid & 31;
    const int wid  = tid >> 5;
    const int warp_m = (wid & 1) * 64;
    const int warp_n = (wid >> 1) * 32;
    const int m0 = blockIdx.y * 128;
    const int n0 = blockIdx.x * 128;

    const int lrow = tid >> 2;
    const int lkc  = tid & 3;

    uint32_t aaddr[4], baddr[2];
    {
        int ar = warp_m + (lane & 7) + ((lane >> 3) & 1) * 8;
        int acb = (lane >> 4) & 1;
        #pragma unroll
        for (int mi = 0; mi < 4; mi++) {
            int r = ar + mi*16;
            aaddr[mi] = r*64 + ((acb ^ ((r>>1)&3))*16);
        }
        int br = warp_n + (lane & 7) + ((lane >> 4) & 1) * 8;
        int bcb = (lane >> 3) & 1;
        #pragma unroll
        for (int p = 0; p < 2; p++) {
            int r = br + p*16;
            baddr[p] = 8192 + r*64 + ((bcb ^ ((r>>1)&3))*16);
        }
    }

    float acc[4][4][4];
    #pragma unroll
    for (int i = 0; i < 4; i++)
        #pragma unroll
        for (int j = 0; j < 4; j++)
            #pragma unroll
            for (int r = 0; r < 4; r++) acc[i][j][r] = 0.f;

    const int nk = Ksub / 32;

    auto stage_load = [&](int it) {
        uint32_t sA = sbase + (it % 3)*HSTG;
        uint32_t sB = sA + 8192;
        int k0 = koff + it*32;
        #pragma unroll
        for (int j = 0; j < 2; j++) {
            int row = lrow + j*64;
            int gm = m0 + row;
            if (rev) gm = (gm & ~(SEQ-1)) | ((SEQ-1) - (gm & (SEQ-1)));
            uint32_t d = sA + row*64 + ((lkc ^ ((row>>1)&3))*16);
            cp16(d, A + (size_t)gm*lda + k0 + lkc*8, 16);
        }
        #pragma unroll
        for (int j = 0; j < 2; j++) {
            int row = lrow + j*64;
            int wr = n0 + row;
            int valid = (wr < N);
            uint32_t d = sB + row*64 + ((lkc ^ ((row>>1)&3))*16);
            cp16(d, W + (size_t)(valid ? wr : 0)*ldw + k0 + lkc*8, valid ? 16 : 0);
        }
        cp_commit();
    };

    stage_load(0);
    if (nk > 1) stage_load(1); else cp_commit();

    for (int it = 0; it < nk; it++) {
        cp_wait1();
        __syncthreads();
        if (it + 2 < nk) stage_load(it + 2); else cp_commit();

        uint32_t sb = sbase + (it % 3)*HSTG;
        #pragma unroll
        for (int ks = 0; ks < 2; ks++) {
            const uint32_t kx = ks * 32;
            uint32_t af[4][4];
            #pragma unroll
            for (int mi = 0; mi < 4; mi++)
                LDSM4(af[mi][0], af[mi][1], af[mi][2], af[mi][3],
                      sb + (aaddr[mi] ^ kx));
            uint32_t bf[4][2];
            #pragma unroll
            for (int p = 0; p < 2; p++)
                LDSM4(bf[2*p][0], bf[2*p][1], bf[2*p+1][0], bf[2*p+1][1],
                      sb + (baddr[p] ^ kx));
            #pragma unroll
            for (int mi = 0; mi < 4; mi++)
                #pragma unroll
                for (int ni = 0; ni < 4; ni++) {
                    asm volatile(
                        "mma.sync.aligned.m16n8k16.row.col.f32.f16.f16.f32 "
                        "{%0,%1,%2,%3}, {%4,%5,%6,%7}, {%8,%9}, {%0,%1,%2,%3};"
                        : "+f"(acc[mi][ni][0]), "+f"(acc[mi][ni][1]),
                          "+f"(acc[mi][ni][2]), "+f"(acc[mi][ni][3])
                        : "r"(af[mi][0]), "r"(af[mi][1]),
                          "r"(af[mi][2]), "r"(af[mi][3]),
                          "r"(bf[ni][0]), "r"(bf[ni][1]));
                }
        }
        __syncthreads();
    }

    // epilogue
    #pragma unroll
    for (int mi = 0; mi < 4; mi++) {
        #pragma unroll
        for (int ni = 0; ni < 4; ni++) {
            int row = m0 + warp_m + mi*16 + (lane>>2);
            int col = n0 + warp_n + ni*8 + 2*(lane&3);
            #pragma unroll
            for (int half = 0; half < 2; half++) {
                int r = row + half*8;
                float v0 = acc[mi][ni][half*2+0];
                float v1 = acc[mi][ni][half*2+1];
                if (EPI == 1) {
                    v0 += bias[col];   v1 += bias[col+1];
                    v0 = (v0 > 20.f) ? v0 : log1pf(__expf(v0));
                    v1 = (v1 > 20.f) ? v1 : log1pf(__expf(v1));
                } else if (EPI == 2) {
                    v0 = 1.f / (1.f + __expf(-v0));
                    v1 = 1.f / (1.f + __expf(-v1));
                }
                if (col + 1 < N)
                    *(float2*)(C + (size_t)r*Ntot + col) = make_float2(v0, v1);
            }
        }
    }
}

// ---------------- split-K reduce for x_proj ---------------------------------
__global__ void reduce_dbc_kernel() {
    int idx = blockIdx.x * blockDim.x + threadIdx.x;
    const int TOT = NROWS*DBCN;
    if (idx >= 2*TOT) return;
    int dir = idx / TOT;
    int e = idx - dir*TOT;
    float s = 0.f;
    #pragma unroll
    for (int p = 0; p < NSPLIT; p++) s += g_dbcp[dir][p][e];
    g_dbc[dir][e] = s;
    g_dbch[dir][e] = __float2half(s);
}

// ---------------- causal depthwise conv (k=4) + SiLU -----------------------
// reads fp32 xz; writes fp32 xi (scan) + fp16 xi (x_proj GEMM)
__global__ void conv_silu_kernel(const float* __restrict__ w0, const float* __restrict__ w1,
                                 const float* __restrict__ cb0, const float* __restrict__ cb1) {
    int dir = blockIdx.z;
    const float* w  = dir ? w1 : w0;
    const float* cb = dir ? cb1 : cb0;
    int idx = blockIdx.x * blockDim.x + threadIdx.x;
    const int NC4 = DINNER/4;
    if (idx >= NROWS * NC4) return;
    int c4 = idx % NC4;
    int row = idx / NC4;
    int l = row & (SEQ-1);
    const float* base = g_xz[dir] + (size_t)row*XZN + c4*4;
    float4 x0  = *(const float4*)(base);
    float4 xm1 = (l>=1) ? *(const float4*)(base - 1*XZN) : make_float4(0,0,0,0);
    float4 xm2 = (l>=2) ? *(const float4*)(base - 2*XZN) : make_float4(0,0,0,0);
    float4 xm3 = (l>=3) ? *(const float4*)(base - 3*XZN) : make_float4(0,0,0,0);
    float4 cbv = ((const float4*)cb)[c4];
    float4 out;
    {
        float4 wv = ((const float4*)w)[c4*4+0];
        float a = cbv.x;
        a = fmaf(wv.x, xm3.x, a); a = fmaf(wv.y, xm2.x, a);
        a = fmaf(wv.z, xm1.x, a); a = fmaf(wv.w, x0.x, a);
        out.x = a / (1.f + __expf(-a));
    }
    {
        float4 wv = ((const float4*)w)[c4*4+1];
        float a = cbv.y;
        a = fmaf(wv.x, xm3.y, a); a = fmaf(wv.y, xm2.y, a);
        a = fmaf(wv.z, xm1.y, a); a = fmaf(wv.w, x0.y, a);
        out.y = a / (1.f + __expf(-a));
    }
    {
        float4 wv = ((const float4*)w)[c4*4+2];
        float a = cbv.z;
        a = fmaf(wv.x, xm3.z, a); a = fmaf(wv.y, xm2.z, a);
        a = fmaf(wv.z, xm1.z, a); a = fmaf(wv.w, x0.z, a);
        out.z = a / (1.f + __expf(-a));
    }
    {
        float4 wv = ((const float4*)w)[c4*4+3];
        float a = cbv.w;
        a = fmaf(wv.x, xm3.w, a); a = fmaf(wv.y, xm2.w, a);
        a = fmaf(wv.z, xm1.w, a); a = fmaf(wv.w, x0.w, a);
        out.w = a / (1.f + __expf(-a));
    }
    *(float4*)(g_xi[dir] + (size_t)row*DINNER + c4*4) = out;
    __half* hd = g_xih[dir] + (size_t)row*DINNER + c4*4;
    *(__half2*)(hd)   = __floats2half2_rn(out.x, out.y);
    *(__half2*)(hd+2) = __floats2half2_rn(out.z, out.w);
}

// ---------------- selective scan (fp32 in, y out as fp16) -------------------
__global__ __launch_bounds__(64)
void scan_kernel(const float* __restrict__ D0, const float* __restrict__ D1) {
    int dir = blockIdx.z;
    const float* Dp = dir ? D1 : D0;
    int d = blockIdx.x * 64 + threadIdx.x;
    int b = blockIdx.y;
    int lane = threadIdx.x & 31;

    const float* dtp = g_dt[dir]  + (size_t)b*SEQ*DINNER + d;
    const float* xip = g_xi[dir]  + (size_t)b*SEQ*DINNER + d;
    const float* zp  = g_xz[dir]  + (size_t)b*SEQ*XZN + DINNER + d;
    const float* vp  = g_dbc[dir] + (size_t)b*SEQ*DBCN + 64 + lane;
    __half* yp       = g_yh[dir]  + (size_t)b*SEQ*DINNER + d;

    float h[DSTATE];
    #pragma unroll
    for (int s = 0; s < DSTATE; s++) h[s] = 0.f;
    float Av[DSTATE];
    #pragma unroll
    for (int s = 0; s < DSTATE; s++) Av[s] = g_A[dir][d*DSTATE + s];
    float Dv = Dp[d];
    int fast = g_fastA[dir];

    #pragma unroll 1
    for (int l0 = 0; l0 < SEQ; l0 += 4) {
        float cdt[4], cxi[4], cz[4], cv[4];
        #pragma unroll
        for (int u = 0; u < 4; u++) {
            int r = l0 + u;
            cdt[u] = dtp[(size_t)r*DINNER];
            cxi[u] = xip[(size_t)r*DINNER];
            cz[u]  = zp [(size_t)r*XZN];
            cv[u]  = vp [(size_t)r*DBCN];
        }
        #pragma unroll
        for (int u = 0; u < 4; u++) {
            float dt = cdt[u], xi = cxi[u], z = cz[u], v = cv[u];
            float dtxi = dt * xi;
            float acc = 0.f;
            if (fast) {
                float e = __expf(-dt);
                float p = 1.f;
                #pragma unroll
                for (int s = 0; s < DSTATE; s++) {
                    p *= e;
                    float bs = __shfl_sync(0xffffffffu, v, s);
                    float cs = __shfl_sync(0xffffffffu, v, 16 + s);
                    h[s] = fmaf(p, h[s], dtxi * bs);
                    acc = fmaf(h[s], cs, acc);
                }
            } else {
                #pragma unroll
                for (int s = 0; s < DSTATE; s++) {
                    float a = __expf(dt * Av[s]);
                    float bs = __shfl_sync(0xffffffffu, v, s);
                    float cs = __shfl_sync(0xffffffffu, v, 16 + s);
                    h[s] = fmaf(a, h[s], dtxi * bs);
                    acc = fmaf(h[s], cs, acc);
                }
            }
            float sz = z / (1.f + __expf(-z));
            yp[(size_t)(l0+u)*DINNER] = __float2half((acc + xi * Dv) * sz);
        }
    }
}

// ---------------- combine dirs + LayerNorm + residual ----------------------
__global__ __launch_bounds__(256)
void combine_ln_kernel(const float* __restrict__ x,
                       const float* __restrict__ lng, const float* __restrict__ lnb,
                       float* __restrict__ out) {
    int row = blockIdx.x;
    int b = row / SEQ, l = row % SEQ;
    const float* f  = g_outd[0] + (size_t)row*DMODEL;
    const float* bk = g_outd[1] + (size_t)(b*SEQ + (SEQ-1-l))*DMODEL;
    int tid = threadIdx.x;

    float vals[4];
    float s = 0.f, s2 = 0.f;
    #pragma unroll
    for (int j = 0; j < 4; j++) {
        int i = tid + j*256;
        float dv = 0.5f * (f[i] + bk[i]);
        vals[j] = dv;
        s += dv; s2 += dv*dv;
    }
    #pragma unroll
    for (int o = 16; o; o >>= 1) {
        s  += __shfl_xor_sync(0xffffffffu, s,  o);
        s2 += __shfl_xor_sync(0xffffffffu, s2, o);
    }
    __shared__ float sh[2][8];
    if ((tid & 31) == 0) { sh[0][tid>>5] = s; sh[1][tid>>5] = s2; }
    __syncthreads();
    if (tid < 32) {
        float a  = (tid < 8) ? sh[0][tid] : 0.f;
        float a2 = (tid < 8) ? sh[1][tid] : 0.f;
        #pragma unroll
        for (int o = 4; o; o >>= 1) {
            a  += __shfl_xor_sync(0xffffffffu, a,  o);
            a2 += __shfl_xor_sync(0xffffffffu, a2, o);
        }
        if (tid == 0) { sh[0][0] = a; sh[1][0] = a2; }
    }
    __syncthreads();
    float mu  = sh[0][0] * (1.f/DMODEL);
    float var = sh[1][0] * (1.f/DMODEL) - mu*mu;
    float rstd = rsqrtf(var + 1e-5f);
    #pragma unroll
    for (int j = 0; j < 4; j++) {
        int i = tid + j*256;
        out[(size_t)row*DMODEL + i] =
            (vals[j] - mu) * rstd * lng[i] + lnb[i] + x[(size_t)row*DMODEL + i];
    }
}

// ---------------- host launcher --------------------------------------------
extern "C" void kernel_launch(void* const* d_in, const int* in_sizes, int n_in,
                              void* d_out, int out_size) {
    (void)in_sizes; (void)n_in; (void)out_size;
    const float* x       = (const float*)d_in[0];
    const float* Win[2]  = {(const float*)d_in[1],  (const float*)d_in[10]};
    const float* cw[2]   = {(const float*)d_in[2],  (const float*)d_in[11]};
    const float* cbv[2]  = {(const float*)d_in[3],  (const float*)d_in[12]};
    const float* xproj[2]= {(const float*)d_in[4],  (const float*)d_in[13]};
    const float* dtw[2]  = {(const float*)d_in[5],  (const float*)d_in[14]};
    const float* dtb[2]  = {(const float*)d_in[6],  (const float*)d_in[15]};
    const float* Alog[2] = {(const float*)d_in[7],  (const float*)d_in[16]};
    const float* Dp[2]   = {(const float*)d_in[8],  (const float*)d_in[17]};
    const float* Wout[2] = {(const float*)d_in[9],  (const float*)d_in[18]};
    const float* lng = (const float*)d_in[19];
    const float* lnb = (const float*)d_in[20];
    float* out = (float*)d_out;

    float *p_xz, *p_xi, *p_dbc, *p_dbcp, *p_dt, *p_out;
    cudaGetSymbolAddress((void**)&p_xz,   g_xz);
    cudaGetSymbolAddress((void**)&p_xi,   g_xi);
    cudaGetSymbolAddress((void**)&p_dbc,  g_dbc);
    cudaGetSymbolAddress((void**)&p_dbcp, g_dbcp);
    cudaGetSymbolAddress((void**)&p_dt,   g_dt);
    cudaGetSymbolAddress((void**)&p_out,  g_outd);
    __half *p_xh, *p_winh, *p_xih, *p_xprojh, *p_dbch, *p_dtwh, *p_yh, *p_wouth;
    cudaGetSymbolAddress((void**)&p_xh,     g_xh);
    cudaGetSymbolAddress((void**)&p_winh,   g_winh);
    cudaGetSymbolAddress((void**)&p_xih,    g_xih);
    cudaGetSymbolAddress((void**)&p_xprojh, g_xprojh);
    cudaGetSymbolAddress((void**)&p_dbch,   g_dbch);
    cudaGetSymbolAddress((void**)&p_dtwh,   g_dtwh);
    cudaGetSymbolAddress((void**)&p_yh,     g_yh);
    cudaGetSymbolAddress((void**)&p_wouth,  g_wouth);

    const size_t sXZ  = (size_t)NROWS*XZN;
    const size_t sIN  = (size_t)NROWS*DINNER;
    const size_t sDBC = (size_t)NROWS*DBCN;
    const size_t sMD  = (size_t)NROWS*DMODEL;
    const int SMEM = 3*HSTG;

    cudaFuncSetAttribute(hgemm<0>, cudaFuncAttributeMaxDynamicSharedMemorySize, SMEM);
    cudaFuncSetAttribute(hgemm<1>, cudaFuncAttributeMaxDynamicSharedMemorySize, SMEM);
    cudaFuncSetAttribute(hgemm<2>, cudaFuncAttributeMaxDynamicSharedMemorySize, SMEM);

    prepA_kernel<<<2, 256>>>(Alog[0], Alog[1]);

    // one fused conversion launch (x + all weights)
    {
        CvtSegs cs;
        const float* srcs[9] = {x, Win[0], Win[1], xproj[0], xproj[1],
                                dtw[0], dtw[1], Wout[0], Wout[1]};
        __half* dsts[9] = {p_xh, p_winh, p_winh + (size_t)XZN*DMODEL,
                           p_xprojh, p_xprojh + (size_t)DBCN*DINNER,
                           p_dtwh, p_dtwh + (size_t)DINNER*64,
                           p_wouth, p_wouth + (size_t)DMODEL*DINNER};
        int cnts[9] = {NROWS*DMODEL, XZN*DMODEL, XZN*DMODEL,
                       DBCN*DINNER, DBCN*DINNER, DINNER*64, DINNER*64,
                       DMODEL*DINNER, DMODEL*DINNER};
        int off = 0;
        for (int i = 0; i < 9; i++) { cs.s[i]=srcs[i]; cs.d[i]=dsts[i]; cs.off[i]=off; off+=cnts[i]; }
        cs.off[9] = off;
        f2h_multi_kernel<<<(off/4 + 255)/256, 256>>>(cs);
    }

    // in_proj: xz = x @ Win^T (N=4096, K=1024), fp32 out; dir-1 rows reversed
    hgemm<0><<<dim3(XZN/128, NROWS/128, 2), 256, SMEM>>>(
        p_xh, p_xh, p_winh, p_winh + (size_t)XZN*DMODEL, nullptr, nullptr,
        p_xz, p_xz + sXZ, XZN, XZN, DMODEL, DMODEL, DMODEL, 1, 0, 1);

    conv_silu_kernel<<<dim3((NROWS*(DINNER/4) + 255)/256, 1, 2), 256>>>(
        cw[0], cw[1], cbv[0], cbv[1]);

    // x_proj split-K (N=96, K=256/split), fp32 partials
    hgemm<0><<<dim3(1, NROWS/128, 2*NSPLIT), 256, SMEM>>>(
        p_xih, p_xih + sIN, p_xprojh, p_xprojh + (size_t)DBCN*DINNER,
        nullptr, nullptr,
        p_dbcp, p_dbcp + NSPLIT*sDBC, DBCN, DBCN, DINNER/NSPLIT, DINNER, DINNER,
        NSPLIT, sDBC, 0);
    reduce_dbc_kernel<<<(2*NROWS*DBCN + 255)/256, 256>>>();

    // dt = softplus(dbc[:, :64] @ dtw^T + dtb) (N=2048, K=64), fp32 out
    hgemm<1><<<dim3(DINNER/128, NROWS/128, 2), 256, SMEM>>>(
        p_dbch, p_dbch + sDBC, p_dtwh, p_dtwh + (size_t)DINNER*64, dtb[0], dtb[1],
        p_dt, p_dt + sIN, DINNER, DINNER, 64, DBCN, 64, 1, 0, 0);

    scan_kernel<<<dim3(DINNER/64, BATCH, 2), 64>>>(Dp[0], Dp[1]);

    // out = sigmoid(y @ Wout^T) (N=1024, K=2048), fp32 out
    hgemm<2><<<dim3(DMODEL/128, NROWS/128, 2), 256, SMEM>>>(
        p_yh, p_yh + sIN, p_wouth, p_wouth + (size_t)DMODEL*DINNER,
        nullptr, nullptr,
        p_out, p_out + sMD, DMODEL, DMODEL, DINNER, DINNER, DINNER, 1, 0, 0);

    combine_ln_kernel<<<NROWS, 256>>>(x, lng, lnb, out);
}

// round 11
// speedup vs baseline: 1.4953x; 1.0079x over previous
#include <cuda_runtime.h>
#include <cuda_fp16.h>
#include <math.h>
#include <stdint.h>

#define BATCH  2
#define SEQ    1024
#define DMODEL 1024
#define DINNER 2048
#define DSTATE 16
#define NROWS  (BATCH*SEQ)      // 2048
#define DBCN   96
#define XZN    (2*DINNER)       // 4096
#define NSPLIT 8

// ---------------- scratch (fp32) -------------------------------------------
__device__ float g_xz  [2][(size_t)NROWS*XZN];
__device__ float g_xi  [2][(size_t)NROWS*DINNER];
__device__ float g_dbc [2][(size_t)NROWS*DBCN];
__device__ float g_dbcp[2][NSPLIT][(size_t)NROWS*DBCN];
__device__ float g_dt  [2][(size_t)NROWS*DINNER];
__device__ float g_outd[2][(size_t)NROWS*DMODEL];
__device__ float g_A   [2][DINNER*DSTATE];
__device__ int   g_fastA[2];

// ---------------- scratch (fp16 GEMM operands) ------------------------------
__device__ __half g_xh    [(size_t)NROWS*DMODEL];
__device__ __half g_winh  [2][(size_t)XZN*DMODEL];
__device__ __half g_xih   [2][(size_t)NROWS*DINNER];
__device__ __half g_xprojh[2][(size_t)DBCN*DINNER];
__device__ __half g_dbch  [2][(size_t)NROWS*DBCN];
__device__ __half g_dtwh  [2][(size_t)DINNER*64];
__device__ __half g_yh    [2][(size_t)NROWS*DINNER];
__device__ __half g_wouth [2][(size_t)DMODEL*DINNER];

// ---------------- helpers ---------------------------------------------------
__device__ __forceinline__ uint32_t smem_u32(const void* p) {
    uint32_t a;
    asm("{ .reg .u64 t; cvta.to.shared.u64 t, %1; cvt.u32.u64 %0, t; }"
        : "=r"(a) : "l"(p));
    return a;
}
__device__ __forceinline__ void cp16(uint32_t dst, const void* src, int sz) {
    asm volatile("cp.async.cg.shared.global [%0], [%1], 16, %2;"
                 :: "r"(dst), "l"(src), "r"(sz) : "memory");
}
__device__ __forceinline__ void cp_commit() {
    asm volatile("cp.async.commit_group;" ::: "memory");
}
__device__ __forceinline__ void cp_wait1() {
    asm volatile("cp.async.wait_group 1;" ::: "memory");
}
#define LDSM4(r0,r1,r2,r3,a) \
    asm volatile("ldmatrix.sync.aligned.m8n8.x4.shared.b16 {%0,%1,%2,%3}, [%4];" \
                 : "=r"(r0),"=r"(r1),"=r"(r2),"=r"(r3) : "r"(a))

// ---------------- fused fp32->fp16 conversion (9 segments, 1 launch) --------
struct CvtSegs {
    const float* s[9];
    __half*      d[9];
    int          off[10];
};
__global__ void f2h_multi_kernel(CvtSegs segs) {
    int i4 = (blockIdx.x*blockDim.x + threadIdx.x) * 4;
    if (i4 >= segs.off[9]) return;
    int j = 0;
    #pragma unroll
    for (int k = 1; k < 9; k++) j += (i4 >= segs.off[k]);
    int local = i4 - segs.off[j];
    float4 v = *(const float4*)(segs.s[j] + local);
    __half* dst = segs.d[j] + local;
    *(__half2*)(dst)   = __floats2half2_rn(v.x, v.y);
    *(__half2*)(dst+2) = __floats2half2_rn(v.z, v.w);
}

__global__ void prepA_kernel(const float* __restrict__ Alog0,
                             const float* __restrict__ Alog1) {
    int dir = blockIdx.x;
    const float* Alog = dir ? Alog1 : Alog0;
    __shared__ int ok;
    if (threadIdx.x == 0) ok = 1;
    __syncthreads();
    bool good = true;
    for (int i = threadIdx.x; i < DINNER*DSTATE; i += blockDim.x) {
        float a = -__expf(Alog[i]);
        g_A[dir][i] = a;
        int s = i & (DSTATE-1);
        if (fabsf(a + (float)(s+1)) > 1e-3f * (float)(s+1)) good = false;
    }
    if (!good) atomicExch(&ok, 0);
    __syncthreads();
    if (threadIdx.x == 0) g_fastA[dir] = ok;
}

// ==============  FP16 mma.sync GEMM (m16n8k16) ==============================
// CTA 128x128, BK=64 (two proven 8KB 32-k sub-blocks per operand per stage),
// 3-stage cp.async, TWO barriers per k-iter, stage_load issued BEFORE compute
// (R8-proven ordering — do not reorder). Accumulation order identical to R8.
// EPI: 0 none, 1 softplus(+bias), 2 sigmoid.  fp32 C output.

#define HSTG 32768      // A 16KB (2 x 8KB sub-blocks) + B 16KB

template<int EPI>
__global__ __launch_bounds__(256, 2)
void hgemm(const __half* __restrict__ A0, const __half* __restrict__ A1,
           const __half* __restrict__ W0, const __half* __restrict__ W1,
           const float* __restrict__ b0, const float* __restrict__ b1,
           float* __restrict__ C0, float* __restrict__ C1,
           int N, int Ntot, int Ksub, int lda, int ldw,
           int nsplit, size_t csplit, int revA) {
    const int dir   = blockIdx.z / nsplit;
    const int split = blockIdx.z - dir*nsplit;
    const __half* A = dir ? A1 : A0;
    const __half* W = dir ? W1 : W0;
    const float* bias = dir ? b1 : b0;
    float* C = (dir ? C1 : C0) + (size_t)split * csplit;
    const int koff = split * Ksub;
    const int rev  = revA && dir;

    extern __shared__ __align__(16) char sm[];
    const uint32_t sbase = smem_u32(sm);

    const int tid  = threadIdx.x;
    const int lane = tid & 31;
    const int wid  = tid >> 5;
    const int warp_m = (wid & 1) * 64;
    const int warp_n = (wid >> 1) * 32;
    const int m0 = blockIdx.y * 128;
    const int n0 = blockIdx.x * 128;

    const int lrow = tid >> 2;
    const int lkc  = tid & 3;

    // sub-block-relative ldmatrix addresses (identical to R8's proven layout)
    uint32_t aaddr[4], baddr[2];
    {
        int ar = warp_m + (lane & 7) + ((lane >> 3) & 1) * 8;
        int acb = (lane >> 4) & 1;
        #pragma unroll
        for (int mi = 0; mi < 4; mi++) {
            int r = ar + mi*16;
            aaddr[mi] = r*64 + ((acb ^ ((r>>1)&3))*16);
        }
        int br = warp_n + (lane & 7) + ((lane >> 4) & 1) * 8;
        int bcb = (lane >> 3) & 1;
        #pragma unroll
        for (int p = 0; p < 2; p++) {
            int r = br + p*16;
            baddr[p] = r*64 + ((bcb ^ ((r>>1)&3))*16);
        }
    }

    float acc[4][4][4];
    #pragma unroll
    for (int i = 0; i < 4; i++)
        #pragma unroll
        for (int j = 0; j < 4; j++)
            #pragma unroll
            for (int r = 0; r < 4; r++) acc[i][j][r] = 0.f;

    const int nk = Ksub / 64;

    auto stage_load = [&](int it) {
        uint32_t sA = sbase + (it % 3)*HSTG;          // A sub0 @0, sub1 @8192
        uint32_t sB = sA + 16384;                      // B sub0 @0, sub1 @8192
        int k0 = koff + it*64;
        #pragma unroll
        for (int kh = 0; kh < 2; kh++) {
            int kk = k0 + kh*32;
            #pragma unroll
            for (int j = 0; j < 2; j++) {
                int row = lrow + j*64;
                int gm = m0 + row;
                if (rev) gm = (gm & ~(SEQ-1)) | ((SEQ-1) - (gm & (SEQ-1)));
                uint32_t d = sA + kh*8192 + row*64 + ((lkc ^ ((row>>1)&3))*16);
                cp16(d, A + (size_t)gm*lda + kk + lkc*8, 16);
            }
            #pragma unroll
            for (int j = 0; j < 2; j++) {
                int row = lrow + j*64;
                int wr = n0 + row;
                int valid = (wr < N);
                uint32_t d = sB + kh*8192 + row*64 + ((lkc ^ ((row>>1)&3))*16);
                cp16(d, W + (size_t)(valid ? wr : 0)*ldw + kk + lkc*8, valid ? 16 : 0);
            }
        }
        cp_commit();
    };

    stage_load(0);
    if (nk > 1) stage_load(1); else cp_commit();

    for (int it = 0; it < nk; it++) {
        cp_wait1();
        __syncthreads();
        if (it + 2 < nk) stage_load(it + 2); else cp_commit();

        uint32_t sb = sbase + (it % 3)*HSTG;
        #pragma unroll
        for (int ks4 = 0; ks4 < 4; ks4++) {
            const uint32_t sub = (uint32_t)(ks4 >> 1) * 8192;
            const uint32_t kx  = (uint32_t)(ks4 & 1) * 32;
            uint32_t af[4][4];
            #pragma unroll
            for (int mi = 0; mi < 4; mi++)
                LDSM4(af[mi][0], af[mi][1], af[mi][2], af[mi][3],
                      sb + sub + (aaddr[mi] ^ kx));
            uint32_t bf[4][2];
            #pragma unroll
            for (int p = 0; p < 2; p++)
                LDSM4(bf[2*p][0], bf[2*p][1], bf[2*p+1][0], bf[2*p+1][1],
                      sb + 16384 + sub + (baddr[p] ^ kx));
            #pragma unroll
            for (int mi = 0; mi < 4; mi++)
                #pragma unroll
                for (int ni = 0; ni < 4; ni++) {
                    asm volatile(
                        "mma.sync.aligned.m16n8k16.row.col.f32.f16.f16.f32 "
                        "{%0,%1,%2,%3}, {%4,%5,%6,%7}, {%8,%9}, {%0,%1,%2,%3};"
                        : "+f"(acc[mi][ni][0]), "+f"(acc[mi][ni][1]),
                          "+f"(acc[mi][ni][2]), "+f"(acc[mi][ni][3])
                        : "r"(af[mi][0]), "r"(af[mi][1]),
                          "r"(af[mi][2]), "r"(af[mi][3]),
                          "r"(bf[ni][0]), "r"(bf[ni][1]));
                }
        }
        __syncthreads();
    }

    // epilogue
    #pragma unroll
    for (int mi = 0; mi < 4; mi++) {
        #pragma unroll
        for (int ni = 0; ni < 4; ni++) {
            int row = m0 + warp_m + mi*16 + (lane>>2);
            int col = n0 + warp_n + ni*8 + 2*(lane&3);
            #pragma unroll
            for (int half = 0; half < 2; half++) {
                int r = row + half*8;
                float v0 = acc[mi][ni][half*2+0];
                float v1 = acc[mi][ni][half*2+1];
                if (EPI == 1) {
                    v0 += bias[col];   v1 += bias[col+1];
                    v0 = (v0 > 20.f) ? v0 : log1pf(__expf(v0));
                    v1 = (v1 > 20.f) ? v1 : log1pf(__expf(v1));
                } else if (EPI == 2) {
                    v0 = 1.f / (1.f + __expf(-v0));
                    v1 = 1.f / (1.f + __expf(-v1));
                }
                if (col + 1 < N)
                    *(float2*)(C + (size_t)r*Ntot + col) = make_float2(v0, v1);
            }
        }
    }
}

// ---------------- split-K reduce for x_proj ---------------------------------
__global__ void reduce_dbc_kernel() {
    int idx = blockIdx.x * blockDim.x + threadIdx.x;
    const int TOT = NROWS*DBCN;
    if (idx >= 2*TOT) return;
    int dir = idx / TOT;
    int e = idx - dir*TOT;
    float s = 0.f;
    #pragma unroll
    for (int p = 0; p < NSPLIT; p++) s += g_dbcp[dir][p][e];
    g_dbc[dir][e] = s;
    g_dbch[dir][e] = __float2half(s);
}

// ---------------- causal depthwise conv (k=4) + SiLU, row pairs -------------
// reads fp32 xz; writes fp32 xi (scan) + fp16 xi (x_proj GEMM)
// each thread handles rows (2p, 2p+1) for one 4-channel group: 5 loads / 2 rows
__global__ void conv_silu_kernel(const float* __restrict__ w0, const float* __restrict__ w1,
                                 const float* __restrict__ cb0, const float* __restrict__ cb1) {
    int dir = blockIdx.z;
    const float* w  = dir ? w1 : w0;
    const float* cb = dir ? cb1 : cb0;
    int idx = blockIdx.x * blockDim.x + threadIdx.x;
    const int NC4 = DINNER/4;
    const int NPAIR = NROWS/2;
    if (idx >= NPAIR * NC4) return;
    int c4 = idx % NC4;
    int pr = idx / NC4;
    int row0 = pr * 2;
    int l0 = row0 & (SEQ-1);
    const float* base = g_xz[dir] + (size_t)row0*XZN + c4*4;
    float4 xp1 = *(const float4*)(base + XZN);            // row0+1 (always valid)
    float4 x0  = *(const float4*)(base);
    float4 xm1 = (l0>=1) ? *(const float4*)(base - 1*XZN) : make_float4(0,0,0,0);
    float4 xm2 = (l0>=2) ? *(const float4*)(base - 2*XZN) : make_float4(0,0,0,0);
    float4 xm3 = (l0>=3) ? *(const float4*)(base - 3*XZN) : make_float4(0,0,0,0);
    float4 cbv = ((const float4*)cb)[c4];

    float o0[4], o1[4];
    const float* cbp = (const float*)&cbv;
    const float* pxp1 = (const float*)&xp1;
    const float* px0  = (const float*)&x0;
    const float* pxm1 = (const float*)&xm1;
    const float* pxm2 = (const float*)&xm2;
    const float* pxm3 = (const float*)&xm3;
    #pragma unroll
    for (int c = 0; c < 4; c++) {
        float4 wv = ((const float4*)w)[c4*4+c];
        // row0: w0*x[-3] + w1*x[-2] + w2*x[-1] + w3*x[0]
        float a = cbp[c];
        a = fmaf(wv.x, pxm3[c], a);
        a = fmaf(wv.y, pxm2[c], a);
        a = fmaf(wv.z, pxm1[c], a);
        a = fmaf(wv.w, px0[c], a);
        o0[c] = a / (1.f + __expf(-a));
        // row1: w0*x[-2] + w1*x[-1] + w2*x[0] + w3*x[1]
        float b = cbp[c];
        b = fmaf(wv.x, pxm2[c], b);
        b = fmaf(wv.y, pxm1[c], b);
        b = fmaf(wv.z, px0[c], b);
        b = fmaf(wv.w, pxp1[c], b);
        o1[c] = b / (1.f + __expf(-b));
    }
    float* f0 = g_xi[dir] + (size_t)row0*DINNER + c4*4;
    *(float4*)(f0)          = make_float4(o0[0], o0[1], o0[2], o0[3]);
    *(float4*)(f0 + DINNER) = make_float4(o1[0], o1[1], o1[2], o1[3]);
    __half* h0 = g_xih[dir] + (size_t)row0*DINNER + c4*4;
    *(__half2*)(h0)            = __floats2half2_rn(o0[0], o0[1]);
    *(__half2*)(h0+2)          = __floats2half2_rn(o0[2], o0[3]);
    *(__half2*)(h0+DINNER)     = __floats2half2_rn(o1[0], o1[1]);
    *(__half2*)(h0+DINNER+2)   = __floats2half2_rn(o1[2], o1[3]);
}

// ---------------- selective scan (fp32 in, y out as fp16) -------------------
__global__ __launch_bounds__(64)
void scan_kernel(const float* __restrict__ D0, const float* __restrict__ D1) {
    int dir = blockIdx.z;
    const float* Dp = dir ? D1 : D0;
    int d = blockIdx.x * 64 + threadIdx.x;
    int b = blockIdx.y;
    int lane = threadIdx.x & 31;

    const float* dtp = g_dt[dir]  + (size_t)b*SEQ*DINNER + d;
    const float* xip = g_xi[dir]  + (size_t)b*SEQ*DINNER + d;
    const float* zp  = g_xz[dir]  + (size_t)b*SEQ*XZN + DINNER + d;
    const float* vp  = g_dbc[dir] + (size_t)b*SEQ*DBCN + 64 + lane;
    __half* yp       = g_yh[dir]  + (size_t)b*SEQ*DINNER + d;

    float h[DSTATE];
    #pragma unroll
    for (int s = 0; s < DSTATE; s++) h[s] = 0.f;
    float Av[DSTATE];
    #pragma unroll
    for (int s = 0; s < DSTATE; s++) Av[s] = g_A[dir][d*DSTATE + s];
    float Dv = Dp[d];
    int fast = g_fastA[dir];

    #pragma unroll 1
    for (int l0 = 0; l0 < SEQ; l0 += 4) {
        float cdt[4], cxi[4], cz[4], cv[4];
        #pragma unroll
        for (int u = 0; u < 4; u++) {
            int r = l0 + u;
            cdt[u] = dtp[(size_t)r*DINNER];
            cxi[u] = xip[(size_t)r*DINNER];
            cz[u]  = zp [(size_t)r*XZN];
            cv[u]  = vp [(size_t)r*DBCN];
        }
        #pragma unroll
        for (int u = 0; u < 4; u++) {
            float dt = cdt[u], xi = cxi[u], z = cz[u], v = cv[u];
            float dtxi = dt * xi;
            float acc = 0.f;
            if (fast) {
                float e = __expf(-dt);
                float p = 1.f;
                #pragma unroll
                for (int s = 0; s < DSTATE; s++) {
                    p *= e;
                    float bs = __shfl_sync(0xffffffffu, v, s);
                    float cs = __shfl_sync(0xffffffffu, v, 16 + s);
                    h[s] = fmaf(p, h[s], dtxi * bs);
                    acc = fmaf(h[s], cs, acc);
                }
            } else {
                #pragma unroll
                for (int s = 0; s < DSTATE; s++) {
                    float a = __expf(dt * Av[s]);
                    float bs = __shfl_sync(0xffffffffu, v, s);
                    float cs = __shfl_sync(0xffffffffu, v, 16 + s);
                    h[s] = fmaf(a, h[s], dtxi * bs);
                    acc = fmaf(h[s], cs, acc);
                }
            }
            float sz = z / (1.f + __expf(-z));
            yp[(size_t)(l0+u)*DINNER] = __float2half((acc + xi * Dv) * sz);
        }
    }
}

// ---------------- combine dirs + LayerNorm + residual ----------------------
__global__ __launch_bounds__(256)
void combine_ln_kernel(const float* __restrict__ x,
                       const float* __restrict__ lng, const float* __restrict__ lnb,
                       float* __restrict__ out) {
    int row = blockIdx.x;
    int b = row / SEQ, l = row % SEQ;
    const float* f  = g_outd[0] + (size_t)row*DMODEL;
    const float* bk = g_outd[1] + (size_t)(b*SEQ + (SEQ-1-l))*DMODEL;
    int tid = threadIdx.x;

    float vals[4];
    float s = 0.f, s2 = 0.f;
    #pragma unroll
    for (int j = 0; j < 4; j++) {
        int i = tid + j*256;
        float dv = 0.5f * (f[i] + bk[i]);
        vals[j] = dv;
        s += dv; s2 += dv*dv;
    }
    #pragma unroll
    for (int o = 16; o; o >>= 1) {
        s  += __shfl_xor_sync(0xffffffffu, s,  o);
        s2 += __shfl_xor_sync(0xffffffffu, s2, o);
    }
    __shared__ float sh[2][8];
    if ((tid & 31) == 0) { sh[0][tid>>5] = s; sh[1][tid>>5] = s2; }
    __syncthreads();
    if (tid < 32) {
        float a  = (tid < 8) ? sh[0][tid] : 0.f;
        float a2 = (tid < 8) ? sh[1][tid] : 0.f;
        #pragma unroll
        for (int o = 4; o; o >>= 1) {
            a  += __shfl_xor_sync(0xffffffffu, a,  o);
            a2 += __shfl_xor_sync(0xffffffffu, a2, o);
        }
        if (tid == 0) { sh[0][0] = a; sh[1][0] = a2; }
    }
    __syncthreads();
    float mu  = sh[0][0] * (1.f/DMODEL);
    float var = sh[1][0] * (1.f/DMODEL) - mu*mu;
    float rstd = rsqrtf(var + 1e-5f);
    #pragma unroll
    for (int j = 0; j < 4; j++) {
        int i = tid + j*256;
        out[(size_t)row*DMODEL + i] =
            (vals[j] - mu) * rstd * lng[i] + lnb[i] + x[(size_t)row*DMODEL + i];
    }
}

// ---------------- host launcher --------------------------------------------
extern "C" void kernel_launch(void* const* d_in, const int* in_sizes, int n_in,
                              void* d_out, int out_size) {
    (void)in_sizes; (void)n_in; (void)out_size;
    const float* x       = (const float*)d_in[0];
    const float* Win[2]  = {(const float*)d_in[1],  (const float*)d_in[10]};
    const float* cw[2]   = {(const float*)d_in[2],  (const float*)d_in[11]};
    const float* cbv[2]  = {(const float*)d_in[3],  (const float*)d_in[12]};
    const float* xproj[2]= {(const float*)d_in[4],  (const float*)d_in[13]};
    const float* dtw[2]  = {(const float*)d_in[5],  (const float*)d_in[14]};
    const float* dtb[2]  = {(const float*)d_in[6],  (const float*)d_in[15]};
    const float* Alog[2] = {(const float*)d_in[7],  (const float*)d_in[16]};
    const float* Dp[2]   = {(const float*)d_in[8],  (const float*)d_in[17]};
    const float* Wout[2] = {(const float*)d_in[9],  (const float*)d_in[18]};
    const float* lng = (const float*)d_in[19];
    const float* lnb = (const float*)d_in[20];
    float* out = (float*)d_out;

    float *p_xz, *p_xi, *p_dbc, *p_dbcp, *p_dt, *p_out;
    cudaGetSymbolAddress((void**)&p_xz,   g_xz);
    cudaGetSymbolAddress((void**)&p_xi,   g_xi);
    cudaGetSymbolAddress((void**)&p_dbc,  g_dbc);
    cudaGetSymbolAddress((void**)&p_dbcp, g_dbcp);
    cudaGetSymbolAddress((void**)&p_dt,   g_dt);
    cudaGetSymbolAddress((void**)&p_out,  g_outd);
    __half *p_xh, *p_winh, *p_xih, *p_xprojh, *p_dbch, *p_dtwh, *p_yh, *p_wouth;
    cudaGetSymbolAddress((void**)&p_xh,     g_xh);
    cudaGetSymbolAddress((void**)&p_winh,   g_winh);
    cudaGetSymbolAddress((void**)&p_xih,    g_xih);
    cudaGetSymbolAddress((void**)&p_xprojh, g_xprojh);
    cudaGetSymbolAddress((void**)&p_dbch,   g_dbch);
    cudaGetSymbolAddress((void**)&p_dtwh,   g_dtwh);
    cudaGetSymbolAddress((void**)&p_yh,     g_yh);
    cudaGetSymbolAddress((void**)&p_wouth,  g_wouth);

    const size_t sXZ  = (size_t)NROWS*XZN;
    const size_t sIN  = (size_t)NROWS*DINNER;
    const size_t sDBC = (size_t)NROWS*DBCN;
    const size_t sMD  = (size_t)NROWS*DMODEL;
    const int SMEM = 3*HSTG;   // 98304

    cudaFuncSetAttribute(hgemm<0>, cudaFuncAttributeMaxDynamicSharedMemorySize, SMEM);
    cudaFuncSetAttribute(hgemm<1>, cudaFuncAttributeMaxDynamicSharedMemorySize, SMEM);
    cudaFuncSetAttribute(hgemm<2>, cudaFuncAttributeMaxDynamicSharedMemorySize, SMEM);

    prepA_kernel<<<2, 256>>>(Alog[0], Alog[1]);

    // one fused conversion launch (x + all weights)
    {
        CvtSegs cs;
        const float* srcs[9] = {x, Win[0], Win[1], xproj[0], xproj[1],
                                dtw[0], dtw[1], Wout[0], Wout[1]};
        __half* dsts[9] = {p_xh, p_winh, p_winh + (size_t)XZN*DMODEL,
                           p_xprojh, p_xprojh + (size_t)DBCN*DINNER,
                           p_dtwh, p_dtwh + (size_t)DINNER*64,
                           p_wouth, p_wouth + (size_t)DMODEL*DINNER};
        int cnts[9] = {NROWS*DMODEL, XZN*DMODEL, XZN*DMODEL,
                       DBCN*DINNER, DBCN*DINNER, DINNER*64, DINNER*64,
                       DMODEL*DINNER, DMODEL*DINNER};
        int off = 0;
        for (int i = 0; i < 9; i++) { cs.s[i]=srcs[i]; cs.d[i]=dsts[i]; cs.off[i]=off; off+=cnts[i]; }
        cs.off[9] = off;
        f2h_multi_kernel<<<(off/4 + 255)/256, 256>>>(cs);
    }

    // in_proj: xz = x @ Win^T (N=4096, K=1024), fp32 out; dir-1 rows reversed
    hgemm<0><<<dim3(XZN/128, NROWS/128, 2), 256, SMEM>>>(
        p_xh, p_xh, p_winh, p_winh + (size_t)XZN*DMODEL, nullptr, nullptr,
        p_xz, p_xz + sXZ, XZN, XZN, DMODEL, DMODEL, DMODEL, 1, 0, 1);

    conv_silu_kernel<<<dim3(((NROWS/2)*(DINNER/4) + 255)/256, 1, 2), 256>>>(
        cw[0], cw[1], cbv[0], cbv[1]);

    // x_proj split-K (N=96, K=256/split), fp32 partials
    hgemm<0><<<dim3(1, NROWS/128, 2*NSPLIT), 256, SMEM>>>(
        p_xih, p_xih + sIN, p_xprojh, p_xprojh + (size_t)DBCN*DINNER,
        nullptr, nullptr,
        p_dbcp, p_dbcp + NSPLIT*sDBC, DBCN, DBCN, DINNER/NSPLIT, DINNER, DINNER,
        NSPLIT, sDBC, 0);
    reduce_dbc_kernel<<<(2*NROWS*DBCN + 255)/256, 256>>>();

    // dt = softplus(dbc[:, :64] @ dtw^T + dtb) (N=2048, K=64), fp32 out
    hgemm<1><<<dim3(DINNER/128, NROWS/128, 2), 256, SMEM>>>(
        p_dbch, p_dbch + sDBC, p_dtwh, p_dtwh + (size_t)DINNER*64, dtb[0], dtb[1],
        p_dt, p_dt + sIN, DINNER, DINNER, 64, DBCN, 64, 1, 0, 0);

    scan_kernel<<<dim3(DINNER/64, BATCH, 2), 64>>>(Dp[0], Dp[1]);

    // out = sigmoid(y @ Wout^T) (N=1024, K=2048), fp32 out
    hgemm<2><<<dim3(DMODEL/128, NROWS/128, 2), 256, SMEM>>>(
        p_yh, p_yh + sIN, p_wouth, p_wouth + (size_t)DMODEL*DINNER,
        nullptr, nullptr,
        p_out, p_out + sMD, DMODEL, DMODEL, DINNER, DINNER, DINNER, 1, 0, 0);

    combine_ln_kernel<<<NROWS, 256>>>(x, lng, lnb, out);
}

// round 12
// speedup vs baseline: 2.4937x; 1.6676x over previous
#include <cuda_runtime.h>
#include <cuda_fp16.h>
#include <math.h>
#include <stdint.h>

#define BATCH  2
#define SEQ    1024
#define DMODEL 1024
#define DINNER 2048
#define DSTATE 16
#define NROWS  (BATCH*SEQ)      // 2048
#define DBCN   96
#define XZN    (2*DINNER)       // 4096
#define NSPLIT 8
#define NCHUNK 8
#define CHLEN  (SEQ/NCHUNK)     // 128

// ---------------- scratch (fp32) -------------------------------------------
__device__ float g_xz  [2][(size_t)NROWS*XZN];
__device__ float g_xi  [2][(size_t)NROWS*DINNER];
__device__ float g_dbc [2][(size_t)NROWS*DBCN];
__device__ float g_dbcp[2][NSPLIT][(size_t)NROWS*DBCN];
__device__ float g_dt  [2][(size_t)NROWS*DINNER];
__device__ float g_outd[2][(size_t)NROWS*DMODEL];
__device__ float g_A   [2][DINNER*DSTATE];
__device__ int   g_fastA[2];
// chunked-scan state
__device__ float g_hloc[2][BATCH][NCHUNK][DSTATE][DINNER];
__device__ float g_hini[2][BATCH][NCHUNK][DSTATE][DINNER];
__device__ float g_sdt [2][BATCH][NCHUNK][DINNER];

// ---------------- scratch (fp16 GEMM operands) ------------------------------
__device__ __half g_xh    [(size_t)NROWS*DMODEL];
__device__ __half g_winh  [2][(size_t)XZN*DMODEL];
__device__ __half g_xih   [2][(size_t)NROWS*DINNER];
__device__ __half g_xprojh[2][(size_t)DBCN*DINNER];
__device__ __half g_dbch  [2][(size_t)NROWS*DBCN];
__device__ __half g_dtwh  [2][(size_t)DINNER*64];
__device__ __half g_yh    [2][(size_t)NROWS*DINNER];
__device__ __half g_wouth [2][(size_t)DMODEL*DINNER];

// ---------------- helpers ---------------------------------------------------
__device__ __forceinline__ uint32_t smem_u32(const void* p) {
    uint32_t a;
    asm("{ .reg .u64 t; cvta.to.shared.u64 t, %1; cvt.u32.u64 %0, t; }"
        : "=r"(a) : "l"(p));
    return a;
}
__device__ __forceinline__ void cp16(uint32_t dst, const void* src, int sz) {
    asm volatile("cp.async.cg.shared.global [%0], [%1], 16, %2;"
                 :: "r"(dst), "l"(src), "r"(sz) : "memory");
}
__device__ __forceinline__ void cp_commit() {
    asm volatile("cp.async.commit_group;" ::: "memory");
}
__device__ __forceinline__ void cp_wait1() {
    asm volatile("cp.async.wait_group 1;" ::: "memory");
}
#define LDSM4(r0,r1,r2,r3,a) \
    asm volatile("ldmatrix.sync.aligned.m8n8.x4.shared.b16 {%0,%1,%2,%3}, [%4];" \
                 : "=r"(r0),"=r"(r1),"=r"(r2),"=r"(r3) : "r"(a))

// ---------------- fused fp32->fp16 conversion (9 segments, 1 launch) --------
struct CvtSegs {
    const float* s[9];
    __half*      d[9];
    int          off[10];
};
__global__ void f2h_multi_kernel(CvtSegs segs) {
    int i4 = (blockIdx.x*blockDim.x + threadIdx.x) * 4;
    if (i4 >= segs.off[9]) return;
    int j = 0;
    #pragma unroll
    for (int k = 1; k < 9; k++) j += (i4 >= segs.off[k]);
    int local = i4 - segs.off[j];
    float4 v = *(const float4*)(segs.s[j] + local);
    __half* dst = segs.d[j] + local;
    *(__half2*)(dst)   = __floats2half2_rn(v.x, v.y);
    *(__half2*)(dst+2) = __floats2half2_rn(v.z, v.w);
}

__global__ void prepA_kernel(const float* __restrict__ Alog0,
                             const float* __restrict__ Alog1) {
    int dir = blockIdx.x;
    const float* Alog = dir ? Alog1 : Alog0;
    __shared__ int ok;
    if (threadIdx.x == 0) ok = 1;
    __syncthreads();
    bool good = true;
    for (int i = threadIdx.x; i < DINNER*DSTATE; i += blockDim.x) {
        float a = -__expf(Alog[i]);
        g_A[dir][i] = a;
        int s = i & (DSTATE-1);
        if (fabsf(a + (float)(s+1)) > 1e-3f * (float)(s+1)) good = false;
    }
    if (!good) atomicExch(&ok, 0);
    __syncthreads();
    if (threadIdx.x == 0) g_fastA[dir] = ok;
}

// ==============  FP16 mma.sync GEMM (m16n8k16) — frozen R10 =================
#define HSTG 32768

template<int EPI>
__global__ __launch_bounds__(256, 2)
void hgemm(const __half* __restrict__ A0, const __half* __restrict__ A1,
           const __half* __restrict__ W0, const __half* __restrict__ W1,
           const float* __restrict__ b0, const float* __restrict__ b1,
           float* __restrict__ C0, float* __restrict__ C1,
           int N, int Ntot, int Ksub, int lda, int ldw,
           int nsplit, size_t csplit, int revA) {
    const int dir   = blockIdx.z / nsplit;
    const int split = blockIdx.z - dir*nsplit;
    const __half* A = dir ? A1 : A0;
    const __half* W = dir ? W1 : W0;
    const float* bias = dir ? b1 : b0;
    float* C = (dir ? C1 : C0) + (size_t)split * csplit;
    const int koff = split * Ksub;
    const int rev  = revA && dir;

    extern __shared__ __align__(16) char sm[];
    const uint32_t sbase = smem_u32(sm);

    const int tid  = threadIdx.x;
    const int lane = tid & 31;
    const int wid  = tid >> 5;
    const int warp_m = (wid & 1) * 64;
    const int warp_n = (wid >> 1) * 32;
    const int m0 = blockIdx.y * 128;
    const int n0 = blockIdx.x * 128;

    const int lrow = tid >> 2;
    const int lkc  = tid & 3;

    uint32_t aaddr[4], baddr[2];
    {
        int ar = warp_m + (lane & 7) + ((lane >> 3) & 1) * 8;
        int acb = (lane >> 4) & 1;
        #pragma unroll
        for (int mi = 0; mi < 4; mi++) {
            int r = ar + mi*16;
            aaddr[mi] = r*64 + ((acb ^ ((r>>1)&3))*16);
        }
        int br = warp_n + (lane & 7) + ((lane >> 4) & 1) * 8;
        int bcb = (lane >> 3) & 1;
        #pragma unroll
        for (int p = 0; p < 2; p++) {
            int r = br + p*16;
            baddr[p] = r*64 + ((bcb ^ ((r>>1)&3))*16);
        }
    }

    float acc[4][4][4];
    #pragma unroll
    for (int i = 0; i < 4; i++)
        #pragma unroll
        for (int j = 0; j < 4; j++)
            #pragma unroll
            for (int r = 0; r < 4; r++) acc[i][j][r] = 0.f;

    const int nk = Ksub / 64;

    auto stage_load = [&](int it) {
        uint32_t sA = sbase + (it % 3)*HSTG;
        uint32_t sB = sA + 16384;
        int k0 = koff + it*64;
        #pragma unroll
        for (int kh = 0; kh < 2; kh++) {
            int kk = k0 + kh*32;
            #pragma unroll
            for (int j = 0; j < 2; j++) {
                int row = lrow + j*64;
                int gm = m0 + row;
                if (rev) gm = (gm & ~(SEQ-1)) | ((SEQ-1) - (gm & (SEQ-1)));
                uint32_t d = sA + kh*8192 + row*64 + ((lkc ^ ((row>>1)&3))*16);
                cp16(d, A + (size_t)gm*lda + kk + lkc*8, 16);
            }
            #pragma unroll
            for (int j = 0; j < 2; j++) {
                int row = lrow + j*64;
                int wr = n0 + row;
                int valid = (wr < N);
                uint32_t d = sB + kh*8192 + row*64 + ((lkc ^ ((row>>1)&3))*16);
                cp16(d, W + (size_t)(valid ? wr : 0)*ldw + kk + lkc*8, valid ? 16 : 0);
            }
        }
        cp_commit();
    };

    stage_load(0);
    if (nk > 1) stage_load(1); else cp_commit();

    for (int it = 0; it < nk; it++) {
        cp_wait1();
        __syncthreads();
        if (it + 2 < nk) stage_load(it + 2); else cp_commit();

        uint32_t sb = sbase + (it % 3)*HSTG;
        #pragma unroll
        for (int ks4 = 0; ks4 < 4; ks4++) {
            const uint32_t sub = (uint32_t)(ks4 >> 1) * 8192;
            const uint32_t kx  = (uint32_t)(ks4 & 1) * 32;
            uint32_t af[4][4];
            #pragma unroll
            for (int mi = 0; mi < 4; mi++)
                LDSM4(af[mi][0], af[mi][1], af[mi][2], af[mi][3],
                      sb + sub + (aaddr[mi] ^ kx));
            uint32_t bf[4][2];
            #pragma unroll
            for (int p = 0; p < 2; p++)
                LDSM4(bf[2*p][0], bf[2*p][1], bf[2*p+1][0], bf[2*p+1][1],
                      sb + 16384 + sub + (baddr[p] ^ kx));
            #pragma unroll
            for (int mi = 0; mi < 4; mi++)
                #pragma unroll
                for (int ni = 0; ni < 4; ni++) {
                    asm volatile(
                        "mma.sync.aligned.m16n8k16.row.col.f32.f16.f16.f32 "
                        "{%0,%1,%2,%3}, {%4,%5,%6,%7}, {%8,%9}, {%0,%1,%2,%3};"
                        : "+f"(acc[mi][ni][0]), "+f"(acc[mi][ni][1]),
                          "+f"(acc[mi][ni][2]), "+f"(acc[mi][ni][3])
                        : "r"(af[mi][0]), "r"(af[mi][1]),
                          "r"(af[mi][2]), "r"(af[mi][3]),
                          "r"(bf[ni][0]), "r"(bf[ni][1]));
                }
        }
        __syncthreads();
    }

    #pragma unroll
    for (int mi = 0; mi < 4; mi++) {
        #pragma unroll
        for (int ni = 0; ni < 4; ni++) {
            int row = m0 + warp_m + mi*16 + (lane>>2);
            int col = n0 + warp_n + ni*8 + 2*(lane&3);
            #pragma unroll
            for (int half = 0; half < 2; half++) {
                int r = row + half*8;
                float v0 = acc[mi][ni][half*2+0];
                float v1 = acc[mi][ni][half*2+1];
                if (EPI == 1) {
                    v0 += bias[col];   v1 += bias[col+1];
                    v0 = (v0 > 20.f) ? v0 : log1pf(__expf(v0));
                    v1 = (v1 > 20.f) ? v1 : log1pf(__expf(v1));
                } else if (EPI == 2) {
                    v0 = 1.f / (1.f + __expf(-v0));
                    v1 = 1.f / (1.f + __expf(-v1));
                }
                if (col + 1 < N)
                    *(float2*)(C + (size_t)r*Ntot + col) = make_float2(v0, v1);
            }
        }
    }
}

// ---------------- split-K reduce for x_proj ---------------------------------
__global__ void reduce_dbc_kernel() {
    int idx = blockIdx.x * blockDim.x + threadIdx.x;
    const int TOT = NROWS*DBCN;
    if (idx >= 2*TOT) return;
    int dir = idx / TOT;
    int e = idx - dir*TOT;
    float s = 0.f;
    #pragma unroll
    for (int p = 0; p < NSPLIT; p++) s += g_dbcp[dir][p][e];
    g_dbc[dir][e] = s;
    g_dbch[dir][e] = __float2half(s);
}

// ---------------- causal depthwise conv (k=4) + SiLU, row pairs (R10) -------
__global__ void conv_silu_kernel(const float* __restrict__ w0, const float* __restrict__ w1,
                                 const float* __restrict__ cb0, const float* __restrict__ cb1) {
    int dir = blockIdx.z;
    const float* w  = dir ? w1 : w0;
    const float* cb = dir ? cb1 : cb0;
    int idx = blockIdx.x * blockDim.x + threadIdx.x;
    const int NC4 = DINNER/4;
    const int NPAIR = NROWS/2;
    if (idx >= NPAIR * NC4) return;
    int c4 = idx % NC4;
    int pr = idx / NC4;
    int row0 = pr * 2;
    int l0 = row0 & (SEQ-1);
    const float* base = g_xz[dir] + (size_t)row0*XZN + c4*4;
    float4 xp1 = *(const float4*)(base + XZN);
    float4 x0  = *(const float4*)(base);
    float4 xm1 = (l0>=1) ? *(const float4*)(base - 1*XZN) : make_float4(0,0,0,0);
    float4 xm2 = (l0>=2) ? *(const float4*)(base - 2*XZN) : make_float4(0,0,0,0);
    float4 xm3 = (l0>=3) ? *(const float4*)(base - 3*XZN) : make_float4(0,0,0,0);
    float4 cbv = ((const float4*)cb)[c4];

    float o0[4], o1[4];
    const float* cbp = (const float*)&cbv;
    const float* pxp1 = (const float*)&xp1;
    const float* px0  = (const float*)&x0;
    const float* pxm1 = (const float*)&xm1;
    const float* pxm2 = (const float*)&xm2;
    const float* pxm3 = (const float*)&xm3;
    #pragma unroll
    for (int c = 0; c < 4; c++) {
        float4 wv = ((const float4*)w)[c4*4+c];
        float a = cbp[c];
        a = fmaf(wv.x, pxm3[c], a);
        a = fmaf(wv.y, pxm2[c], a);
        a = fmaf(wv.z, pxm1[c], a);
        a = fmaf(wv.w, px0[c], a);
        o0[c] = a / (1.f + __expf(-a));
        float b = cbp[c];
        b = fmaf(wv.x, pxm2[c], b);
        b = fmaf(wv.y, pxm1[c], b);
        b = fmaf(wv.z, px0[c], b);
        b = fmaf(wv.w, pxp1[c], b);
        o1[c] = b / (1.f + __expf(-b));
    }
    float* f0 = g_xi[dir] + (size_t)row0*DINNER + c4*4;
    *(float4*)(f0)          = make_float4(o0[0], o0[1], o0[2], o0[3]);
    *(float4*)(f0 + DINNER) = make_float4(o1[0], o1[1], o1[2], o1[3]);
    __half* h0 = g_xih[dir] + (size_t)row0*DINNER + c4*4;
    *(__half2*)(h0)            = __floats2half2_rn(o0[0], o0[1]);
    *(__half2*)(h0+2)          = __floats2half2_rn(o0[2], o0[3]);
    *(__half2*)(h0+DINNER)     = __floats2half2_rn(o1[0], o1[1]);
    *(__half2*)(h0+DINNER+2)   = __floats2half2_rn(o1[2], o1[3]);
}

// ---------------- chunked scan: pass A (local states + sum-dt) --------------
__global__ __launch_bounds__(64)
void scan_local_kernel() {
    int dir = blockIdx.z >> 1;
    int b   = blockIdx.z & 1;
    int c   = blockIdx.y;
    int d   = blockIdx.x * 64 + threadIdx.x;
    int lane = threadIdx.x & 31;
    int row0 = c * CHLEN;

    const float* dtp = g_dt[dir]  + ((size_t)(b*SEQ + row0))*DINNER + d;
    const float* xip = g_xi[dir]  + ((size_t)(b*SEQ + row0))*DINNER + d;
    const float* vp  = g_dbc[dir] + ((size_t)(b*SEQ + row0))*DBCN + 64 + lane;

    float h[DSTATE];
    #pragma unroll
    for (int s = 0; s < DSTATE; s++) h[s] = 0.f;
    float Av[DSTATE];
    #pragma unroll
    for (int s = 0; s < DSTATE; s++) Av[s] = g_A[dir][d*DSTATE + s];
    int fast = g_fastA[dir];
    float sdt = 0.f;

    #pragma unroll 1
    for (int l0 = 0; l0 < CHLEN; l0 += 4) {
        float cdt[4], cxi[4], cv[4];
        #pragma unroll
        for (int u = 0; u < 4; u++) {
            int r = l0 + u;
            cdt[u] = dtp[(size_t)r*DINNER];
            cxi[u] = xip[(size_t)r*DINNER];
            cv[u]  = vp [(size_t)r*DBCN];
        }
        #pragma unroll
        for (int u = 0; u < 4; u++) {
            float dt = cdt[u], xi = cxi[u], v = cv[u];
            float dtxi = dt * xi;
            sdt += dt;
            if (fast) {
                float e = __expf(-dt);
                float p = 1.f;
                #pragma unroll
                for (int s = 0; s < DSTATE; s++) {
                    p *= e;
                    float bs = __shfl_sync(0xffffffffu, v, s);
                    h[s] = fmaf(p, h[s], dtxi * bs);
                }
            } else {
                #pragma unroll
                for (int s = 0; s < DSTATE; s++) {
                    float a = __expf(dt * Av[s]);
                    float bs = __shfl_sync(0xffffffffu, v, s);
                    h[s] = fmaf(a, h[s], dtxi * bs);
                }
            }
        }
    }
    #pragma unroll
    for (int s = 0; s < DSTATE; s++) g_hloc[dir][b][c][s][d] = h[s];
    g_sdt[dir][b][c][d] = sdt;
}

// ---------------- chunked scan: combine (sequential over 8 chunks) ----------
__global__ void scan_combine_kernel() {
    int idx = blockIdx.x * blockDim.x + threadIdx.x;
    if (idx >= 2*BATCH*DINNER) return;
    int dir = idx / (BATCH*DINNER);
    int rem = idx - dir*(BATCH*DINNER);
    int b = rem / DINNER;
    int d = rem - b*DINNER;
    int fast = g_fastA[dir];
    float Av[DSTATE];
    #pragma unroll
    for (int s = 0; s < DSTATE; s++) Av[s] = g_A[dir][d*DSTATE + s];
    float h[DSTATE];
    #pragma unroll
    for (int s = 0; s < DSTATE; s++) h[s] = 0.f;
    #pragma unroll
    for (int c = 0; c < NCHUNK; c++) {
        #pragma unroll
        for (int s = 0; s < DSTATE; s++) g_hini[dir][b][c][s][d] = h[s];
        float S = g_sdt[dir][b][c][d];
        if (fast) {
            float E = __expf(-S);
            float p = 1.f;
            #pragma unroll
            for (int s = 0; s < DSTATE; s++) {
                p *= E;
                h[s] = fmaf(p, h[s], g_hloc[dir][b][c][s][d]);
            }
        } else {
            #pragma unroll
            for (int s = 0; s < DSTATE; s++) {
                float a = __expf(Av[s] * S);
                h[s] = fmaf(a, h[s], g_hloc[dir][b][c][s][d]);
            }
        }
    }
}

// ---------------- chunked scan: pass C (final, writes y) --------------------
__global__ __launch_bounds__(64)
void scan_final_kernel(const float* __restrict__ D0, const float* __restrict__ D1) {
    int dir = blockIdx.z >> 1;
    int b   = blockIdx.z & 1;
    int c   = blockIdx.y;
    int d   = blockIdx.x * 64 + threadIdx.x;
    int lane = threadIdx.x & 31;
    int row0 = c * CHLEN;
    const float* Dp = dir ? D1 : D0;

    const float* dtp = g_dt[dir]  + ((size_t)(b*SEQ + row0))*DINNER + d;
    const float* xip = g_xi[dir]  + ((size_t)(b*SEQ + row0))*DINNER + d;
    const float* zp  = g_xz[dir]  + ((size_t)(b*SEQ + row0))*XZN + DINNER + d;
    const float* vp  = g_dbc[dir] + ((size_t)(b*SEQ + row0))*DBCN + 64 + lane;
    __half* yp       = g_yh[dir]  + ((size_t)(b*SEQ + row0))*DINNER + d;

    float h[DSTATE];
    #pragma unroll
    for (int s = 0; s < DSTATE; s++) h[s] = g_hini[dir][b][c][s][d];
    float Av[DSTATE];
    #pragma unroll
    for (int s = 0; s < DSTATE; s++) Av[s] = g_A[dir][d*DSTATE + s];
    float Dv = Dp[d];
    int fast = g_fastA[dir];

    #pragma unroll 1
    for (int l0 = 0; l0 < CHLEN; l0 += 4) {
        float cdt[4], cxi[4], cz[4], cv[4];
        #pragma unroll
        for (int u = 0; u < 4; u++) {
            int r = l0 + u;
            cdt[u] = dtp[(size_t)r*DINNER];
            cxi[u] = xip[(size_t)r*DINNER];
            cz[u]  = zp [(size_t)r*XZN];
            cv[u]  = vp [(size_t)r*DBCN];
        }
        #pragma unroll
        for (int u = 0; u < 4; u++) {
            float dt = cdt[u], xi = cxi[u], z = cz[u], v = cv[u];
            float dtxi = dt * xi;
            float acc = 0.f;
            if (fast) {
                float e = __expf(-dt);
                float p = 1.f;
                #pragma unroll
                for (int s = 0; s < DSTATE; s++) {
                    p *= e;
                    float bs = __shfl_sync(0xffffffffu, v, s);
                    float cs = __shfl_sync(0xffffffffu, v, 16 + s);
                    h[s] = fmaf(p, h[s], dtxi * bs);
                    acc = fmaf(h[s], cs, acc);
                }
            } else {
                #pragma unroll
                for (int s = 0; s < DSTATE; s++) {
                    float a = __expf(dt * Av[s]);
                    float bs = __shfl_sync(0xffffffffu, v, s);
                    float cs = __shfl_sync(0xffffffffu, v, 16 + s);
                    h[s] = fmaf(a, h[s], dtxi * bs);
                    acc = fmaf(h[s], cs, acc);
                }
            }
            float sz = z / (1.f + __expf(-z));
            yp[(size_t)(l0+u)*DINNER] = __float2half((acc + xi * Dv) * sz);
        }
    }
}

// ---------------- combine dirs + LayerNorm + residual (float4) --------------
__global__ __launch_bounds__(256)
void combine_ln_kernel(const float* __restrict__ x,
                       const float* __restrict__ lng, const float* __restrict__ lnb,
                       float* __restrict__ out) {
    int row = blockIdx.x;
    int b = row / SEQ, l = row % SEQ;
    const float* f  = g_outd[0] + (size_t)row*DMODEL;
    const float* bk = g_outd[1] + (size_t)(b*SEQ + (SEQ-1-l))*DMODEL;
    int tid = threadIdx.x;

    float4 fv = *(const float4*)(f + tid*4);
    float4 bv = *(const float4*)(bk + tid*4);
    float4 dv = make_float4(0.5f*(fv.x+bv.x), 0.5f*(fv.y+bv.y),
                            0.5f*(fv.z+bv.z), 0.5f*(fv.w+bv.w));
    float s  = dv.x + dv.y + dv.z + dv.w;
    float s2 = dv.x*dv.x + dv.y*dv.y + dv.z*dv.z + dv.w*dv.w;
    #pragma unroll
    for (int o = 16; o; o >>= 1) {
        s  += __shfl_xor_sync(0xffffffffu, s,  o);
        s2 += __shfl_xor_sync(0xffffffffu, s2, o);
    }
    __shared__ float sh[2][8];
    if ((tid & 31) == 0) { sh[0][tid>>5] = s; sh[1][tid>>5] = s2; }
    __syncthreads();
    if (tid < 32) {
        float a  = (tid < 8) ? sh[0][tid] : 0.f;
        float a2 = (tid < 8) ? sh[1][tid] : 0.f;
        #pragma unroll
        for (int o = 4; o; o >>= 1) {
            a  += __shfl_xor_sync(0xffffffffu, a,  o);
            a2 += __shfl_xor_sync(0xffffffffu, a2, o);
        }
        if (tid == 0) { sh[0][0] = a; sh[1][0] = a2; }
    }
    __syncthreads();
    float mu  = sh[0][0] * (1.f/DMODEL);
    float var = sh[1][0] * (1.f/DMODEL) - mu*mu;
    float rstd = rsqrtf(var + 1e-5f);
    float4 gv = *(const float4*)(lng + tid*4);
    float4 bb = *(const float4*)(lnb + tid*4);
    float4 xv = *(const float4*)(x + (size_t)row*DMODEL + tid*4);
    float4 ov;
    ov.x = (dv.x - mu)*rstd*gv.x + bb.x + xv.x;
    ov.y = (dv.y - mu)*rstd*gv.y + bb.y + xv.y;
    ov.z = (dv.z - mu)*rstd*gv.z + bb.z + xv.z;
    ov.w = (dv.w - mu)*rstd*gv.w + bb.w + xv.w;
    *(float4*)(out + (size_t)row*DMODEL + tid*4) = ov;
}

// ---------------- host launcher --------------------------------------------
extern "C" void kernel_launch(void* const* d_in, const int* in_sizes, int n_in,
                              void* d_out, int out_size) {
    (void)in_sizes; (void)n_in; (void)out_size;
    const float* x       = (const float*)d_in[0];
    const float* Win[2]  = {(const float*)d_in[1],  (const float*)d_in[10]};
    const float* cw[2]   = {(const float*)d_in[2],  (const float*)d_in[11]};
    const float* cbv[2]  = {(const float*)d_in[3],  (const float*)d_in[12]};
    const float* xproj[2]= {(const float*)d_in[4],  (const float*)d_in[13]};
    const float* dtw[2]  = {(const float*)d_in[5],  (const float*)d_in[14]};
    const float* dtb[2]  = {(const float*)d_in[6],  (const float*)d_in[15]};
    const float* Alog[2] = {(const float*)d_in[7],  (const float*)d_in[16]};
    const float* Dp[2]   = {(const float*)d_in[8],  (const float*)d_in[17]};
    const float* Wout[2] = {(const float*)d_in[9],  (const float*)d_in[18]};
    const float* lng = (const float*)d_in[19];
    const float* lnb = (const float*)d_in[20];
    float* out = (float*)d_out;

    float *p_xz, *p_xi, *p_dbc, *p_dbcp, *p_dt, *p_out;
    cudaGetSymbolAddress((void**)&p_xz,   g_xz);
    cudaGetSymbolAddress((void**)&p_xi,   g_xi);
    cudaGetSymbolAddress((void**)&p_dbc,  g_dbc);
    cudaGetSymbolAddress((void**)&p_dbcp, g_dbcp);
    cudaGetSymbolAddress((void**)&p_dt,   g_dt);
    cudaGetSymbolAddress((void**)&p_out,  g_outd);
    __half *p_xh, *p_winh, *p_xih, *p_xprojh, *p_dbch, *p_dtwh, *p_yh, *p_wouth;
    cudaGetSymbolAddress((void**)&p_xh,     g_xh);
    cudaGetSymbolAddress((void**)&p_winh,   g_winh);
    cudaGetSymbolAddress((void**)&p_xih,    g_xih);
    cudaGetSymbolAddress((void**)&p_xprojh, g_xprojh);
    cudaGetSymbolAddress((void**)&p_dbch,   g_dbch);
    cudaGetSymbolAddress((void**)&p_dtwh,   g_dtwh);
    cudaGetSymbolAddress((void**)&p_yh,     g_yh);
    cudaGetSymbolAddress((void**)&p_wouth,  g_wouth);

    const size_t sXZ  = (size_t)NROWS*XZN;
    const size_t sIN  = (size_t)NROWS*DINNER;
    const size_t sDBC = (size_t)NROWS*DBCN;
    const size_t sMD  = (size_t)NROWS*DMODEL;
    const int SMEM = 3*HSTG;   // 98304

    cudaFuncSetAttribute(hgemm<0>, cudaFuncAttributeMaxDynamicSharedMemorySize, SMEM);
    cudaFuncSetAttribute(hgemm<1>, cudaFuncAttributeMaxDynamicSharedMemorySize, SMEM);
    cudaFuncSetAttribute(hgemm<2>, cudaFuncAttributeMaxDynamicSharedMemorySize, SMEM);

    prepA_kernel<<<2, 256>>>(Alog[0], Alog[1]);

    // one fused conversion launch (x + all weights)
    {
        CvtSegs cs;
        const float* srcs[9] = {x, Win[0], Win[1], xproj[0], xproj[1],
                                dtw[0], dtw[1], Wout[0], Wout[1]};
        __half* dsts[9] = {p_xh, p_winh, p_winh + (size_t)XZN*DMODEL,
                           p_xprojh, p_xprojh + (size_t)DBCN*DINNER,
                           p_dtwh, p_dtwh + (size_t)DINNER*64,
                           p_wouth, p_wouth + (size_t)DMODEL*DINNER};
        int cnts[9] = {NROWS*DMODEL, XZN*DMODEL, XZN*DMODEL,
                       DBCN*DINNER, DBCN*DINNER, DINNER*64, DINNER*64,
                       DMODEL*DINNER, DMODEL*DINNER};
        int off = 0;
        for (int i = 0; i < 9; i++) { cs.s[i]=srcs[i]; cs.d[i]=dsts[i]; cs.off[i]=off; off+=cnts[i]; }
        cs.off[9] = off;
        f2h_multi_kernel<<<(off/4 + 255)/256, 256>>>(cs);
    }

    // in_proj: xz = x @ Win^T (N=4096, K=1024), fp32 out; dir-1 rows reversed
    hgemm<0><<<dim3(XZN/128, NROWS/128, 2), 256, SMEM>>>(
        p_xh, p_xh, p_winh, p_winh + (size_t)XZN*DMODEL, nullptr, nullptr,
        p_xz, p_xz + sXZ, XZN, XZN, DMODEL, DMODEL, DMODEL, 1, 0, 1);

    conv_silu_kernel<<<dim3(((NROWS/2)*(DINNER/4) + 255)/256, 1, 2), 256>>>(
        cw[0], cw[1], cbv[0], cbv[1]);

    // x_proj split-K (N=96, K=256/split), fp32 partials
    hgemm<0><<<dim3(1, NROWS/128, 2*NSPLIT), 256, SMEM>>>(
        p_xih, p_xih + sIN, p_xprojh, p_xprojh + (size_t)DBCN*DINNER,
        nullptr, nullptr,
        p_dbcp, p_dbcp + NSPLIT*sDBC, DBCN, DBCN, DINNER/NSPLIT, DINNER, DINNER,
        NSPLIT, sDBC, 0);
    reduce_dbc_kernel<<<(2*NROWS*DBCN + 255)/256, 256>>>();

    // dt = softplus(dbc[:, :64] @ dtw^T + dtb) (N=2048, K=64), fp32 out
    hgemm<1><<<dim3(DINNER/128, NROWS/128, 2), 256, SMEM>>>(
        p_dbch, p_dbch + sDBC, p_dtwh, p_dtwh + (size_t)DINNER*64, dtb[0], dtb[1],
        p_dt, p_dt + sIN, DINNER, DINNER, 64, DBCN, 64, 1, 0, 0);

    // chunked scan: local -> combine -> final
    scan_local_kernel<<<dim3(DINNER/64, NCHUNK, 2*BATCH), 64>>>();
    scan_combine_kernel<<<(2*BATCH*DINNER + 255)/256, 256>>>();
    scan_final_kernel<<<dim3(DINNER/64, NCHUNK, 2*BATCH), 64>>>(Dp[0], Dp[1]);

    // out = sigmoid(y @ Wout^T) (N=1024, K=2048), fp32 out
    hgemm<2><<<dim3(DMODEL/128, NROWS/128, 2), 256, SMEM>>>(
        p_yh, p_yh + sIN, p_wouth, p_wouth + (size_t)DMODEL*DINNER,
        nullptr, nullptr,
        p_out, p_out + sMD, DMODEL, DMODEL, DINNER, DINNER, DINNER, 1, 0, 0);

    combine_ln_kernel<<<NROWS, 256>>>(x, lng, lnb, out);
}

// round 13
// speedup vs baseline: 2.4941x; 1.0002x over previous
#include <cuda_runtime.h>
#include <cuda_fp16.h>
#include <math.h>
#include <stdint.h>

#define BATCH  2
#define SEQ    1024
#define DMODEL 1024
#define DINNER 2048
#define DSTATE 16
#define NROWS  (BATCH*SEQ)      // 2048
#define DBCN   96
#define XZN    (2*DINNER)       // 4096
#define NSPLIT 8
#define NCHUNK 8
#define CHLEN  (SEQ/NCHUNK)     // 128

// ---------------- scratch (fp32) -------------------------------------------
__device__ float g_xz  [2][(size_t)NROWS*XZN];
__device__ float g_dbc [2][(size_t)NROWS*DBCN];
__device__ float g_dbcp[2][NSPLIT][(size_t)NROWS*DBCN];
__device__ float g_dt  [2][(size_t)NROWS*DINNER];
__device__ float g_outd[2][(size_t)NROWS*DMODEL];
__device__ float g_A   [2][DINNER*DSTATE];
__device__ int   g_fastA[2];
// chunked-scan state
__device__ float g_hloc[2][BATCH][NCHUNK][DSTATE][DINNER];
__device__ float g_sdt [2][BATCH][NCHUNK][DINNER];

// ---------------- scratch (fp16 GEMM operands) ------------------------------
__device__ __half g_xh    [(size_t)NROWS*DMODEL];
__device__ __half g_winh  [2][(size_t)XZN*DMODEL];
__device__ __half g_xih   [2][(size_t)NROWS*DINNER];
__device__ __half g_xprojh[2][(size_t)DBCN*DINNER];
__device__ __half g_dbch  [2][(size_t)NROWS*DBCN];
__device__ __half g_dtwh  [2][(size_t)DINNER*64];
__device__ __half g_yh    [2][(size_t)NROWS*DINNER];
__device__ __half g_wouth [2][(size_t)DMODEL*DINNER];

// ---------------- helpers ---------------------------------------------------
__device__ __forceinline__ uint32_t smem_u32(const void* p) {
    uint32_t a;
    asm("{ .reg .u64 t; cvta.to.shared.u64 t, %1; cvt.u32.u64 %0, t; }"
        : "=r"(a) : "l"(p));
    return a;
}
__device__ __forceinline__ void cp16(uint32_t dst, const void* src, int sz) {
    asm volatile("cp.async.cg.shared.global [%0], [%1], 16, %2;"
                 :: "r"(dst), "l"(src), "r"(sz) : "memory");
}
__device__ __forceinline__ void cp_commit() {
    asm volatile("cp.async.commit_group;" ::: "memory");
}
__device__ __forceinline__ void cp_wait1() {
    asm volatile("cp.async.wait_group 1;" ::: "memory");
}
#define LDSM4(r0,r1,r2,r3,a) \
    asm volatile("ldmatrix.sync.aligned.m8n8.x4.shared.b16 {%0,%1,%2,%3}, [%4];" \
                 : "=r"(r0),"=r"(r1),"=r"(r2),"=r"(r3) : "r"(a))

// ---------------- fused fp32->fp16 conversion (9 segments, 1 launch) --------
struct CvtSegs {
    const float* s[9];
    __half*      d[9];
    int          off[10];
};
__global__ void f2h_multi_kernel(CvtSegs segs) {
    int i4 = (blockIdx.x*blockDim.x + threadIdx.x) * 4;
    if (i4 >= segs.off[9]) return;
    int j = 0;
    #pragma unroll
    for (int k = 1; k < 9; k++) j += (i4 >= segs.off[k]);
    int local = i4 - segs.off[j];
    float4 v = *(const float4*)(segs.s[j] + local);
    __half* dst = segs.d[j] + local;
    *(__half2*)(dst)   = __floats2half2_rn(v.x, v.y);
    *(__half2*)(dst+2) = __floats2half2_rn(v.z, v.w);
}

__global__ void prepA_kernel(const float* __restrict__ Alog0,
                             const float* __restrict__ Alog1) {
    int dir = blockIdx.x;
    const float* Alog = dir ? Alog1 : Alog0;
    __shared__ int ok;
    if (threadIdx.x == 0) ok = 1;
    __syncthreads();
    bool good = true;
    for (int i = threadIdx.x; i < DINNER*DSTATE; i += blockDim.x) {
        float a = -__expf(Alog[i]);
        g_A[dir][i] = a;
        int s = i & (DSTATE-1);
        if (fabsf(a + (float)(s+1)) > 1e-3f * (float)(s+1)) good = false;
    }
    if (!good) atomicExch(&ok, 0);
    __syncthreads();
    if (threadIdx.x == 0) g_fastA[dir] = ok;
}

// ==============  FP16 mma.sync GEMM (m16n8k16) — frozen R10 =================
#define HSTG 32768

template<int EPI>
__global__ __launch_bounds__(256, 2)
void hgemm(const __half* __restrict__ A0, const __half* __restrict__ A1,
           const __half* __restrict__ W0, const __half* __restrict__ W1,
           const float* __restrict__ b0, const float* __restrict__ b1,
           float* __restrict__ C0, float* __restrict__ C1,
           int N, int Ntot, int Ksub, int lda, int ldw,
           int nsplit, size_t csplit, int revA) {
    const int dir   = blockIdx.z / nsplit;
    const int split = blockIdx.z - dir*nsplit;
    const __half* A = dir ? A1 : A0;
    const __half* W = dir ? W1 : W0;
    const float* bias = dir ? b1 : b0;
    float* C = (dir ? C1 : C0) + (size_t)split * csplit;
    const int koff = split * Ksub;
    const int rev  = revA && dir;

    extern __shared__ __align__(16) char sm[];
    const uint32_t sbase = smem_u32(sm);

    const int tid  = threadIdx.x;
    const int lane = tid & 31;
    const int wid  = tid >> 5;
    const int warp_m = (wid & 1) * 64;
    const int warp_n = (wid >> 1) * 32;
    const int m0 = blockIdx.y * 128;
    const int n0 = blockIdx.x * 128;

    const int lrow = tid >> 2;
    const int lkc  = tid & 3;

    uint32_t aaddr[4], baddr[2];
    {
        int ar = warp_m + (lane & 7) + ((lane >> 3) & 1) * 8;
        int acb = (lane >> 4) & 1;
        #pragma unroll
        for (int mi = 0; mi < 4; mi++) {
            int r = ar + mi*16;
            aaddr[mi] = r*64 + ((acb ^ ((r>>1)&3))*16);
        }
        int br = warp_n + (lane & 7) + ((lane >> 4) & 1) * 8;
        int bcb = (lane >> 3) & 1;
        #pragma unroll
        for (int p = 0; p < 2; p++) {
            int r = br + p*16;
            baddr[p] = r*64 + ((bcb ^ ((r>>1)&3))*16);
        }
    }

    float acc[4][4][4];
    #pragma unroll
    for (int i = 0; i < 4; i++)
        #pragma unroll
        for (int j = 0; j < 4; j++)
            #pragma unroll
            for (int r = 0; r < 4; r++) acc[i][j][r] = 0.f;

    const int nk = Ksub / 64;

    auto stage_load = [&](int it) {
        uint32_t sA = sbase + (it % 3)*HSTG;
        uint32_t sB = sA + 16384;
        int k0 = koff + it*64;
        #pragma unroll
        for (int kh = 0; kh < 2; kh++) {
            int kk = k0 + kh*32;
            #pragma unroll
            for (int j = 0; j < 2; j++) {
                int row = lrow + j*64;
                int gm = m0 + row;
                if (rev) gm = (gm & ~(SEQ-1)) | ((SEQ-1) - (gm & (SEQ-1)));
                uint32_t d = sA + kh*8192 + row*64 + ((lkc ^ ((row>>1)&3))*16);
                cp16(d, A + (size_t)gm*lda + kk + lkc*8, 16);
            }
            #pragma unroll
            for (int j = 0; j < 2; j++) {
                int row = lrow + j*64;
                int wr = n0 + row;
                int valid = (wr < N);
                uint32_t d = sB + kh*8192 + row*64 + ((lkc ^ ((row>>1)&3))*16);
                cp16(d, W + (size_t)(valid ? wr : 0)*ldw + kk + lkc*8, valid ? 16 : 0);
            }
        }
        cp_commit();
    };

    stage_load(0);
    if (nk > 1) stage_load(1); else cp_commit();

    for (int it = 0; it < nk; it++) {
        cp_wait1();
        __syncthreads();
        if (it + 2 < nk) stage_load(it + 2); else cp_commit();

        uint32_t sb = sbase + (it % 3)*HSTG;
        #pragma unroll
        for (int ks4 = 0; ks4 < 4; ks4++) {
            const uint32_t sub = (uint32_t)(ks4 >> 1) * 8192;
            const uint32_t kx  = (uint32_t)(ks4 & 1) * 32;
            uint32_t af[4][4];
            #pragma unroll
            for (int mi = 0; mi < 4; mi++)
                LDSM4(af[mi][0], af[mi][1], af[mi][2], af[mi][3],
                      sb + sub + (aaddr[mi] ^ kx));
            uint32_t bf[4][2];
            #pragma unroll
            for (int p = 0; p < 2; p++)
                LDSM4(bf[2*p][0], bf[2*p][1], bf[2*p+1][0], bf[2*p+1][1],
                      sb + 16384 + sub + (baddr[p] ^ kx));
            #pragma unroll
            for (int mi = 0; mi < 4; mi++)
                #pragma unroll
                for (int ni = 0; ni < 4; ni++) {
                    asm volatile(
                        "mma.sync.aligned.m16n8k16.row.col.f32.f16.f16.f32 "
                        "{%0,%1,%2,%3}, {%4,%5,%6,%7}, {%8,%9}, {%0,%1,%2,%3};"
                        : "+f"(acc[mi][ni][0]), "+f"(acc[mi][ni][1]),
                          "+f"(acc[mi][ni][2]), "+f"(acc[mi][ni][3])
                        : "r"(af[mi][0]), "r"(af[mi][1]),
                          "r"(af[mi][2]), "r"(af[mi][3]),
                          "r"(bf[ni][0]), "r"(bf[ni][1]));
                }
        }
        __syncthreads();
    }

    #pragma unroll
    for (int mi = 0; mi < 4; mi++) {
        #pragma unroll
        for (int ni = 0; ni < 4; ni++) {
            int row = m0 + warp_m + mi*16 + (lane>>2);
            int col = n0 + warp_n + ni*8 + 2*(lane&3);
            #pragma unroll
            for (int half = 0; half < 2; half++) {
                int r = row + half*8;
                float v0 = acc[mi][ni][half*2+0];
                float v1 = acc[mi][ni][half*2+1];
                if (EPI == 1) {
                    v0 += bias[col];   v1 += bias[col+1];
                    v0 = (v0 > 20.f) ? v0 : log1pf(__expf(v0));
                    v1 = (v1 > 20.f) ? v1 : log1pf(__expf(v1));
                } else if (EPI == 2) {
                    v0 = 1.f / (1.f + __expf(-v0));
                    v1 = 1.f / (1.f + __expf(-v1));
                }
                if (col + 1 < N)
                    *(float2*)(C + (size_t)r*Ntot + col) = make_float2(v0, v1);
            }
        }
    }
}

// ---------------- split-K reduce for x_proj ---------------------------------
__global__ void reduce_dbc_kernel() {
    int idx = blockIdx.x * blockDim.x + threadIdx.x;
    const int TOT = NROWS*DBCN;
    if (idx >= 2*TOT) return;
    int dir = idx / TOT;
    int e = idx - dir*TOT;
    float s = 0.f;
    #pragma unroll
    for (int p = 0; p < NSPLIT; p++) s += g_dbcp[dir][p][e];
    g_dbc[dir][e] = s;
    g_dbch[dir][e] = __float2half(s);
}

// ---------------- causal depthwise conv (k=4) + SiLU -> fp16 only -----------
__global__ void conv_silu_kernel(const float* __restrict__ w0, const float* __restrict__ w1,
                                 const float* __restrict__ cb0, const float* __restrict__ cb1) {
    int dir = blockIdx.z;
    const float* w  = dir ? w1 : w0;
    const float* cb = dir ? cb1 : cb0;
    int idx = blockIdx.x * blockDim.x + threadIdx.x;
    const int NC4 = DINNER/4;
    const int NPAIR = NROWS/2;
    if (idx >= NPAIR * NC4) return;
    int c4 = idx % NC4;
    int pr = idx / NC4;
    int row0 = pr * 2;
    int l0 = row0 & (SEQ-1);
    const float* base = g_xz[dir] + (size_t)row0*XZN + c4*4;
    float4 xp1 = *(const float4*)(base + XZN);
    float4 x0  = *(const float4*)(base);
    float4 xm1 = (l0>=1) ? *(const float4*)(base - 1*XZN) : make_float4(0,0,0,0);
    float4 xm2 = (l0>=2) ? *(const float4*)(base - 2*XZN) : make_float4(0,0,0,0);
    float4 xm3 = (l0>=3) ? *(const float4*)(base - 3*XZN) : make_float4(0,0,0,0);
    float4 cbv = ((const float4*)cb)[c4];

    float o0[4], o1[4];
    const float* cbp = (const float*)&cbv;
    const float* pxp1 = (const float*)&xp1;
    const float* px0  = (const float*)&x0;
    const float* pxm1 = (const float*)&xm1;
    const float* pxm2 = (const float*)&xm2;
    const float* pxm3 = (const float*)&xm3;
    #pragma unroll
    for (int c = 0; c < 4; c++) {
        float4 wv = ((const float4*)w)[c4*4+c];
        float a = cbp[c];
        a = fmaf(wv.x, pxm3[c], a);
        a = fmaf(wv.y, pxm2[c], a);
        a = fmaf(wv.z, pxm1[c], a);
        a = fmaf(wv.w, px0[c], a);
        o0[c] = a / (1.f + __expf(-a));
        float b = cbp[c];
        b = fmaf(wv.x, pxm2[c], b);
        b = fmaf(wv.y, pxm1[c], b);
        b = fmaf(wv.z, px0[c], b);
        b = fmaf(wv.w, pxp1[c], b);
        o1[c] = b / (1.f + __expf(-b));
    }
    __half* h0 = g_xih[dir] + (size_t)row0*DINNER + c4*4;
    *(__half2*)(h0)            = __floats2half2_rn(o0[0], o0[1]);
    *(__half2*)(h0+2)          = __floats2half2_rn(o0[2], o0[3]);
    *(__half2*)(h0+DINNER)     = __floats2half2_rn(o1[0], o1[1]);
    *(__half2*)(h0+DINNER+2)   = __floats2half2_rn(o1[2], o1[3]);
}

// ---------------- chunked scan: pass A (local states + sum-dt) --------------
// conv+silu recomputed inline from xz (bit-identical fma order to conv kernel)
__global__ __launch_bounds__(64)
void scan_local_kernel(const float* __restrict__ cw0, const float* __restrict__ cw1,
                       const float* __restrict__ cb0, const float* __restrict__ cb1) {
    int dir = blockIdx.z >> 1;
    int b   = blockIdx.z & 1;
    int c   = blockIdx.y;                 // 0..NCHUNK-2
    int d   = blockIdx.x * 64 + threadIdx.x;
    int lane = threadIdx.x & 31;
    int row0 = c * CHLEN;

    const float* dtp = g_dt[dir]  + ((size_t)(b*SEQ + row0))*DINNER + d;
    const float* xzp = g_xz[dir]  + ((size_t)(b*SEQ + row0))*XZN + d;    // x part
    const float* vp  = g_dbc[dir] + ((size_t)(b*SEQ + row0))*DBCN + 64 + lane;
    const float* cw  = dir ? cw1 : cw0;
    const float* cb  = dir ? cb1 : cb0;

    float4 wv = ((const float4*)cw)[d];
    float cbv = cb[d];
    float x1 = 0.f, x2 = 0.f, x3 = 0.f;
    if (c > 0) {
        x1 = xzp[-(ptrdiff_t)XZN];
        x2 = xzp[-(ptrdiff_t)(2*XZN)];
        x3 = xzp[-(ptrdiff_t)(3*XZN)];
    }

    float h[DSTATE];
    #pragma unroll
    for (int s = 0; s < DSTATE; s++) h[s] = 0.f;
    float Av[DSTATE];
    #pragma unroll
    for (int s = 0; s < DSTATE; s++) Av[s] = g_A[dir][d*DSTATE + s];
    int fast = g_fastA[dir];
    float sdt = 0.f;

    #pragma unroll 1
    for (int l0 = 0; l0 < CHLEN; l0 += 4) {
        float cdt[4], cx[4], cv[4];
        #pragma unroll
        for (int u = 0; u < 4; u++) {
            int r = l0 + u;
            cdt[u] = dtp[(size_t)r*DINNER];
            cx[u]  = xzp[(size_t)r*XZN];
            cv[u]  = vp [(size_t)r*DBCN];
        }
        #pragma unroll
        for (int u = 0; u < 4; u++) {
            float dt = cdt[u], xc = cx[u], v = cv[u];
            // conv + silu (identical order to conv kernel)
            float a = cbv;
            a = fmaf(wv.x, x3, a);
            a = fmaf(wv.y, x2, a);
            a = fmaf(wv.z, x1, a);
            a = fmaf(wv.w, xc, a);
            float xi = a / (1.f + __expf(-a));
            x3 = x2; x2 = x1; x1 = xc;

            float dtxi = dt * xi;
            sdt += dt;
            if (fast) {
                float e = __expf(-dt);
                float p = 1.f;
                #pragma unroll
                for (int s = 0; s < DSTATE; s++) {
                    p *= e;
                    float bs = __shfl_sync(0xffffffffu, v, s);
                    h[s] = fmaf(p, h[s], dtxi * bs);
                }
            } else {
                #pragma unroll
                for (int s = 0; s < DSTATE; s++) {
                    float aa = __expf(dt * Av[s]);
                    float bs = __shfl_sync(0xffffffffu, v, s);
                    h[s] = fmaf(aa, h[s], dtxi * bs);
                }
            }
        }
    }
    #pragma unroll
    for (int s = 0; s < DSTATE; s++) g_hloc[dir][b][c][s][d] = h[s];
    g_sdt[dir][b][c][d] = sdt;
}

// ---------------- chunked scan: pass C (inline combine + conv, writes y) ----
__global__ __launch_bounds__(64)
void scan_final_kernel(const float* __restrict__ cw0, const float* __restrict__ cw1,
                       const float* __restrict__ cb0, const float* __restrict__ cb1,
                       const float* __restrict__ D0, const float* __restrict__ D1) {
    int dir = blockIdx.z >> 1;
    int b   = blockIdx.z & 1;
    int c   = blockIdx.y;
    int d   = blockIdx.x * 64 + threadIdx.x;
    int lane = threadIdx.x & 31;
    int row0 = c * CHLEN;
    const float* Dp = dir ? D1 : D0;

    const float* dtp = g_dt[dir]  + ((size_t)(b*SEQ + row0))*DINNER + d;
    const float* xzp = g_xz[dir]  + ((size_t)(b*SEQ + row0))*XZN + d;    // x part
    const float* zp  = g_xz[dir]  + ((size_t)(b*SEQ + row0))*XZN + DINNER + d;
    const float* vp  = g_dbc[dir] + ((size_t)(b*SEQ + row0))*DBCN + 64 + lane;
    __half* yp       = g_yh[dir]  + ((size_t)(b*SEQ + row0))*DINNER + d;
    const float* cw  = dir ? cw1 : cw0;
    const float* cb  = dir ? cb1 : cb0;

    float Av[DSTATE];
    #pragma unroll
    for (int s = 0; s < DSTATE; s++) Av[s] = g_A[dir][d*DSTATE + s];
    int fast = g_fastA[dir];

    // inline combine: h_init = fold of chunks 0..c-1 (same order as before)
    float h[DSTATE];
    #pragma unroll
    for (int s = 0; s < DSTATE; s++) h[s] = 0.f;
    for (int cc = 0; cc < c; cc++) {
        float S = g_sdt[dir][b][cc][d];
        if (fast) {
            float E = __expf(-S);
            float p = 1.f;
            #pragma unroll
            for (int s = 0; s < DSTATE; s++) {
                p *= E;
                h[s] = fmaf(p, h[s], g_hloc[dir][b][cc][s][d]);
            }
        } else {
            #pragma unroll
            for (int s = 0; s < DSTATE; s++) {
                float aa = __expf(Av[s] * S);
                h[s] = fmaf(aa, h[s], g_hloc[dir][b][cc][s][d]);
            }
        }
    }

    float4 wv = ((const float4*)cw)[d];
    float cbv = cb[d];
    float x1 = 0.f, x2 = 0.f, x3 = 0.f;
    if (c > 0) {
        x1 = xzp[-(ptrdiff_t)XZN];
        x2 = xzp[-(ptrdiff_t)(2*XZN)];
        x3 = xzp[-(ptrdiff_t)(3*XZN)];
    }
    float Dv = Dp[d];

    #pragma unroll 1
    for (int l0 = 0; l0 < CHLEN; l0 += 4) {
        float cdt[4], cx[4], cz[4], cv[4];
        #pragma unroll
        for (int u = 0; u < 4; u++) {
            int r = l0 + u;
            cdt[u] = dtp[(size_t)r*DINNER];
            cx[u]  = xzp[(size_t)r*XZN];
            cz[u]  = zp [(size_t)r*XZN];
            cv[u]  = vp [(size_t)r*DBCN];
        }
        #pragma unroll
        for (int u = 0; u < 4; u++) {
            float dt = cdt[u], xc = cx[u], z = cz[u], v = cv[u];
            float a = cbv;
            a = fmaf(wv.x, x3, a);
            a = fmaf(wv.y, x2, a);
            a = fmaf(wv.z, x1, a);
            a = fmaf(wv.w, xc, a);
            float xi = a / (1.f + __expf(-a));
            x3 = x2; x2 = x1; x1 = xc;

            float dtxi = dt * xi;
            float acc = 0.f;
            if (fast) {
                float e = __expf(-dt);
                float p = 1.f;
                #pragma unroll
                for (int s = 0; s < DSTATE; s++) {
                    p *= e;
                    float bs = __shfl_sync(0xffffffffu, v, s);
                    float cs = __shfl_sync(0xffffffffu, v, 16 + s);
                    h[s] = fmaf(p, h[s], dtxi * bs);
                    acc = fmaf(h[s], cs, acc);
                }
            } else {
                #pragma unroll
                for (int s = 0; s < DSTATE; s++) {
                    float aa = __expf(dt * Av[s]);
                    float bs = __shfl_sync(0xffffffffu, v, s);
                    float cs = __shfl_sync(0xffffffffu, v, 16 + s);
                    h[s] = fmaf(aa, h[s], dtxi * bs);
                    acc = fmaf(h[s], cs, acc);
                }
            }
            float sz = z / (1.f + __expf(-z));
            yp[(size_t)(l0+u)*DINNER] = __float2half((acc + xi * Dv) * sz);
        }
    }
}

// ---------------- combine dirs + LayerNorm + residual (float4) --------------
__global__ __launch_bounds__(256)
void combine_ln_kernel(const float* __restrict__ x,
                       const float* __restrict__ lng, const float* __restrict__ lnb,
                       float* __restrict__ out) {
    int row = blockIdx.x;
    int b = row / SEQ, l = row % SEQ;
    const float* f  = g_outd[0] + (size_t)row*DMODEL;
    const float* bk = g_outd[1] + (size_t)(b*SEQ + (SEQ-1-l))*DMODEL;
    int tid = threadIdx.x;

    float4 fv = *(const float4*)(f + tid*4);
    float4 bv = *(const float4*)(bk + tid*4);
    float4 dv = make_float4(0.5f*(fv.x+bv.x), 0.5f*(fv.y+bv.y),
                            0.5f*(fv.z+bv.z), 0.5f*(fv.w+bv.w));
    float s  = dv.x + dv.y + dv.z + dv.w;
    float s2 = dv.x*dv.x + dv.y*dv.y + dv.z*dv.z + dv.w*dv.w;
    #pragma unroll
    for (int o = 16; o; o >>= 1) {
        s  += __shfl_xor_sync(0xffffffffu, s,  o);
        s2 += __shfl_xor_sync(0xffffffffu, s2, o);
    }
    __shared__ float sh[2][8];
    if ((tid & 31) == 0) { sh[0][tid>>5] = s; sh[1][tid>>5] = s2; }
    __syncthreads();
    if (tid < 32) {
        float a  = (tid < 8) ? sh[0][tid] : 0.f;
        float a2 = (tid < 8) ? sh[1][tid] : 0.f;
        #pragma unroll
        for (int o = 4; o; o >>= 1) {
            a  += __shfl_xor_sync(0xffffffffu, a,  o);
            a2 += __shfl_xor_sync(0xffffffffu, a2, o);
        }
        if (tid == 0) { sh[0][0] = a; sh[1][0] = a2; }
    }
    __syncthreads();
    float mu  = sh[0][0] * (1.f/DMODEL);
    float var = sh[1][0] * (1.f/DMODEL) - mu*mu;
    float rstd = rsqrtf(var + 1e-5f);
    float4 gv = *(const float4*)(lng + tid*4);
    float4 bb = *(const float4*)(lnb + tid*4);
    float4 xv = *(const float4*)(x + (size_t)row*DMODEL + tid*4);
    float4 ov;
    ov.x = (dv.x - mu)*rstd*gv.x + bb.x + xv.x;
    ov.y = (dv.y - mu)*rstd*gv.y + bb.y + xv.y;
    ov.z = (dv.z - mu)*rstd*gv.z + bb.z + xv.z;
    ov.w = (dv.w - mu)*rstd*gv.w + bb.w + xv.w;
    *(float4*)(out + (size_t)row*DMODEL + tid*4) = ov;
}

// ---------------- host launcher --------------------------------------------
extern "C" void kernel_launch(void* const* d_in, const int* in_sizes, int n_in,
                              void* d_out, int out_size) {
    (void)in_sizes; (void)n_in; (void)out_size;
    const float* x       = (const float*)d_in[0];
    const float* Win[2]  = {(const float*)d_in[1],  (const float*)d_in[10]};
    const float* cw[2]   = {(const float*)d_in[2],  (const float*)d_in[11]};
    const float* cbv[2]  = {(const float*)d_in[3],  (const float*)d_in[12]};
    const float* xproj[2]= {(const float*)d_in[4],  (const float*)d_in[13]};
    const float* dtw[2]  = {(const float*)d_in[5],  (const float*)d_in[14]};
    const float* dtb[2]  = {(const float*)d_in[6],  (const float*)d_in[15]};
    const float* Alog[2] = {(const float*)d_in[7],  (const float*)d_in[16]};
    const float* Dp[2]   = {(const float*)d_in[8],  (const float*)d_in[17]};
    const float* Wout[2] = {(const float*)d_in[9],  (const float*)d_in[18]};
    const float* lng = (const float*)d_in[19];
    const float* lnb = (const float*)d_in[20];
    float* out = (float*)d_out;

    float *p_xz, *p_dbc, *p_dbcp, *p_dt, *p_out;
    cudaGetSymbolAddress((void**)&p_xz,   g_xz);
    cudaGetSymbolAddress((void**)&p_dbc,  g_dbc);
    cudaGetSymbolAddress((void**)&p_dbcp, g_dbcp);
    cudaGetSymbolAddress((void**)&p_dt,   g_dt);
    cudaGetSymbolAddress((void**)&p_out,  g_outd);
    __half *p_xh, *p_winh, *p_xih, *p_xprojh, *p_dbch, *p_dtwh, *p_yh, *p_wouth;
    cudaGetSymbolAddress((void**)&p_xh,     g_xh);
    cudaGetSymbolAddress((void**)&p_winh,   g_winh);
    cudaGetSymbolAddress((void**)&p_xih,    g_xih);
    cudaGetSymbolAddress((void**)&p_xprojh, g_xprojh);
    cudaGetSymbolAddress((void**)&p_dbch,   g_dbch);
    cudaGetSymbolAddress((void**)&p_dtwh,   g_dtwh);
    cudaGetSymbolAddress((void**)&p_yh,     g_yh);
    cudaGetSymbolAddress((void**)&p_wouth,  g_wouth);

    const size_t sXZ  = (size_t)NROWS*XZN;
    const size_t sIN  = (size_t)NROWS*DINNER;
    const size_t sDBC = (size_t)NROWS*DBCN;
    const size_t sMD  = (size_t)NROWS*DMODEL;
    const int SMEM = 3*HSTG;   // 98304

    cudaFuncSetAttribute(hgemm<0>, cudaFuncAttributeMaxDynamicSharedMemorySize, SMEM);
    cudaFuncSetAttribute(hgemm<1>, cudaFuncAttributeMaxDynamicSharedMemorySize, SMEM);
    cudaFuncSetAttribute(hgemm<2>, cudaFuncAttributeMaxDynamicSharedMemorySize, SMEM);

    prepA_kernel<<<2, 256>>>(Alog[0], Alog[1]);

    // one fused conversion launch (x + all weights)
    {
        CvtSegs cs;
        const float* srcs[9] = {x, Win[0], Win[1], xproj[0], xproj[1],
                                dtw[0], dtw[1], Wout[0], Wout[1]};
        __half* dsts[9] = {p_xh, p_winh, p_winh + (size_t)XZN*DMODEL,
                           p_xprojh, p_xprojh + (size_t)DBCN*DINNER,
                           p_dtwh, p_dtwh + (size_t)DINNER*64,
                           p_wouth, p_wouth + (size_t)DMODEL*DINNER};
        int cnts[9] = {NROWS*DMODEL, XZN*DMODEL, XZN*DMODEL,
                       DBCN*DINNER, DBCN*DINNER, DINNER*64, DINNER*64,
                       DMODEL*DINNER, DMODEL*DINNER};
        int off = 0;
        for (int i = 0; i < 9; i++) { cs.s[i]=srcs[i]; cs.d[i]=dsts[i]; cs.off[i]=off; off+=cnts[i]; }
        cs.off[9] = off;
        f2h_multi_kernel<<<(off/4 + 255)/256, 256>>>(cs);
    }

    // in_proj: xz = x @ Win^T (N=4096, K=1024), fp32 out; dir-1 rows reversed
    hgemm<0><<<dim3(XZN/128, NROWS/128, 2), 256, SMEM>>>(
        p_xh, p_xh, p_winh, p_winh + (size_t)XZN*DMODEL, nullptr, nullptr,
        p_xz, p_xz + sXZ, XZN, XZN, DMODEL, DMODEL, DMODEL, 1, 0, 1);

    conv_silu_kernel<<<dim3(((NROWS/2)*(DINNER/4) + 255)/256, 1, 2), 256>>>(
        cw[0], cw[1], cbv[0], cbv[1]);

    // x_proj split-K (N=96, K=256/split), fp32 partials
    hgemm<0><<<dim3(1, NROWS/128, 2*NSPLIT), 256, SMEM>>>(
        p_xih, p_xih + sIN, p_xprojh, p_xprojh + (size_t)DBCN*DINNER,
        nullptr, nullptr,
        p_dbcp, p_dbcp + NSPLIT*sDBC, DBCN, DBCN, DINNER/NSPLIT, DINNER, DINNER,
        NSPLIT, sDBC, 0);
    reduce_dbc_kernel<<<(2*NROWS*DBCN + 255)/256, 256>>>();

    // dt = softplus(dbc[:, :64] @ dtw^T + dtb) (N=2048, K=64), fp32 out
    hgemm<1><<<dim3(DINNER/128, NROWS/128, 2), 256, SMEM>>>(
        p_dbch, p_dbch + sDBC, p_dtwh, p_dtwh + (size_t)DINNER*64, dtb[0], dtb[1],
        p_dt, p_dt + sIN, DINNER, DINNER, 64, DBCN, 64, 1, 0, 0);

    // chunked scan: local (chunks 0..6) -> final (inline combine + conv)
    scan_local_kernel<<<dim3(DINNER/64, NCHUNK-1, 2*BATCH), 64>>>(
        cw[0], cw[1], cbv[0], cbv[1]);
    scan_final_kernel<<<dim3(DINNER/64, NCHUNK, 2*BATCH), 64>>>(
        cw[0], cw[1], cbv[0], cbv[1], Dp[0], Dp[1]);

    // out = sigmoid(y @ Wout^T) (N=1024, K=2048), fp32 out
    hgemm<2><<<dim3(DMODEL/128, NROWS/128, 2), 256, SMEM>>>(
        p_yh, p_yh + sIN, p_wouth, p_wouth + (size_t)DMODEL*DINNER,
        nullptr, nullptr,
        p_out, p_out + sMD, DMODEL, DMODEL, DINNER, DINNER, DINNER, 1, 0, 0);

    combine_ln_kernel<<<NROWS, 256>>>(x, lng, lnb, out);
}

// round 14
// speedup vs baseline: 2.5082x; 1.0056x over previous
#include <cuda_runtime.h>
#include <cuda_fp16.h>
#include <math.h>
#include <stdint.h>

#define BATCH  2
#define SEQ    1024
#define DMODEL 1024
#define DINNER 2048
#define DSTATE 16
#define NROWS  (BATCH*SEQ)      // 2048
#define DBCN   96
#define XZN    (2*DINNER)       // 4096
#define NSPLIT 8
#define NCHUNK 8
#define CHLEN  (SEQ/NCHUNK)     // 128

// ---------------- scratch (fp32) -------------------------------------------
__device__ float g_xz  [2][(size_t)NROWS*XZN];
__device__ float g_dbc [2][(size_t)NROWS*DBCN];
__device__ float g_dbcp[2][NSPLIT][(size_t)NROWS*DBCN];
__device__ float g_dt  [2][(size_t)NROWS*DINNER];
__device__ float g_outd[2][(size_t)NROWS*DMODEL];
__device__ float g_A   [2][DINNER*DSTATE];
__device__ int   g_fastA[2];
// chunked-scan state
__device__ float g_hloc[2][BATCH][NCHUNK][DSTATE][DINNER];
__device__ float g_sdt [2][BATCH][NCHUNK][DINNER];

// ---------------- scratch (fp16 GEMM operands) ------------------------------
__device__ __half g_xh    [(size_t)NROWS*DMODEL];
__device__ __half g_winh  [2][(size_t)XZN*DMODEL];
__device__ __half g_xih   [2][(size_t)NROWS*DINNER];
__device__ __half g_xprojh[2][(size_t)DBCN*DINNER];
__device__ __half g_dbch  [2][(size_t)NROWS*DBCN];
__device__ __half g_dtwh  [2][(size_t)DINNER*64];
__device__ __half g_yh    [2][(size_t)NROWS*DINNER];
__device__ __half g_wouth [2][(size_t)DMODEL*DINNER];

// ---------------- helpers ---------------------------------------------------
__device__ __forceinline__ uint32_t smem_u32(const void* p) {
    uint32_t a;
    asm("{ .reg .u64 t; cvta.to.shared.u64 t, %1; cvt.u32.u64 %0, t; }"
        : "=r"(a) : "l"(p));
    return a;
}
__device__ __forceinline__ void cp16(uint32_t dst, const void* src, int sz) {
    asm volatile("cp.async.cg.shared.global [%0], [%1], 16, %2;"
                 :: "r"(dst), "l"(src), "r"(sz) : "memory");
}
__device__ __forceinline__ void cp_commit() {
    asm volatile("cp.async.commit_group;" ::: "memory");
}
__device__ __forceinline__ void cp_wait1() {
    asm volatile("cp.async.wait_group 1;" ::: "memory");
}
#define LDSM4(r0,r1,r2,r3,a) \
    asm volatile("ldmatrix.sync.aligned.m8n8.x4.shared.b16 {%0,%1,%2,%3}, [%4];" \
                 : "=r"(r0),"=r"(r1),"=r"(r2),"=r"(r3) : "r"(a))

// ---------------- fused fp32->fp16 conversion (9 segments, 1 launch) --------
struct CvtSegs {
    const float* s[9];
    __half*      d[9];
    int          off[10];
};
__global__ void f2h_multi_kernel(CvtSegs segs) {
    int i4 = (blockIdx.x*blockDim.x + threadIdx.x) * 4;
    if (i4 >= segs.off[9]) return;
    int j = 0;
    #pragma unroll
    for (int k = 1; k < 9; k++) j += (i4 >= segs.off[k]);
    int local = i4 - segs.off[j];
    float4 v = *(const float4*)(segs.s[j] + local);
    __half* dst = segs.d[j] + local;
    *(__half2*)(dst)   = __floats2half2_rn(v.x, v.y);
    *(__half2*)(dst+2) = __floats2half2_rn(v.z, v.w);
}

__global__ void prepA_kernel(const float* __restrict__ Alog0,
                             const float* __restrict__ Alog1) {
    int dir = blockIdx.x;
    const float* Alog = dir ? Alog1 : Alog0;
    __shared__ int ok;
    if (threadIdx.x == 0) ok = 1;
    __syncthreads();
    bool good = true;
    for (int i = threadIdx.x; i < DINNER*DSTATE; i += blockDim.x) {
        float a = -__expf(Alog[i]);
        g_A[dir][i] = a;
        int s = i & (DSTATE-1);
        if (fabsf(a + (float)(s+1)) > 1e-3f * (float)(s+1)) good = false;
    }
    if (!good) atomicExch(&ok, 0);
    __syncthreads();
    if (threadIdx.x == 0) g_fastA[dir] = ok;
}

// ==============  FP16 mma.sync GEMM (m16n8k16) — frozen R10 =================
#define HSTG 32768

template<int EPI>
__global__ __launch_bounds__(256, 2)
void hgemm(const __half* __restrict__ A0, const __half* __restrict__ A1,
           const __half* __restrict__ W0, const __half* __restrict__ W1,
           const float* __restrict__ b0, const float* __restrict__ b1,
           float* __restrict__ C0, float* __restrict__ C1,
           int N, int Ntot, int Ksub, int lda, int ldw,
           int nsplit, size_t csplit, int revA) {
    const int dir   = blockIdx.z / nsplit;
    const int split = blockIdx.z - dir*nsplit;
    const __half* A = dir ? A1 : A0;
    const __half* W = dir ? W1 : W0;
    const float* bias = dir ? b1 : b0;
    float* C = (dir ? C1 : C0) + (size_t)split * csplit;
    const int koff = split * Ksub;
    const int rev  = revA && dir;

    extern __shared__ __align__(16) char sm[];
    const uint32_t sbase = smem_u32(sm);

    const int tid  = threadIdx.x;
    const int lane = tid & 31;
    const int wid  = tid >> 5;
    const int warp_m = (wid & 1) * 64;
    const int warp_n = (wid >> 1) * 32;
    const int m0 = blockIdx.y * 128;
    const int n0 = blockIdx.x * 128;

    const int lrow = tid >> 2;
    const int lkc  = tid & 3;

    uint32_t aaddr[4], baddr[2];
    {
        int ar = warp_m + (lane & 7) + ((lane >> 3) & 1) * 8;
        int acb = (lane >> 4) & 1;
        #pragma unroll
        for (int mi = 0; mi < 4; mi++) {
            int r = ar + mi*16;
            aaddr[mi] = r*64 + ((acb ^ ((r>>1)&3))*16);
        }
        int br = warp_n + (lane & 7) + ((lane >> 4) & 1) * 8;
        int bcb = (lane >> 3) & 1;
        #pragma unroll
        for (int p = 0; p < 2; p++) {
            int r = br + p*16;
            baddr[p] = r*64 + ((bcb ^ ((r>>1)&3))*16);
        }
    }

    float acc[4][4][4];
    #pragma unroll
    for (int i = 0; i < 4; i++)
        #pragma unroll
        for (int j = 0; j < 4; j++)
            #pragma unroll
            for (int r = 0; r < 4; r++) acc[i][j][r] = 0.f;

    const int nk = Ksub / 64;

    auto stage_load = [&](int it) {
        uint32_t sA = sbase + (it % 3)*HSTG;
        uint32_t sB = sA + 16384;
        int k0 = koff + it*64;
        #pragma unroll
        for (int kh = 0; kh < 2; kh++) {
            int kk = k0 + kh*32;
            #pragma unroll
            for (int j = 0; j < 2; j++) {
                int row = lrow + j*64;
                int gm = m0 + row;
                if (rev) gm = (gm & ~(SEQ-1)) | ((SEQ-1) - (gm & (SEQ-1)));
                uint32_t d = sA + kh*8192 + row*64 + ((lkc ^ ((row>>1)&3))*16);
                cp16(d, A + (size_t)gm*lda + kk + lkc*8, 16);
            }
            #pragma unroll
            for (int j = 0; j < 2; j++) {
                int row = lrow + j*64;
                int wr = n0 + row;
                int valid = (wr < N);
                uint32_t d = sB + kh*8192 + row*64 + ((lkc ^ ((row>>1)&3))*16);
                cp16(d, W + (size_t)(valid ? wr : 0)*ldw + kk + lkc*8, valid ? 16 : 0);
            }
        }
        cp_commit();
    };

    stage_load(0);
    if (nk > 1) stage_load(1); else cp_commit();

    for (int it = 0; it < nk; it++) {
        cp_wait1();
        __syncthreads();
        if (it + 2 < nk) stage_load(it + 2); else cp_commit();

        uint32_t sb = sbase + (it % 3)*HSTG;
        #pragma unroll
        for (int ks4 = 0; ks4 < 4; ks4++) {
            const uint32_t sub = (uint32_t)(ks4 >> 1) * 8192;
            const uint32_t kx  = (uint32_t)(ks4 & 1) * 32;
            uint32_t af[4][4];
            #pragma unroll
            for (int mi = 0; mi < 4; mi++)
                LDSM4(af[mi][0], af[mi][1], af[mi][2], af[mi][3],
                      sb + sub + (aaddr[mi] ^ kx));
            uint32_t bf[4][2];
            #pragma unroll
            for (int p = 0; p < 2; p++)
                LDSM4(bf[2*p][0], bf[2*p][1], bf[2*p+1][0], bf[2*p+1][1],
                      sb + 16384 + sub + (baddr[p] ^ kx));
            #pragma unroll
            for (int mi = 0; mi < 4; mi++)
                #pragma unroll
                for (int ni = 0; ni < 4; ni++) {
                    asm volatile(
                        "mma.sync.aligned.m16n8k16.row.col.f32.f16.f16.f32 "
                        "{%0,%1,%2,%3}, {%4,%5,%6,%7}, {%8,%9}, {%0,%1,%2,%3};"
                        : "+f"(acc[mi][ni][0]), "+f"(acc[mi][ni][1]),
                          "+f"(acc[mi][ni][2]), "+f"(acc[mi][ni][3])
                        : "r"(af[mi][0]), "r"(af[mi][1]),
                          "r"(af[mi][2]), "r"(af[mi][3]),
                          "r"(bf[ni][0]), "r"(bf[ni][1]));
                }
        }
        __syncthreads();
    }

    #pragma unroll
    for (int mi = 0; mi < 4; mi++) {
        #pragma unroll
        for (int ni = 0; ni < 4; ni++) {
            int row = m0 + warp_m + mi*16 + (lane>>2);
            int col = n0 + warp_n + ni*8 + 2*(lane&3);
            #pragma unroll
            for (int half = 0; half < 2; half++) {
                int r = row + half*8;
                float v0 = acc[mi][ni][half*2+0];
                float v1 = acc[mi][ni][half*2+1];
                if (EPI == 1) {
                    v0 += bias[col];   v1 += bias[col+1];
                    v0 = (v0 > 20.f) ? v0 : log1pf(__expf(v0));
                    v1 = (v1 > 20.f) ? v1 : log1pf(__expf(v1));
                } else if (EPI == 2) {
                    v0 = 1.f / (1.f + __expf(-v0));
                    v1 = 1.f / (1.f + __expf(-v1));
                }
                if (col + 1 < N)
                    *(float2*)(C + (size_t)r*Ntot + col) = make_float2(v0, v1);
            }
        }
    }
}

// ---------------- split-K reduce for x_proj ---------------------------------
__global__ void reduce_dbc_kernel() {
    int idx = blockIdx.x * blockDim.x + threadIdx.x;
    const int TOT = NROWS*DBCN;
    if (idx >= 2*TOT) return;
    int dir = idx / TOT;
    int e = idx - dir*TOT;
    float s = 0.f;
    #pragma unroll
    for (int p = 0; p < NSPLIT; p++) s += g_dbcp[dir][p][e];
    g_dbc[dir][e] = s;
    g_dbch[dir][e] = __float2half(s);
}

// ---------------- causal depthwise conv (k=4) + SiLU -> fp16 only -----------
__global__ void conv_silu_kernel(const float* __restrict__ w0, const float* __restrict__ w1,
                                 const float* __restrict__ cb0, const float* __restrict__ cb1) {
    int dir = blockIdx.z;
    const float* w  = dir ? w1 : w0;
    const float* cb = dir ? cb1 : cb0;
    int idx = blockIdx.x * blockDim.x + threadIdx.x;
    const int NC4 = DINNER/4;
    const int NPAIR = NROWS/2;
    if (idx >= NPAIR * NC4) return;
    int c4 = idx % NC4;
    int pr = idx / NC4;
    int row0 = pr * 2;
    int l0 = row0 & (SEQ-1);
    const float* base = g_xz[dir] + (size_t)row0*XZN + c4*4;
    float4 xp1 = *(const float4*)(base + XZN);
    float4 x0  = *(const float4*)(base);
    float4 xm1 = (l0>=1) ? *(const float4*)(base - 1*XZN) : make_float4(0,0,0,0);
    float4 xm2 = (l0>=2) ? *(const float4*)(base - 2*XZN) : make_float4(0,0,0,0);
    float4 xm3 = (l0>=3) ? *(const float4*)(base - 3*XZN) : make_float4(0,0,0,0);
    float4 cbv = ((const float4*)cb)[c4];

    float o0[4], o1[4];
    const float* cbp = (const float*)&cbv;
    const float* pxp1 = (const float*)&xp1;
    const float* px0  = (const float*)&x0;
    const float* pxm1 = (const float*)&xm1;
    const float* pxm2 = (const float*)&xm2;
    const float* pxm3 = (const float*)&xm3;
    #pragma unroll
    for (int c = 0; c < 4; c++) {
        float4 wv = ((const float4*)w)[c4*4+c];
        float a = cbp[c];
        a = fmaf(wv.x, pxm3[c], a);
        a = fmaf(wv.y, pxm2[c], a);
        a = fmaf(wv.z, pxm1[c], a);
        a = fmaf(wv.w, px0[c], a);
        o0[c] = a / (1.f + __expf(-a));
        float b = cbp[c];
        b = fmaf(wv.x, pxm2[c], b);
        b = fmaf(wv.y, pxm1[c], b);
        b = fmaf(wv.z, px0[c], b);
        b = fmaf(wv.w, pxp1[c], b);
        o1[c] = b / (1.f + __expf(-b));
    }
    __half* h0 = g_xih[dir] + (size_t)row0*DINNER + c4*4;
    *(__half2*)(h0)            = __floats2half2_rn(o0[0], o0[1]);
    *(__half2*)(h0+2)          = __floats2half2_rn(o0[2], o0[3]);
    *(__half2*)(h0+DINNER)     = __floats2half2_rn(o1[0], o1[1]);
    *(__half2*)(h0+DINNER+2)   = __floats2half2_rn(o1[2], o1[3]);
}

// ---------------- chunked scan: pass A (local states + sum-dt) --------------
// conv+silu inline (bit-identical order); B staged in smem (float4 broadcast)
__global__ __launch_bounds__(128)
void scan_local_kernel(const float* __restrict__ cw0, const float* __restrict__ cw1,
                       const float* __restrict__ cb0, const float* __restrict__ cb1) {
    int dir = blockIdx.z >> 1;
    int b   = blockIdx.z & 1;
    int c   = blockIdx.y;                 // 0..NCHUNK-2
    int d   = blockIdx.x * 128 + threadIdx.x;
    int row0 = c * CHLEN;

    __shared__ float4 sB[CHLEN][4];       // B: 16 floats/row, 8KB
    for (int i = threadIdx.x; i < CHLEN*4; i += 128) {
        int row = i >> 2, q = i & 3;
        sB[row][q] = *(const float4*)(g_dbc[dir] +
                        (size_t)(b*SEQ + row0 + row)*DBCN + 64 + q*4);
    }
    __syncthreads();

    const float* dtp = g_dt[dir]  + ((size_t)(b*SEQ + row0))*DINNER + d;
    const float* xzp = g_xz[dir]  + ((size_t)(b*SEQ + row0))*XZN + d;
    const float* cw  = dir ? cw1 : cw0;
    const float* cb  = dir ? cb1 : cb0;

    float4 wv = ((const float4*)cw)[d];
    float cbv = cb[d];
    float x1 = 0.f, x2 = 0.f, x3 = 0.f;
    if (c > 0) {
        x1 = xzp[-(ptrdiff_t)XZN];
        x2 = xzp[-(ptrdiff_t)(2*XZN)];
        x3 = xzp[-(ptrdiff_t)(3*XZN)];
    }

    float h[DSTATE];
    #pragma unroll
    for (int s = 0; s < DSTATE; s++) h[s] = 0.f;
    float Av[DSTATE];
    #pragma unroll
    for (int s = 0; s < DSTATE; s++) Av[s] = g_A[dir][d*DSTATE + s];
    int fast = g_fastA[dir];
    float sdt = 0.f;

    #pragma unroll 1
    for (int l0 = 0; l0 < CHLEN; l0 += 4) {
        float cdt[4], cx[4];
        #pragma unroll
        for (int u = 0; u < 4; u++) {
            int r = l0 + u;
            cdt[u] = dtp[(size_t)r*DINNER];
            cx[u]  = xzp[(size_t)r*XZN];
        }
        #pragma unroll
        for (int u = 0; u < 4; u++) {
            int r = l0 + u;
            float dt = cdt[u], xc = cx[u];
            float a = cbv;
            a = fmaf(wv.x, x3, a);
            a = fmaf(wv.y, x2, a);
            a = fmaf(wv.z, x1, a);
            a = fmaf(wv.w, xc, a);
            float xi = a / (1.f + __expf(-a));
            x3 = x2; x2 = x1; x1 = xc;

            float4 b0 = sB[r][0], b1 = sB[r][1], b2 = sB[r][2], b3 = sB[r][3];
            float bsv[16] = {b0.x,b0.y,b0.z,b0.w, b1.x,b1.y,b1.z,b1.w,
                             b2.x,b2.y,b2.z,b2.w, b3.x,b3.y,b3.z,b3.w};
            float dtxi = dt * xi;
            sdt += dt;
            if (fast) {
                float e = __expf(-dt);
                float p = 1.f;
                #pragma unroll
                for (int s = 0; s < DSTATE; s++) {
                    p *= e;
                    h[s] = fmaf(p, h[s], dtxi * bsv[s]);
                }
            } else {
                #pragma unroll
                for (int s = 0; s < DSTATE; s++) {
                    float aa = __expf(dt * Av[s]);
                    h[s] = fmaf(aa, h[s], dtxi * bsv[s]);
                }
            }
        }
    }
    #pragma unroll
    for (int s = 0; s < DSTATE; s++) g_hloc[dir][b][c][s][d] = h[s];
    g_sdt[dir][b][c][d] = sdt;
}

// ---------------- chunked scan: pass C (combine + conv inline, writes y) ----
__global__ __launch_bounds__(128)
void scan_final_kernel(const float* __restrict__ cw0, const float* __restrict__ cw1,
                       const float* __restrict__ cb0, const float* __restrict__ cb1,
                       const float* __restrict__ D0, const float* __restrict__ D1) {
    int dir = blockIdx.z >> 1;
    int b   = blockIdx.z & 1;
    int c   = blockIdx.y;
    int d   = blockIdx.x * 128 + threadIdx.x;
    int row0 = c * CHLEN;
    const float* Dp = dir ? D1 : D0;

    __shared__ float4 sBC[CHLEN][8];      // B then C: 32 floats/row, 16KB
    for (int i = threadIdx.x; i < CHLEN*8; i += 128) {
        int row = i >> 3, q = i & 7;
        sBC[row][q] = *(const float4*)(g_dbc[dir] +
                         (size_t)(b*SEQ + row0 + row)*DBCN + 64 + q*4);
    }
    __syncthreads();

    const float* dtp = g_dt[dir]  + ((size_t)(b*SEQ + row0))*DINNER + d;
    const float* xzp = g_xz[dir]  + ((size_t)(b*SEQ + row0))*XZN + d;
    const float* zp  = g_xz[dir]  + ((size_t)(b*SEQ + row0))*XZN + DINNER + d;
    __half* yp       = g_yh[dir]  + ((size_t)(b*SEQ + row0))*DINNER + d;
    const float* cw  = dir ? cw1 : cw0;
    const float* cb  = dir ? cb1 : cb0;

    float Av[DSTATE];
    #pragma unroll
    for (int s = 0; s < DSTATE; s++) Av[s] = g_A[dir][d*DSTATE + s];
    int fast = g_fastA[dir];

    // inline combine: h_init = fold of chunks 0..c-1
    float h[DSTATE];
    #pragma unroll
    for (int s = 0; s < DSTATE; s++) h[s] = 0.f;
    for (int cc = 0; cc < c; cc++) {
        float S = g_sdt[dir][b][cc][d];
        if (fast) {
            float E = __expf(-S);
            float p = 1.f;
            #pragma unroll
            for (int s = 0; s < DSTATE; s++) {
                p *= E;
                h[s] = fmaf(p, h[s], g_hloc[dir][b][cc][s][d]);
            }
        } else {
            #pragma unroll
            for (int s = 0; s < DSTATE; s++) {
                float aa = __expf(Av[s] * S);
                h[s] = fmaf(aa, h[s], g_hloc[dir][b][cc][s][d]);
            }
        }
    }

    float4 wv = ((const float4*)cw)[d];
    float cbv = cb[d];
    float x1 = 0.f, x2 = 0.f, x3 = 0.f;
    if (c > 0) {
        x1 = xzp[-(ptrdiff_t)XZN];
        x2 = xzp[-(ptrdiff_t)(2*XZN)];
        x3 = xzp[-(ptrdiff_t)(3*XZN)];
    }
    float Dv = Dp[d];

    #pragma unroll 1
    for (int l0 = 0; l0 < CHLEN; l0 += 4) {
        float cdt[4], cx[4], cz[4];
        #pragma unroll
        for (int u = 0; u < 4; u++) {
            int r = l0 + u;
            cdt[u] = dtp[(size_t)r*DINNER];
            cx[u]  = xzp[(size_t)r*XZN];
            cz[u]  = zp [(size_t)r*XZN];
        }
        #pragma unroll
        for (int u = 0; u < 4; u++) {
            int r = l0 + u;
            float dt = cdt[u], xc = cx[u], z = cz[u];
            float a = cbv;
            a = fmaf(wv.x, x3, a);
            a = fmaf(wv.y, x2, a);
            a = fmaf(wv.z, x1, a);
            a = fmaf(wv.w, xc, a);
            float xi = a / (1.f + __expf(-a));
            x3 = x2; x2 = x1; x1 = xc;

            float4 b0 = sBC[r][0], b1 = sBC[r][1], b2 = sBC[r][2], b3 = sBC[r][3];
            float4 c0 = sBC[r][4], c1 = sBC[r][5], c2 = sBC[r][6], c3 = sBC[r][7];
            float bsv[16] = {b0.x,b0.y,b0.z,b0.w, b1.x,b1.y,b1.z,b1.w,
                             b2.x,b2.y,b2.z,b2.w, b3.x,b3.y,b3.z,b3.w};
            float csv[16] = {c0.x,c0.y,c0.z,c0.w, c1.x,c1.y,c1.z,c1.w,
                             c2.x,c2.y,c2.z,c2.w, c3.x,c3.y,c3.z,c3.w};

            float dtxi = dt * xi;
            float acc = 0.f;
            if (fast) {
                float e = __expf(-dt);
                float p = 1.f;
                #pragma unroll
                for (int s = 0; s < DSTATE; s++) {
                    p *= e;
                    h[s] = fmaf(p, h[s], dtxi * bsv[s]);
                    acc = fmaf(h[s], csv[s], acc);
                }
            } else {
                #pragma unroll
                for (int s = 0; s < DSTATE; s++) {
                    float aa = __expf(dt * Av[s]);
                    h[s] = fmaf(aa, h[s], dtxi * bsv[s]);
                    acc = fmaf(h[s], csv[s], acc);
                }
            }
            float sz = z / (1.f + __expf(-z));
            yp[(size_t)r*DINNER] = __float2half((acc + xi * Dv) * sz);
        }
    }
}

// ---------------- combine dirs + LayerNorm + residual (float4) --------------
__global__ __launch_bounds__(256)
void combine_ln_kernel(const float* __restrict__ x,
                       const float* __restrict__ lng, const float* __restrict__ lnb,
                       float* __restrict__ out) {
    int row = blockIdx.x;
    int b = row / SEQ, l = row % SEQ;
    const float* f  = g_outd[0] + (size_t)row*DMODEL;
    const float* bk = g_outd[1] + (size_t)(b*SEQ + (SEQ-1-l))*DMODEL;
    int tid = threadIdx.x;

    float4 fv = *(const float4*)(f + tid*4);
    float4 bv = *(const float4*)(bk + tid*4);
    float4 dv = make_float4(0.5f*(fv.x+bv.x), 0.5f*(fv.y+bv.y),
                            0.5f*(fv.z+bv.z), 0.5f*(fv.w+bv.w));
    float s  = dv.x + dv.y + dv.z + dv.w;
    float s2 = dv.x*dv.x + dv.y*dv.y + dv.z*dv.z + dv.w*dv.w;
    #pragma unroll
    for (int o = 16; o; o >>= 1) {
        s  += __shfl_xor_sync(0xffffffffu, s,  o);
        s2 += __shfl_xor_sync(0xffffffffu, s2, o);
    }
    __shared__ float sh[2][8];
    if ((tid & 31) == 0) { sh[0][tid>>5] = s; sh[1][tid>>5] = s2; }
    __syncthreads();
    if (tid < 32) {
        float a  = (tid < 8) ? sh[0][tid] : 0.f;
        float a2 = (tid < 8) ? sh[1][tid] : 0.f;
        #pragma unroll
        for (int o = 4; o; o >>= 1) {
            a  += __shfl_xor_sync(0xffffffffu, a,  o);
            a2 += __shfl_xor_sync(0xffffffffu, a2, o);
        }
        if (tid == 0) { sh[0][0] = a; sh[1][0] = a2; }
    }
    __syncthreads();
    float mu  = sh[0][0] * (1.f/DMODEL);
    float var = sh[1][0] * (1.f/DMODEL) - mu*mu;
    float rstd = rsqrtf(var + 1e-5f);
    float4 gv = *(const float4*)(lng + tid*4);
    float4 bb = *(const float4*)(lnb + tid*4);
    float4 xv = *(const float4*)(x + (size_t)row*DMODEL + tid*4);
    float4 ov;
    ov.x = (dv.x - mu)*rstd*gv.x + bb.x + xv.x;
    ov.y = (dv.y - mu)*rstd*gv.y + bb.y + xv.y;
    ov.z = (dv.z - mu)*rstd*gv.z + bb.z + xv.z;
    ov.w = (dv.w - mu)*rstd*gv.w + bb.w + xv.w;
    *(float4*)(out + (size_t)row*DMODEL + tid*4) = ov;
}

// ---------------- host launcher --------------------------------------------
extern "C" void kernel_launch(void* const* d_in, const int* in_sizes, int n_in,
                              void* d_out, int out_size) {
    (void)in_sizes; (void)n_in; (void)out_size;
    const float* x       = (const float*)d_in[0];
    const float* Win[2]  = {(const float*)d_in[1],  (const float*)d_in[10]};
    const float* cw[2]   = {(const float*)d_in[2],  (const float*)d_in[11]};
    const float* cbv[2]  = {(const float*)d_in[3],  (const float*)d_in[12]};
    const float* xproj[2]= {(const float*)d_in[4],  (const float*)d_in[13]};
    const float* dtw[2]  = {(const float*)d_in[5],  (const float*)d_in[14]};
    const float* dtb[2]  = {(const float*)d_in[6],  (const float*)d_in[15]};
    const float* Alog[2] = {(const float*)d_in[7],  (const float*)d_in[16]};
    const float* Dp[2]   = {(const float*)d_in[8],  (const float*)d_in[17]};
    const float* Wout[2] = {(const float*)d_in[9],  (const float*)d_in[18]};
    const float* lng = (const float*)d_in[19];
    const float* lnb = (const float*)d_in[20];
    float* out = (float*)d_out;

    float *p_xz, *p_dbc, *p_dbcp, *p_dt, *p_out;
    cudaGetSymbolAddress((void**)&p_xz,   g_xz);
    cudaGetSymbolAddress((void**)&p_dbc,  g_dbc);
    cudaGetSymbolAddress((void**)&p_dbcp, g_dbcp);
    cudaGetSymbolAddress((void**)&p_dt,   g_dt);
    cudaGetSymbolAddress((void**)&p_out,  g_outd);
    __half *p_xh, *p_winh, *p_xih, *p_xprojh, *p_dbch, *p_dtwh, *p_yh, *p_wouth;
    cudaGetSymbolAddress((void**)&p_xh,     g_xh);
    cudaGetSymbolAddress((void**)&p_winh,   g_winh);
    cudaGetSymbolAddress((void**)&p_xih,    g_xih);
    cudaGetSymbolAddress((void**)&p_xprojh, g_xprojh);
    cudaGetSymbolAddress((void**)&p_dbch,   g_dbch);
    cudaGetSymbolAddress((void**)&p_dtwh,   g_dtwh);
    cudaGetSymbolAddress((void**)&p_yh,     g_yh);
    cudaGetSymbolAddress((void**)&p_wouth,  g_wouth);

    const size_t sXZ  = (size_t)NROWS*XZN;
    const size_t sIN  = (size_t)NROWS*DINNER;
    const size_t sDBC = (size_t)NROWS*DBCN;
    const size_t sMD  = (size_t)NROWS*DMODEL;
    const int SMEM = 3*HSTG;   // 98304

    cudaFuncSetAttribute(hgemm<0>, cudaFuncAttributeMaxDynamicSharedMemorySize, SMEM);
    cudaFuncSetAttribute(hgemm<1>, cudaFuncAttributeMaxDynamicSharedMemorySize, SMEM);
    cudaFuncSetAttribute(hgemm<2>, cudaFuncAttributeMaxDynamicSharedMemorySize, SMEM);

    prepA_kernel<<<2, 256>>>(Alog[0], Alog[1]);

    // one fused conversion launch (x + all weights)
    {
        CvtSegs cs;
        const float* srcs[9] = {x, Win[0], Win[1], xproj[0], xproj[1],
                                dtw[0], dtw[1], Wout[0], Wout[1]};
        __half* dsts[9] = {p_xh, p_winh, p_winh + (size_t)XZN*DMODEL,
                           p_xprojh, p_xprojh + (size_t)DBCN*DINNER,
                           p_dtwh, p_dtwh + (size_t)DINNER*64,
                           p_wouth, p_wouth + (size_t)DMODEL*DINNER};
        int cnts[9] = {NROWS*DMODEL, XZN*DMODEL, XZN*DMODEL,
                       DBCN*DINNER, DBCN*DINNER, DINNER*64, DINNER*64,
                       DMODEL*DINNER, DMODEL*DINNER};
        int off = 0;
        for (int i = 0; i < 9; i++) { cs.s[i]=srcs[i]; cs.d[i]=dsts[i]; cs.off[i]=off; off+=cnts[i]; }
        cs.off[9] = off;
        f2h_multi_kernel<<<(off/4 + 255)/256, 256>>>(cs);
    }

    // in_proj: xz = x @ Win^T (N=4096, K=1024), fp32 out; dir-1 rows reversed
    hgemm<0><<<dim3(XZN/128, NROWS/128, 2), 256, SMEM>>>(
        p_xh, p_xh, p_winh, p_winh + (size_t)XZN*DMODEL, nullptr, nullptr,
        p_xz, p_xz + sXZ, XZN, XZN, DMODEL, DMODEL, DMODEL, 1, 0, 1);

    conv_silu_kernel<<<dim3(((NROWS/2)*(DINNER/4) + 255)/256, 1, 2), 256>>>(
        cw[0], cw[1], cbv[0], cbv[1]);

    // x_proj split-K (N=96, K=256/split), fp32 partials
    hgemm<0><<<dim3(1, NROWS/128, 2*NSPLIT), 256, SMEM>>>(
        p_xih, p_xih + sIN, p_xprojh, p_xprojh + (size_t)DBCN*DINNER,
        nullptr, nullptr,
        p_dbcp, p_dbcp + NSPLIT*sDBC, DBCN, DBCN, DINNER/NSPLIT, DINNER, DINNER,
        NSPLIT, sDBC, 0);
    reduce_dbc_kernel<<<(2*NROWS*DBCN + 255)/256, 256>>>();

    // dt = softplus(dbc[:, :64] @ dtw^T + dtb) (N=2048, K=64), fp32 out
    hgemm<1><<<dim3(DINNER/128, NROWS/128, 2), 256, SMEM>>>(
        p_dbch, p_dbch + sDBC, p_dtwh, p_dtwh + (size_t)DINNER*64, dtb[0], dtb[1],
        p_dt, p_dt + sIN, DINNER, DINNER, 64, DBCN, 64, 1, 0, 0);

    // chunked scan: local (chunks 0..6) -> final (inline combine + conv)
    scan_local_kernel<<<dim3(DINNER/128, NCHUNK-1, 2*BATCH), 128>>>(
        cw[0], cw[1], cbv[0], cbv[1]);
    scan_final_kernel<<<dim3(DINNER/128, NCHUNK, 2*BATCH), 128>>>(
        cw[0], cw[1], cbv[0], cbv[1], Dp[0], Dp[1]);

    // out = sigmoid(y @ Wout^T) (N=1024, K=2048), fp32 out
    hgemm<2><<<dim3(DMODEL/128, NROWS/128, 2), 256, SMEM>>>(
        p_yh, p_yh + sIN, p_wouth, p_wouth + (size_t)DMODEL*DINNER,
        nullptr, nullptr,
        p_out, p_out + sMD, DMODEL, DMODEL, DINNER, DINNER, DINNER, 1, 0, 0);

    combine_ln_kernel<<<NROWS, 256>>>(x, lng, lnb, out);
}

// round 15
// speedup vs baseline: 2.5396x; 1.0125x over previous
#include <cuda_runtime.h>
#include <cuda_fp16.h>
#include <math.h>
#include <stdint.h>

#define BATCH  2
#define SEQ    1024
#define DMODEL 1024
#define DINNER 2048
#define DSTATE 16
#define NROWS  (BATCH*SEQ)      // 2048
#define DBCN   96
#define XZN    (2*DINNER)       // 4096
#define NSPLIT 8
#define NCHUNK 8
#define CHLEN  (SEQ/NCHUNK)     // 128

// ---------------- scratch (fp32) -------------------------------------------
__device__ float g_xz  [2][(size_t)NROWS*XZN];
__device__ float g_dbc [2][(size_t)NROWS*DBCN];
__device__ float g_dbcp[2][NSPLIT][(size_t)NROWS*DBCN];
__device__ float g_dt  [2][(size_t)NROWS*DINNER];
__device__ float g_outd[2][(size_t)NROWS*DMODEL];
__device__ float g_A   [2][DINNER*DSTATE];
__device__ int   g_fastA[2];
__device__ float g_hloc[2][BATCH][NCHUNK][DSTATE][DINNER];
__device__ float g_sdt [2][BATCH][NCHUNK][DINNER];

// ---------------- scratch (fp16 GEMM operands) ------------------------------
__device__ __half g_xh    [(size_t)NROWS*DMODEL];
__device__ __half g_winh  [2][(size_t)XZN*DMODEL];
__device__ __half g_xih   [2][(size_t)NROWS*DINNER];
__device__ __half g_xprojh[2][(size_t)DBCN*DINNER];
__device__ __half g_dbch  [2][(size_t)NROWS*DBCN];
__device__ __half g_dtwh  [2][(size_t)DINNER*64];
__device__ __half g_yh    [2][(size_t)NROWS*DINNER];
__device__ __half g_wouth [2][(size_t)DMODEL*DINNER];

// ---------------- helpers ---------------------------------------------------
__device__ __forceinline__ uint32_t smem_u32(const void* p) {
    uint32_t a;
    asm("{ .reg .u64 t; cvta.to.shared.u64 t, %1; cvt.u32.u64 %0, t; }"
        : "=r"(a) : "l"(p));
    return a;
}
__device__ __forceinline__ void cp16(uint32_t dst, const void* src, int sz) {
    asm volatile("cp.async.cg.shared.global [%0], [%1], 16, %2;"
                 :: "r"(dst), "l"(src), "r"(sz) : "memory");
}
__device__ __forceinline__ void cp_commit() {
    asm volatile("cp.async.commit_group;" ::: "memory");
}
__device__ __forceinline__ void cp_wait1() {
    asm volatile("cp.async.wait_group 1;" ::: "memory");
}
#define LDSM4(r0,r1,r2,r3,a) \
    asm volatile("ldmatrix.sync.aligned.m8n8.x4.shared.b16 {%0,%1,%2,%3}, [%4];" \
                 : "=r"(r0),"=r"(r1),"=r"(r2),"=r"(r3) : "r"(a))

// ---------------- fused fp32->fp16 conversion (9 segments, 1 launch) --------
struct CvtSegs {
    const float* s[9];
    __half*      d[9];
    int          off[10];
};
__global__ void f2h_multi_kernel(CvtSegs segs) {
    int i4 = (blockIdx.x*blockDim.x + threadIdx.x) * 4;
    if (i4 >= segs.off[9]) return;
    int j = 0;
    #pragma unroll
    for (int k = 1; k < 9; k++) j += (i4 >= segs.off[k]);
    int local = i4 - segs.off[j];
    float4 v = *(const float4*)(segs.s[j] + local);
    __half* dst = segs.d[j] + local;
    *(__half2*)(dst)   = __floats2half2_rn(v.x, v.y);
    *(__half2*)(dst+2) = __floats2half2_rn(v.z, v.w);
}

__global__ void prepA_kernel(const float* __restrict__ Alog0,
                             const float* __restrict__ Alog1) {
    int dir = blockIdx.x;
    const float* Alog = dir ? Alog1 : Alog0;
    __shared__ int ok;
    if (threadIdx.x == 0) ok = 1;
    __syncthreads();
    bool good = true;
    for (int i = threadIdx.x; i < DINNER*DSTATE; i += blockDim.x) {
        float a = -__expf(Alog[i]);
        g_A[dir][i] = a;
        int s = i & (DSTATE-1);
        if (fabsf(a + (float)(s+1)) > 1e-3f * (float)(s+1)) good = false;
    }
    if (!good) atomicExch(&ok, 0);
    __syncthreads();
    if (threadIdx.x == 0) g_fastA[dir] = ok;
}

// ==============  FP16 mma.sync GEMM (m16n8k16) — frozen internals ===========
#define HSTG 32768

template<int EPI>
__global__ __launch_bounds__(256, 2)
void hgemm(const __half* __restrict__ A0, const __half* __restrict__ A1,
           const __half* __restrict__ W0, const __half* __restrict__ W1,
           const float* __restrict__ b0, const float* __restrict__ b1,
           float* __restrict__ C0, float* __restrict__ C1,
           int N, int Ntot, int Ksub, int lda, int ldw,
           size_t csplit, int revA, int dirsel) {
    const int dir   = dirsel;
    const int split = blockIdx.z;
    const __half* A = dir ? A1 : A0;
    const __half* W = dir ? W1 : W0;
    const float* bias = dir ? b1 : b0;
    float* C = (dir ? C1 : C0) + (size_t)split * csplit;
    const int koff = split * Ksub;
    const int rev  = revA && dir;

    extern __shared__ __align__(16) char sm[];
    const uint32_t sbase = smem_u32(sm);

    const int tid  = threadIdx.x;
    const int lane = tid & 31;
    const int wid  = tid >> 5;
    const int warp_m = (wid & 1) * 64;
    const int warp_n = (wid >> 1) * 32;
    const int m0 = blockIdx.y * 128;
    const int n0 = blockIdx.x * 128;

    const int lrow = tid >> 2;
    const int lkc  = tid & 3;

    uint32_t aaddr[4], baddr[2];
    {
        int ar = warp_m + (lane & 7) + ((lane >> 3) & 1) * 8;
        int acb = (lane >> 4) & 1;
        #pragma unroll
        for (int mi = 0; mi < 4; mi++) {
            int r = ar + mi*16;
            aaddr[mi] = r*64 + ((acb ^ ((r>>1)&3))*16);
        }
        int br = warp_n + (lane & 7) + ((lane >> 4) & 1) * 8;
        int bcb = (lane >> 3) & 1;
        #pragma unroll
        for (int p = 0; p < 2; p++) {
            int r = br + p*16;
            baddr[p] = r*64 + ((bcb ^ ((r>>1)&3))*16);
        }
    }

    float acc[4][4][4];
    #pragma unroll
    for (int i = 0; i < 4; i++)
        #pragma unroll
        for (int j = 0; j < 4; j++)
            #pragma unroll
            for (int r = 0; r < 4; r++) acc[i][j][r] = 0.f;

    const int nk = Ksub / 64;

    auto stage_load = [&](int it) {
        uint32_t sA = sbase + (it % 3)*HSTG;
        uint32_t sB = sA + 16384;
        int k0 = koff + it*64;
        #pragma unroll
        for (int kh = 0; kh < 2; kh++) {
            int kk = k0 + kh*32;
            #pragma unroll
            for (int j = 0; j < 2; j++) {
                int row = lrow + j*64;
                int gm = m0 + row;
                if (rev) gm = (gm & ~(SEQ-1)) | ((SEQ-1) - (gm & (SEQ-1)));
                uint32_t d = sA + kh*8192 + row*64 + ((lkc ^ ((row>>1)&3))*16);
                cp16(d, A + (size_t)gm*lda + kk + lkc*8, 16);
            }
            #pragma unroll
            for (int j = 0; j < 2; j++) {
                int row = lrow + j*64;
                int wr = n0 + row;
                int valid = (wr < N);
                uint32_t d = sB + kh*8192 + row*64 + ((lkc ^ ((row>>1)&3))*16);
                cp16(d, W + (size_t)(valid ? wr : 0)*ldw + kk + lkc*8, valid ? 16 : 0);
            }
        }
        cp_commit();
    };

    stage_load(0);
    if (nk > 1) stage_load(1); else cp_commit();

    for (int it = 0; it < nk; it++) {
        cp_wait1();
        __syncthreads();
        if (it + 2 < nk) stage_load(it + 2); else cp_commit();

        uint32_t sb = sbase + (it % 3)*HSTG;
        #pragma unroll
        for (int ks4 = 0; ks4 < 4; ks4++) {
            const uint32_t sub = (uint32_t)(ks4 >> 1) * 8192;
            const uint32_t kx  = (uint32_t)(ks4 & 1) * 32;
            uint32_t af[4][4];
            #pragma unroll
            for (int mi = 0; mi < 4; mi++)
                LDSM4(af[mi][0], af[mi][1], af[mi][2], af[mi][3],
                      sb + sub + (aaddr[mi] ^ kx));
            uint32_t bf[4][2];
            #pragma unroll
            for (int p = 0; p < 2; p++)
                LDSM4(bf[2*p][0], bf[2*p][1], bf[2*p+1][0], bf[2*p+1][1],
                      sb + 16384 + sub + (baddr[p] ^ kx));
            #pragma unroll
            for (int mi = 0; mi < 4; mi++)
                #pragma unroll
                for (int ni = 0; ni < 4; ni++) {
                    asm volatile(
                        "mma.sync.aligned.m16n8k16.row.col.f32.f16.f16.f32 "
                        "{%0,%1,%2,%3}, {%4,%5,%6,%7}, {%8,%9}, {%0,%1,%2,%3};"
                        : "+f"(acc[mi][ni][0]), "+f"(acc[mi][ni][1]),
                          "+f"(acc[mi][ni][2]), "+f"(acc[mi][ni][3])
                        : "r"(af[mi][0]), "r"(af[mi][1]),
                          "r"(af[mi][2]), "r"(af[mi][3]),
                          "r"(bf[ni][0]), "r"(bf[ni][1]));
                }
        }
        __syncthreads();
    }

    #pragma unroll
    for (int mi = 0; mi < 4; mi++) {
        #pragma unroll
        for (int ni = 0; ni < 4; ni++) {
            int row = m0 + warp_m + mi*16 + (lane>>2);
            int col = n0 + warp_n + ni*8 + 2*(lane&3);
            #pragma unroll
            for (int half = 0; half < 2; half++) {
                int r = row + half*8;
                float v0 = acc[mi][ni][half*2+0];
                float v1 = acc[mi][ni][half*2+1];
                if (EPI == 1) {
                    v0 += bias[col];   v1 += bias[col+1];
                    v0 = (v0 > 20.f) ? v0 : log1pf(__expf(v0));
                    v1 = (v1 > 20.f) ? v1 : log1pf(__expf(v1));
                } else if (EPI == 2) {
                    v0 = 1.f / (1.f + __expf(-v0));
                    v1 = 1.f / (1.f + __expf(-v1));
                }
                if (col + 1 < N)
                    *(float2*)(C + (size_t)r*Ntot + col) = make_float2(v0, v1);
            }
        }
    }
}

// ---------------- split-K reduce for x_proj (per-dir) ------------------------
__global__ void reduce_dbc_kernel(int dirsel) {
    int idx = blockIdx.x * blockDim.x + threadIdx.x;
    const int TOT = NROWS*DBCN;
    if (idx >= TOT) return;
    int dir = dirsel;
    float s = 0.f;
    #pragma unroll
    for (int p = 0; p < NSPLIT; p++) s += g_dbcp[dir][p][idx];
    g_dbc[dir][idx] = s;
    g_dbch[dir][idx] = __float2half(s);
}

// ---------------- causal depthwise conv (k=4) + SiLU -> fp16 (per-dir) ------
__global__ void conv_silu_kernel(const float* __restrict__ w0, const float* __restrict__ w1,
                                 const float* __restrict__ cb0, const float* __restrict__ cb1,
                                 int dirsel) {
    int dir = dirsel;
    const float* w  = dir ? w1 : w0;
    const float* cb = dir ? cb1 : cb0;
    int idx = blockIdx.x * blockDim.x + threadIdx.x;
    const int NC4 = DINNER/4;
    const int NPAIR = NROWS/2;
    if (idx >= NPAIR * NC4) return;
    int c4 = idx % NC4;
    int pr = idx / NC4;
    int row0 = pr * 2;
    int l0 = row0 & (SEQ-1);
    const float* base = g_xz[dir] + (size_t)row0*XZN + c4*4;
    float4 xp1 = *(const float4*)(base + XZN);
    float4 x0  = *(const float4*)(base);
    float4 xm1 = (l0>=1) ? *(const float4*)(base - 1*XZN) : make_float4(0,0,0,0);
    float4 xm2 = (l0>=2) ? *(const float4*)(base - 2*XZN) : make_float4(0,0,0,0);
    float4 xm3 = (l0>=3) ? *(const float4*)(base - 3*XZN) : make_float4(0,0,0,0);
    float4 cbv = ((const float4*)cb)[c4];

    float o0[4], o1[4];
    const float* cbp = (const float*)&cbv;
    const float* pxp1 = (const float*)&xp1;
    const float* px0  = (const float*)&x0;
    const float* pxm1 = (const float*)&xm1;
    const float* pxm2 = (const float*)&xm2;
    const float* pxm3 = (const float*)&xm3;
    #pragma unroll
    for (int c = 0; c < 4; c++) {
        float4 wv = ((const float4*)w)[c4*4+c];
        float a = cbp[c];
        a = fmaf(wv.x, pxm3[c], a);
        a = fmaf(wv.y, pxm2[c], a);
        a = fmaf(wv.z, pxm1[c], a);
        a = fmaf(wv.w, px0[c], a);
        o0[c] = a / (1.f + __expf(-a));
        float b = cbp[c];
        b = fmaf(wv.x, pxm2[c], b);
        b = fmaf(wv.y, pxm1[c], b);
        b = fmaf(wv.z, px0[c], b);
        b = fmaf(wv.w, pxp1[c], b);
        o1[c] = b / (1.f + __expf(-b));
    }
    __half* h0 = g_xih[dir] + (size_t)row0*DINNER + c4*4;
    *(__half2*)(h0)            = __floats2half2_rn(o0[0], o0[1]);
    *(__half2*)(h0+2)          = __floats2half2_rn(o0[2], o0[3]);
    *(__half2*)(h0+DINNER)     = __floats2half2_rn(o1[0], o1[1]);
    *(__half2*)(h0+DINNER+2)   = __floats2half2_rn(o1[2], o1[3]);
}

// ---------------- chunked scan: pass A (per-dir) -----------------------------
__global__ __launch_bounds__(128)
void scan_local_kernel(const float* __restrict__ cw0, const float* __restrict__ cw1,
                       const float* __restrict__ cb0, const float* __restrict__ cb1,
                       int dirsel) {
    int dir = dirsel;
    int b   = blockIdx.z;
    int c   = blockIdx.y;                 // 0..NCHUNK-2
    int d   = blockIdx.x * 128 + threadIdx.x;
    int row0 = c * CHLEN;

    __shared__ float4 sB[CHLEN][4];
    for (int i = threadIdx.x; i < CHLEN*4; i += 128) {
        int row = i >> 2, q = i & 3;
        sB[row][q] = *(const float4*)(g_dbc[dir] +
                        (size_t)(b*SEQ + row0 + row)*DBCN + 64 + q*4);
    }
    __syncthreads();

    const float* dtp = g_dt[dir]  + ((size_t)(b*SEQ + row0))*DINNER + d;
    const float* xzp = g_xz[dir]  + ((size_t)(b*SEQ + row0))*XZN + d;
    const float* cw  = dir ? cw1 : cw0;
    const float* cb  = dir ? cb1 : cb0;

    float4 wv = ((const float4*)cw)[d];
    float cbv = cb[d];
    float x1 = 0.f, x2 = 0.f, x3 = 0.f;
    if (c > 0) {
        x1 = xzp[-(ptrdiff_t)XZN];
        x2 = xzp[-(ptrdiff_t)(2*XZN)];
        x3 = xzp[-(ptrdiff_t)(3*XZN)];
    }

    float h[DSTATE];
    #pragma unroll
    for (int s = 0; s < DSTATE; s++) h[s] = 0.f;
    float Av[DSTATE];
    #pragma unroll
    for (int s = 0; s < DSTATE; s++) Av[s] = g_A[dir][d*DSTATE + s];
    int fast = g_fastA[dir];
    float sdt = 0.f;

    #pragma unroll 1
    for (int l0 = 0; l0 < CHLEN; l0 += 4) {
        float cdt[4], cx[4];
        #pragma unroll
        for (int u = 0; u < 4; u++) {
            int r = l0 + u;
            cdt[u] = dtp[(size_t)r*DINNER];
            cx[u]  = xzp[(size_t)r*XZN];
        }
        #pragma unroll
        for (int u = 0; u < 4; u++) {
            int r = l0 + u;
            float dt = cdt[u], xc = cx[u];
            float a = cbv;
            a = fmaf(wv.x, x3, a);
            a = fmaf(wv.y, x2, a);
            a = fmaf(wv.z, x1, a);
            a = fmaf(wv.w, xc, a);
            float xi = a / (1.f + __expf(-a));
            x3 = x2; x2 = x1; x1 = xc;

            float4 b0 = sB[r][0], b1 = sB[r][1], b2 = sB[r][2], b3 = sB[r][3];
            float bsv[16] = {b0.x,b0.y,b0.z,b0.w, b1.x,b1.y,b1.z,b1.w,
                             b2.x,b2.y,b2.z,b2.w, b3.x,b3.y,b3.z,b3.w};
            float dtxi = dt * xi;
            sdt += dt;
            if (fast) {
                float e = __expf(-dt);
                float p = 1.f;
                #pragma unroll
                for (int s = 0; s < DSTATE; s++) {
                    p *= e;
                    h[s] = fmaf(p, h[s], dtxi * bsv[s]);
                }
            } else {
                #pragma unroll
                for (int s = 0; s < DSTATE; s++) {
                    float aa = __expf(dt * Av[s]);
                    h[s] = fmaf(aa, h[s], dtxi * bsv[s]);
                }
            }
        }
    }
    #pragma unroll
    for (int s = 0; s < DSTATE; s++) g_hloc[dir][b][c][s][d] = h[s];
    g_sdt[dir][b][c][d] = sdt;
}

// ---------------- chunked scan: pass C (per-dir) -----------------------------
__global__ __launch_bounds__(128)
void scan_final_kernel(const float* __restrict__ cw0, const float* __restrict__ cw1,
                       const float* __restrict__ cb0, const float* __restrict__ cb1,
                       const float* __restrict__ D0, const float* __restrict__ D1,
                       int dirsel) {
    int dir = dirsel;
    int b   = blockIdx.z;
    int c   = blockIdx.y;
    int d   = blockIdx.x * 128 + threadIdx.x;
    int row0 = c * CHLEN;
    const float* Dp = dir ? D1 : D0;

    __shared__ float4 sBC[CHLEN][8];
    for (int i = threadIdx.x; i < CHLEN*8; i += 128) {
        int row = i >> 3, q = i & 7;
        sBC[row][q] = *(const float4*)(g_dbc[dir] +
                         (size_t)(b*SEQ + row0 + row)*DBCN + 64 + q*4);
    }
    __syncthreads();

    const float* dtp = g_dt[dir]  + ((size_t)(b*SEQ + row0))*DINNER + d;
    const float* xzp = g_xz[dir]  + ((size_t)(b*SEQ + row0))*XZN + d;
    const float* zp  = g_xz[dir]  + ((size_t)(b*SEQ + row0))*XZN + DINNER + d;
    __half* yp       = g_yh[dir]  + ((size_t)(b*SEQ + row0))*DINNER + d;
    const float* cw  = dir ? cw1 : cw0;
    const float* cb  = dir ? cb1 : cb0;

    float Av[DSTATE];
    #pragma unroll
    for (int s = 0; s < DSTATE; s++) Av[s] = g_A[dir][d*DSTATE + s];
    int fast = g_fastA[dir];

    float h[DSTATE];
    #pragma unroll
    for (int s = 0; s < DSTATE; s++) h[s] = 0.f;
    for (int cc = 0; cc < c; cc++) {
        float S = g_sdt[dir][b][cc][d];
        if (fast) {
            float E = __expf(-S);
            float p = 1.f;
            #pragma unroll
            for (int s = 0; s < DSTATE; s++) {
                p *= E;
                h[s] = fmaf(p, h[s], g_hloc[dir][b][cc][s][d]);
            }
        } else {
            #pragma unroll
            for (int s = 0; s < DSTATE; s++) {
                float aa = __expf(Av[s] * S);
                h[s] = fmaf(aa, h[s], g_hloc[dir][b][cc][s][d]);
            }
        }
    }

    float4 wv = ((const float4*)cw)[d];
    float cbv = cb[d];
    float x1 = 0.f, x2 = 0.f, x3 = 0.f;
    if (c > 0) {
        x1 = xzp[-(ptrdiff_t)XZN];
        x2 = xzp[-(ptrdiff_t)(2*XZN)];
        x3 = xzp[-(ptrdiff_t)(3*XZN)];
    }
    float Dv = Dp[d];

    #pragma unroll 1
    for (int l0 = 0; l0 < CHLEN; l0 += 4) {
        float cdt[4], cx[4], cz[4];
        #pragma unroll
        for (int u = 0; u < 4; u++) {
            int r = l0 + u;
            cdt[u] = dtp[(size_t)r*DINNER];
            cx[u]  = xzp[(size_t)r*XZN];
            cz[u]  = zp [(size_t)r*XZN];
        }
        #pragma unroll
        for (int u = 0; u < 4; u++) {
            int r = l0 + u;
            float dt = cdt[u], xc = cx[u], z = cz[u];
            float a = cbv;
            a = fmaf(wv.x, x3, a);
            a = fmaf(wv.y, x2, a);
            a = fmaf(wv.z, x1, a);
            a = fmaf(wv.w, xc, a);
            float xi = a / (1.f + __expf(-a));
            x3 = x2; x2 = x1; x1 = xc;

            float4 b0 = sBC[r][0], b1 = sBC[r][1], b2 = sBC[r][2], b3 = sBC[r][3];
            float4 c0 = sBC[r][4], c1 = sBC[r][5], c2 = sBC[r][6], c3 = sBC[r][7];
            float bsv[16] = {b0.x,b0.y,b0.z,b0.w, b1.x,b1.y,b1.z,b1.w,
                             b2.x,b2.y,b2.z,b2.w, b3.x,b3.y,b3.z,b3.w};
            float csv[16] = {c0.x,c0.y,c0.z,c0.w, c1.x,c1.y,c1.z,c1.w,
                             c2.x,c2.y,c2.z,c2.w, c3.x,c3.y,c3.z,c3.w};

            float dtxi = dt * xi;
            float acc = 0.f;
            if (fast) {
                float e = __expf(-dt);
                float p = 1.f;
                #pragma unroll
                for (int s = 0; s < DSTATE; s++) {
                    p *= e;
                    h[s] = fmaf(p, h[s], dtxi * bsv[s]);
                    acc = fmaf(h[s], csv[s], acc);
                }
            } else {
                #pragma unroll
                for (int s = 0; s < DSTATE; s++) {
                    float aa = __expf(dt * Av[s]);
                    h[s] = fmaf(aa, h[s], dtxi * bsv[s]);
                    acc = fmaf(h[s], csv[s], acc);
                }
            }
            float sz = z / (1.f + __expf(-z));
            yp[(size_t)r*DINNER] = __float2half((acc + xi * Dv) * sz);
        }
    }
}

// ---------------- combine dirs + LayerNorm + residual (float4) --------------
__global__ __launch_bounds__(256)
void combine_ln_kernel(const float* __restrict__ x,
                       const float* __restrict__ lng, const float* __restrict__ lnb,
                       float* __restrict__ out) {
    int row = blockIdx.x;
    int b = row / SEQ, l = row % SEQ;
    const float* f  = g_outd[0] + (size_t)row*DMODEL;
    const float* bk = g_outd[1] + (size_t)(b*SEQ + (SEQ-1-l))*DMODEL;
    int tid = threadIdx.x;

    float4 fv = *(const float4*)(f + tid*4);
    float4 bv = *(const float4*)(bk + tid*4);
    float4 dv = make_float4(0.5f*(fv.x+bv.x), 0.5f*(fv.y+bv.y),
                            0.5f*(fv.z+bv.z), 0.5f*(fv.w+bv.w));
    float s  = dv.x + dv.y + dv.z + dv.w;
    float s2 = dv.x*dv.x + dv.y*dv.y + dv.z*dv.z + dv.w*dv.w;
    #pragma unroll
    for (int o = 16; o; o >>= 1) {
        s  += __shfl_xor_sync(0xffffffffu, s,  o);
        s2 += __shfl_xor_sync(0xffffffffu, s2, o);
    }
    __shared__ float sh[2][8];
    if ((tid & 31) == 0) { sh[0][tid>>5] = s; sh[1][tid>>5] = s2; }
    __syncthreads();
    if (tid < 32) {
        float a  = (tid < 8) ? sh[0][tid] : 0.f;
        float a2 = (tid < 8) ? sh[1][tid] : 0.f;
        #pragma unroll
        for (int o = 4; o; o >>= 1) {
            a  += __shfl_xor_sync(0xffffffffu, a,  o);
            a2 += __shfl_xor_sync(0xffffffffu, a2, o);
        }
        if (tid == 0) { sh[0][0] = a; sh[1][0] = a2; }
    }
    __syncthreads();
    float mu  = sh[0][0] * (1.f/DMODEL);
    float var = sh[1][0] * (1.f/DMODEL) - mu*mu;
    float rstd = rsqrtf(var + 1e-5f);
    float4 gv = *(const float4*)(lng + tid*4);
    float4 bb = *(const float4*)(lnb + tid*4);
    float4 xv = *(const float4*)(x + (size_t)row*DMODEL + tid*4);
    float4 ov;
    ov.x = (dv.x - mu)*rstd*gv.x + bb.x + xv.x;
    ov.y = (dv.y - mu)*rstd*gv.y + bb.y + xv.y;
    ov.z = (dv.z - mu)*rstd*gv.z + bb.z + xv.z;
    ov.w = (dv.w - mu)*rstd*gv.w + bb.w + xv.w;
    *(float4*)(out + (size_t)row*DMODEL + tid*4) = ov;
}

// ---------------- host launcher --------------------------------------------
extern "C" void kernel_launch(void* const* d_in, const int* in_sizes, int n_in,
                              void* d_out, int out_size) {
    (void)in_sizes; (void)n_in; (void)out_size;
    const float* x       = (const float*)d_in[0];
    const float* Win[2]  = {(const float*)d_in[1],  (const float*)d_in[10]};
    const float* cw[2]   = {(const float*)d_in[2],  (const float*)d_in[11]};
    const float* cbv[2]  = {(const float*)d_in[3],  (const float*)d_in[12]};
    const float* xproj[2]= {(const float*)d_in[4],  (const float*)d_in[13]};
    const float* dtw[2]  = {(const float*)d_in[5],  (const float*)d_in[14]};
    const float* dtb[2]  = {(const float*)d_in[6],  (const float*)d_in[15]};
    const float* Alog[2] = {(const float*)d_in[7],  (const float*)d_in[16]};
    const float* Dp[2]   = {(const float*)d_in[8],  (const float*)d_in[17]};
    const float* Wout[2] = {(const float*)d_in[9],  (const float*)d_in[18]};
    const float* lng = (const float*)d_in[19];
    const float* lnb = (const float*)d_in[20];
    float* out = (float*)d_out;

    float *p_xz, *p_dbcp, *p_dt, *p_out;
    cudaGetSymbolAddress((void**)&p_xz,   g_xz);
    cudaGetSymbolAddress((void**)&p_dbcp, g_dbcp);
    cudaGetSymbolAddress((void**)&p_dt,   g_dt);
    cudaGetSymbolAddress((void**)&p_out,  g_outd);
    __half *p_xh, *p_winh, *p_xih, *p_xprojh, *p_dbch, *p_dtwh, *p_yh, *p_wouth;
    cudaGetSymbolAddress((void**)&p_xh,     g_xh);
    cudaGetSymbolAddress((void**)&p_winh,   g_winh);
    cudaGetSymbolAddress((void**)&p_xih,    g_xih);
    cudaGetSymbolAddress((void**)&p_xprojh, g_xprojh);
    cudaGetSymbolAddress((void**)&p_dbch,   g_dbch);
    cudaGetSymbolAddress((void**)&p_dtwh,   g_dtwh);
    cudaGetSymbolAddress((void**)&p_yh,     g_yh);
    cudaGetSymbolAddress((void**)&p_wouth,  g_wouth);

    const size_t sXZ  = (size_t)NROWS*XZN;
    const size_t sIN  = (size_t)NROWS*DINNER;
    const size_t sDBC = (size_t)NROWS*DBCN;
    const size_t sMD  = (size_t)NROWS*DMODEL;
    const int SMEM = 3*HSTG;   // 98304

    cudaFuncSetAttribute(hgemm<0>, cudaFuncAttributeMaxDynamicSharedMemorySize, SMEM);
    cudaFuncSetAttribute(hgemm<1>, cudaFuncAttributeMaxDynamicSharedMemorySize, SMEM);
    cudaFuncSetAttribute(hgemm<2>, cudaFuncAttributeMaxDynamicSharedMemorySize, SMEM);

    // fork-join resources: created fresh per call (kernel_launch runs only a
    // few times pre-replay; streams/events are host objects, never destroyed
    // while a capture could be active)
    cudaStream_t s1;
    cudaEvent_t evF, evJ;
    cudaStreamCreateWithFlags(&s1, cudaStreamNonBlocking);
    cudaEventCreateWithFlags(&evF, cudaEventDisableTiming);
    cudaEventCreateWithFlags(&evJ, cudaEventDisableTiming);

    prepA_kernel<<<2, 256>>>(Alog[0], Alog[1]);

    {
        CvtSegs cs;
        const float* srcs[9] = {x, Win[0], Win[1], xproj[0], xproj[1],
                                dtw[0], dtw[1], Wout[0], Wout[1]};
        __half* dsts[9] = {p_xh, p_winh, p_winh + (size_t)XZN*DMODEL,
                           p_xprojh, p_xprojh + (size_t)DBCN*DINNER,
                           p_dtwh, p_dtwh + (size_t)DINNER*64,
                           p_wouth, p_wouth + (size_t)DMODEL*DINNER};
        int cnts[9] = {NROWS*DMODEL, XZN*DMODEL, XZN*DMODEL,
                       DBCN*DINNER, DBCN*DINNER, DINNER*64, DINNER*64,
                       DMODEL*DINNER, DMODEL*DINNER};
        int off = 0;
        for (int i = 0; i < 9; i++) { cs.s[i]=srcs[i]; cs.d[i]=dsts[i]; cs.off[i]=off; off+=cnts[i]; }
        cs.off[9] = off;
        f2h_multi_kernel<<<(off/4 + 255)/256, 256>>>(cs);
    }

    // fork: dir1 chain runs on s1
    cudaEventRecord(evF, 0);
    cudaStreamWaitEvent(s1, evF, 0);

    for (int dir = 0; dir < 2; dir++) {
        cudaStream_t st = dir ? s1 : (cudaStream_t)0;

        // in_proj: xz = x @ Win^T (N=4096, K=1024); dir-1 rows reversed
        hgemm<0><<<dim3(XZN/128, NROWS/128, 1), 256, SMEM, st>>>(
            p_xh, p_xh, p_winh, p_winh + (size_t)XZN*DMODEL, nullptr, nullptr,
            p_xz, p_xz + sXZ, XZN, XZN, DMODEL, DMODEL, DMODEL, 0, 1, dir);

        conv_silu_kernel<<<dim3(((NROWS/2)*(DINNER/4) + 255)/256, 1, 1), 256, 0, st>>>(
            cw[0], cw[1], cbv[0], cbv[1], dir);

        // x_proj split-K (N=96, K=256/split), fp32 partials
        hgemm<0><<<dim3(1, NROWS/128, NSPLIT), 256, SMEM, st>>>(
            p_xih, p_xih + sIN, p_xprojh, p_xprojh + (size_t)DBCN*DINNER,
            nullptr, nullptr,
            p_dbcp, p_dbcp + NSPLIT*sDBC, DBCN, DBCN, DINNER/NSPLIT, DINNER, DINNER,
            sDBC, 0, dir);
        reduce_dbc_kernel<<<(NROWS*DBCN + 255)/256, 256, 0, st>>>(dir);

        // dt = softplus(dbc[:, :64] @ dtw^T + dtb) (N=2048, K=64)
        hgemm<1><<<dim3(DINNER/128, NROWS/128, 1), 256, SMEM, st>>>(
            p_dbch, p_dbch + sDBC, p_dtwh, p_dtwh + (size_t)DINNER*64, dtb[0], dtb[1],
            p_dt, p_dt + sIN, DINNER, DINNER, 64, DBCN, 64, 0, 0, dir);

        // chunked scan
        scan_local_kernel<<<dim3(DINNER/128, NCHUNK-1, BATCH), 128, 0, st>>>(
            cw[0], cw[1], cbv[0], cbv[1], dir);
        scan_final_kernel<<<dim3(DINNER/128, NCHUNK, BATCH), 128, 0, st>>>(
            cw[0], cw[1], cbv[0], cbv[1], Dp[0], Dp[1], dir);

        // out = sigmoid(y @ Wout^T) (N=1024, K=2048)
        hgemm<2><<<dim3(DMODEL/128, NROWS/128, 1), 256, SMEM, st>>>(
            p_yh, p_yh + sIN, p_wouth, p_wouth + (size_t)DMODEL*DINNER,
            nullptr, nullptr,
            p_out, p_out + sMD, DMODEL, DMODEL, DINNER, DINNER, DINNER, 0, 0, dir);
    }

    // join, then LN on main stream
    cudaEventRecord(evJ, s1);
    cudaStreamWaitEvent((cudaStream_t)0, evJ, 0);
    combine_ln_kernel<<<NROWS, 256>>>(x, lng, lnb, out);
}